// round 5
// baseline (speedup 1.0000x reference)
#include <cuda_runtime.h>
#include <cstdint>
#include <cstdio>

// Problem constants
namespace {
constexpr int Bb = 4, Tt = 4096, Cc = 2048, Hh = 16, DhD = 128;
constexpr int Mrows = Bb * Tt;            // 16384
constexpr int NCHUNK = 64;                // scan chunks
constexpr int LCH = Tt / NCHUNK;          // 64 steps per chunk
constexpr int BK2 = 32;                   // k-floats per stage (2 sub-tiles of 16)
constexpr int KIT = Cc / BK2;             // 64 stages
constexpr int SUBW = 128 * 16;            // 2048 words per sub-tile
constexpr int STW2 = 2 * SUBW;            // 4096 words per (matrix,stage)
constexpr int NST = 3;
constexpr int GEMM_SMEM = NST * 2 * STW2 * 4;   // 98304 B
}

// ---------------- scratch (static device globals; no allocation allowed) ---
__device__ float g_xconv[(size_t)Bb * Tt * Cc];
__device__ float g_q   [(size_t)Bb * Tt * Cc];
__device__ float g_k   [(size_t)Bb * Tt * Cc];
__device__ float g_v   [(size_t)Bb * Tt * Cc];
__device__ float g_gate[(size_t)Bb * Tt * Cc];
__device__ float g_att [(size_t)Bb * Tt * Cc];
__device__ float g_y   [(size_t)Bb * Tt * Cc];
__device__ float g_xt  [(size_t)Bb * Tt * Cc];      // tf32-rounded x
__device__ float g_Wqt [(size_t)Cc * Cc];
__device__ float g_Wkt [(size_t)Cc * Cc];
__device__ float g_Wvt [(size_t)Cc * Cc];
__device__ float g_Wot [(size_t)Cc * Cc];
__device__ float g_Wgt [(size_t)Cc * Cc];
__device__ float g_F    [(size_t)Bb * Hh * NCHUNK * DhD];
__device__ float g_carry[(size_t)Bb * Hh * NCHUNK * DhD];

// ---------------- helpers --------------------------------------------------
__device__ __forceinline__ uint32_t f2tf32(float f) {
    uint32_t u;
    asm("cvt.rna.tf32.f32 %0, %1;" : "=r"(u) : "f"(f));
    return u;
}
__device__ __forceinline__ float tf32r(float f) { return __uint_as_float(f2tf32(f)); }

__device__ __forceinline__ void mma_tf32(float& d0, float& d1, float& d2, float& d3,
                                         uint32_t a0, uint32_t a1, uint32_t a2, uint32_t a3,
                                         uint32_t b0, uint32_t b1) {
    asm volatile(
        "mma.sync.aligned.m16n8k8.row.col.f32.tf32.tf32.f32 "
        "{%0,%1,%2,%3}, {%4,%5,%6,%7}, {%8,%9}, {%0,%1,%2,%3};\n"
        : "+f"(d0), "+f"(d1), "+f"(d2), "+f"(d3)
        : "r"(a0), "r"(a1), "r"(a2), "r"(a3), "r"(b0), "r"(b1));
}

// ---------------- 0) tf32 pre-round (vectorized) ----------------------------
__global__ void cvt_tf32_kernel(const float* __restrict__ in, float* __restrict__ out) {
    int i = blockIdx.x * blockDim.x + threadIdx.x;
    float4 v = reinterpret_cast<const float4*>(in)[i];
    v.x = tf32r(v.x); v.y = tf32r(v.y); v.z = tf32r(v.z); v.w = tf32r(v.w);
    reinterpret_cast<float4*>(out)[i] = v;
}

// ---------------- 1) causal depthwise conv (K=4) + SiLU (tf32-rounded out) --
__global__ void conv_silu_kernel(const float* __restrict__ x,
                                 const float* __restrict__ w,
                                 const float* __restrict__ bias) {
    int idx = blockIdx.x * blockDim.x + threadIdx.x;
    int c  = idx & (Cc - 1);
    int bt = idx >> 11;
    int t  = bt & (Tt - 1);
    float acc = bias[c];
    const float* wr = w + c * 4;
    int base = (bt - t) * Cc + c;
    #pragma unroll
    for (int j = 0; j < 4; j++) {
        int tt = t - 3 + j;
        if (tt >= 0) acc = fmaf(x[base + tt * Cc], wr[j], acc);
    }
    float s = acc / (1.0f + expf(-acc));
    g_xconv[idx] = tf32r(s);
}

// ---------------- 2) TF32 mma.sync GEMM (round-2 core, BK=32 stages) --------
// Out = A[M,K] * W[N,K]^T.  A, W pre-rounded to tf32.
// mode 0: plain.  mode 1: sigmoid(out+bias[col]).  mode 2: per-row l2norm
// over the 128-col tile (tile == one head since BN=128).
// smem per (matrix,stage): 2 sub-tiles, each 128 rows x 16 words, XOR-swizzled:
//   word(row,k) at row*16 + (((k>>2) ^ ((row>>1)&3))<<2) + (k&3)
__global__ __launch_bounds__(256, 1)
void gemm_tf32_r2(const float* __restrict__ A, const float* __restrict__ W,
                  float* __restrict__ Out, const float* __restrict__ bias, int mode) {
    extern __shared__ uint32_t dyn[];
    uint32_t* AsB = dyn;                  // NST * STW2
    uint32_t* BsB = dyn + NST * STW2;     // NST * STW2
    float*    red = (float*)dyn;          // reused after mainloop (post-sync)

    const int tid  = threadIdx.x;
    const int warp = tid >> 5, lane = tid & 31;
    const int gid  = lane >> 2, tg = lane & 3;
    const int wm   = warp & 1;
    const int wn   = warp >> 1;
    const int bm   = blockIdx.y * 128;
    const int bn   = blockIdx.x * 128;

    const int lrow = tid >> 1;            // 0..127 loader row
    const int lsub = tid & 1;             // sub-tile 0/1

    const uint32_t sA = (uint32_t)__cvta_generic_to_shared(AsB);
    const uint32_t sB = (uint32_t)__cvta_generic_to_shared(BsB);

    auto issue = [&](int s, int it) {
        const int k0 = it * BK2 + lsub * 16;
        const int sw = (lrow >> 1) & 3;
        const uint32_t base = (uint32_t)(s * STW2 + lsub * SUBW + lrow * 16) * 4u;
        const float* gA = A + (size_t)(bm + lrow) * Cc + k0;
        const float* gB = W + (size_t)(bn + lrow) * Cc + k0;
        #pragma unroll
        for (int jj = 0; jj < 4; jj++) {
            uint32_t off = base + (uint32_t)(((jj ^ sw) << 2)) * 4u;
            asm volatile("cp.async.cg.shared.global [%0], [%1], 16;\n"
                         :: "r"(sA + off), "l"(gA + jj * 4));
            asm volatile("cp.async.cg.shared.global [%0], [%1], 16;\n"
                         :: "r"(sB + off), "l"(gB + jj * 4));
        }
        asm volatile("cp.async.commit_group;\n" ::: "memory");
    };

    float acc[4][4][4] = {};

    issue(0, 0);
    issue(1, 1);

    for (int i = 0; i < KIT; i++) {
        const int s = i % NST;
        if (i < KIT - 1) asm volatile("cp.async.wait_group 1;\n" ::: "memory");
        else             asm volatile("cp.async.wait_group 0;\n" ::: "memory");
        __syncthreads();

        if (i + 2 < KIT) {
            int s2 = s + 2; if (s2 >= NST) s2 -= NST;
            issue(s2, i + 2);
        }

        #pragma unroll
        for (int half = 0; half < 4; half++) {
            const uint32_t* Ab = &AsB[s * STW2 + (half >> 1) * SUBW];
            const uint32_t* Bs = &BsB[s * STW2 + (half >> 1) * SUBW];
            const int c0 = (half & 1) * 2;
            uint32_t af[4][4], bf[4][2];
            #pragma unroll
            for (int mt = 0; mt < 4; mt++) {
                int row = wm * 64 + mt * 16 + gid;
                int sw  = (row >> 1) & 3;
                int b0i = row * 16 + tg;
                int b1i = (row + 8) * 16 + tg;
                af[mt][0] = Ab[b0i + ((c0 ^ sw) << 2)];
                af[mt][1] = Ab[b1i + ((c0 ^ sw) << 2)];
                af[mt][2] = Ab[b0i + (((c0 + 1) ^ sw) << 2)];
                af[mt][3] = Ab[b1i + (((c0 + 1) ^ sw) << 2)];
            }
            #pragma unroll
            for (int nt = 0; nt < 4; nt++) {
                int col = wn * 32 + nt * 8 + gid;
                int sw  = (col >> 1) & 3;
                int bi  = col * 16 + tg;
                bf[nt][0] = Bs[bi + ((c0 ^ sw) << 2)];
                bf[nt][1] = Bs[bi + (((c0 + 1) ^ sw) << 2)];
            }
            #pragma unroll
            for (int mt = 0; mt < 4; mt++)
                #pragma unroll
                for (int nt = 0; nt < 4; nt++)
                    mma_tf32(acc[mt][nt][0], acc[mt][nt][1], acc[mt][nt][2], acc[mt][nt][3],
                             af[mt][0], af[mt][1], af[mt][2], af[mt][3],
                             bf[nt][0], bf[nt][1]);
        }
    }
    __syncthreads();

    // ---- fused l2norm over the 128-col tile (mode 2) ------------------------
    if (mode == 2) {
        float invLo[4], invHi[4];
        #pragma unroll
        for (int mt = 0; mt < 4; mt++) {
            float slo = 0.0f, shi = 0.0f;
            #pragma unroll
            for (int nt = 0; nt < 4; nt++) {
                slo = fmaf(acc[mt][nt][0], acc[mt][nt][0], slo);
                slo = fmaf(acc[mt][nt][1], acc[mt][nt][1], slo);
                shi = fmaf(acc[mt][nt][2], acc[mt][nt][2], shi);
                shi = fmaf(acc[mt][nt][3], acc[mt][nt][3], shi);
            }
            slo += __shfl_xor_sync(0xffffffffu, slo, 1);
            slo += __shfl_xor_sync(0xffffffffu, slo, 2);
            shi += __shfl_xor_sync(0xffffffffu, shi, 1);
            shi += __shfl_xor_sync(0xffffffffu, shi, 2);
            if (tg == 0) {
                int r = wm * 64 + mt * 16 + gid;
                red[r * 4 + wn]       = slo;
                red[(r + 8) * 4 + wn] = shi;
            }
        }
        __syncthreads();
        #pragma unroll
        for (int mt = 0; mt < 4; mt++) {
            int r = wm * 64 + mt * 16 + gid;
            float slo = red[r * 4 + 0] + red[r * 4 + 1] + red[r * 4 + 2] + red[r * 4 + 3];
            float shi = red[(r + 8) * 4 + 0] + red[(r + 8) * 4 + 1]
                      + red[(r + 8) * 4 + 2] + red[(r + 8) * 4 + 3];
            invLo[mt] = 1.0f / fmaxf(sqrtf(slo), 1e-12f);
            invHi[mt] = 1.0f / fmaxf(sqrtf(shi), 1e-12f);
        }
        #pragma unroll
        for (int mt = 0; mt < 4; mt++)
            #pragma unroll
            for (int nt = 0; nt < 4; nt++) {
                acc[mt][nt][0] *= invLo[mt];
                acc[mt][nt][1] *= invLo[mt];
                acc[mt][nt][2] *= invHi[mt];
                acc[mt][nt][3] *= invHi[mt];
            }
    }

    // ---- stores --------------------------------------------------------------
    #pragma unroll
    for (int mt = 0; mt < 4; mt++) {
        #pragma unroll
        for (int nt = 0; nt < 4; nt++) {
            int row = bm + wm * 64 + mt * 16 + gid;
            int col = bn + wn * 32 + nt * 8 + tg * 2;
            float v0 = acc[mt][nt][0], v1 = acc[mt][nt][1];
            float v2 = acc[mt][nt][2], v3 = acc[mt][nt][3];
            if (mode == 1) {
                float b0 = bias[col], b1 = bias[col + 1];
                v0 = 1.0f / (1.0f + expf(-(v0 + b0)));
                v1 = 1.0f / (1.0f + expf(-(v1 + b1)));
                v2 = 1.0f / (1.0f + expf(-(v2 + b0)));
                v3 = 1.0f / (1.0f + expf(-(v3 + b1)));
            }
            *reinterpret_cast<float2*>(&Out[(size_t)row * Cc + col])       = make_float2(v0, v1);
            *reinterpret_cast<float2*>(&Out[(size_t)(row + 8) * Cc + col]) = make_float2(v2, v3);
        }
    }
}

// ---------------- 4) chunked decayed scan ----------------------------------
__global__ void scan_pass1(const float* __restrict__ k, const float* __restrict__ v,
                           const float* __restrict__ gamma) {
    int blk = blockIdx.x;
    int c  = blk % NCHUNK;
    int bh = blk / NCHUNK;
    int h  = bh % Hh;
    int b  = bh / Hh;
    int d  = threadIdx.x;
    float g = gamma[h];
    size_t idx = ((size_t)(b * Tt + c * LCH)) * Cc + h * DhD + d;
    float S = 0.0f;
    #pragma unroll 4
    for (int i = 0; i < LCH; i++) {
        S = fmaf(g, S, k[idx] * v[idx]);
        idx += Cc;
    }
    g_F[((size_t)bh * NCHUNK + c) * DhD + d] = S;
}

__global__ void scan_pass2(const float* __restrict__ gamma) {
    int tid = blockIdx.x * blockDim.x + threadIdx.x;
    if (tid >= Bb * Hh * DhD) return;
    int d  = tid & (DhD - 1);
    int bh = tid >> 7;
    int h  = bh % Hh;
    float g  = gamma[h];
    float gL = powf(g, (float)LCH);
    float carry = 0.0f;
    for (int c = 0; c < NCHUNK; c++) {
        size_t o = ((size_t)bh * NCHUNK + c) * DhD + d;
        g_carry[o] = carry;
        carry = fmaf(gL, carry, g_F[o]);
    }
}

__global__ void scan_pass3(const float* __restrict__ k, const float* __restrict__ v,
                           const float* __restrict__ q, const float* __restrict__ gate,
                           const float* __restrict__ gamma) {
    int blk = blockIdx.x;
    int c  = blk % NCHUNK;
    int bh = blk / NCHUNK;
    int h  = bh % Hh;
    int b  = bh / Hh;
    int d  = threadIdx.x;
    float g = gamma[h];
    float S = g_carry[((size_t)bh * NCHUNK + c) * DhD + d];
    size_t idx = ((size_t)(b * Tt + c * LCH)) * Cc + h * DhD + d;
    #pragma unroll 4
    for (int i = 0; i < LCH; i++) {
        S = fmaf(g, S, k[idx] * v[idx]);
        g_att[idx] = tf32r(gate[idx] * S * q[idx]);
        idx += Cc;
    }
}

// ---------------- 5) LayerNorm over C=2048 ---------------------------------
__global__ __launch_bounds__(256)
void ln_kernel(const float* __restrict__ y, const float* __restrict__ lw,
               const float* __restrict__ lb, float* __restrict__ out) {
    int row = blockIdx.x;
    int tid = threadIdx.x;
    const float4* yr = reinterpret_cast<const float4*>(y + (size_t)row * Cc);
    float4* orow     = reinterpret_cast<float4*>(out + (size_t)row * Cc);

    float4 v0 = yr[tid];
    float4 v1 = yr[tid + 256];
    float sum = v0.x + v0.y + v0.z + v0.w + v1.x + v1.y + v1.z + v1.w;
    float sq  = v0.x * v0.x + v0.y * v0.y + v0.z * v0.z + v0.w * v0.w
              + v1.x * v1.x + v1.y * v1.y + v1.z * v1.z + v1.w * v1.w;

    #pragma unroll
    for (int o = 16; o; o >>= 1) {
        sum += __shfl_xor_sync(0xffffffffu, sum, o);
        sq  += __shfl_xor_sync(0xffffffffu, sq, o);
    }
    __shared__ float ssum[8], ssq[8];
    __shared__ float s_mu, s_inv;
    int warp = tid >> 5, lane = tid & 31;
    if (lane == 0) { ssum[warp] = sum; ssq[warp] = sq; }
    __syncthreads();
    if (tid == 0) {
        float ts = 0.0f, tq = 0.0f;
        #pragma unroll
        for (int i = 0; i < 8; i++) { ts += ssum[i]; tq += ssq[i]; }
        float mu  = ts / (float)Cc;
        float var = tq / (float)Cc - mu * mu;
        s_mu  = mu;
        s_inv = rsqrtf(var + 1e-5f);
    }
    __syncthreads();
    float mu = s_mu, inv = s_inv;

    const float4 w0 = reinterpret_cast<const float4*>(lw)[tid];
    const float4 w1 = reinterpret_cast<const float4*>(lw)[tid + 256];
    const float4 b0 = reinterpret_cast<const float4*>(lb)[tid];
    const float4 b1 = reinterpret_cast<const float4*>(lb)[tid + 256];

    float4 o0, o1;
    o0.x = (v0.x - mu) * inv * w0.x + b0.x;
    o0.y = (v0.y - mu) * inv * w0.y + b0.y;
    o0.z = (v0.z - mu) * inv * w0.z + b0.z;
    o0.w = (v0.w - mu) * inv * w0.w + b0.w;
    o1.x = (v1.x - mu) * inv * w1.x + b1.x;
    o1.y = (v1.y - mu) * inv * w1.y + b1.y;
    o1.z = (v1.z - mu) * inv * w1.z + b1.z;
    o1.w = (v1.w - mu) * inv * w1.w + b1.w;
    orow[tid]       = o0;
    orow[tid + 256] = o1;
}

// ---------------- host orchestration ---------------------------------------
extern "C" void kernel_launch(void* const* d_in, const int* in_sizes, int n_in,
                              void* d_out, int out_size) {
    (void)in_sizes; (void)n_in; (void)out_size;
    const float* x      = (const float*)d_in[0];
    const float* Wq     = (const float*)d_in[1];
    const float* Wk     = (const float*)d_in[2];
    const float* Wv     = (const float*)d_in[3];
    const float* Wo     = (const float*)d_in[4];
    const float* conv_w = (const float*)d_in[5];
    const float* conv_b = (const float*)d_in[6];
    const float* gate_w = (const float*)d_in[7];
    const float* gate_b = (const float*)d_in[8];
    const float* ln_w   = (const float*)d_in[9];
    const float* ln_b   = (const float*)d_in[10];
    const float* gamma  = (const float*)d_in[11];

    float *p_xconv, *p_q, *p_k, *p_v, *p_gate, *p_att, *p_y;
    float *p_xt, *p_Wqt, *p_Wkt, *p_Wvt, *p_Wot, *p_Wgt;
    cudaGetSymbolAddress((void**)&p_xconv, g_xconv);
    cudaGetSymbolAddress((void**)&p_q, g_q);
    cudaGetSymbolAddress((void**)&p_k, g_k);
    cudaGetSymbolAddress((void**)&p_v, g_v);
    cudaGetSymbolAddress((void**)&p_gate, g_gate);
    cudaGetSymbolAddress((void**)&p_att, g_att);
    cudaGetSymbolAddress((void**)&p_y, g_y);
    cudaGetSymbolAddress((void**)&p_xt, g_xt);
    cudaGetSymbolAddress((void**)&p_Wqt, g_Wqt);
    cudaGetSymbolAddress((void**)&p_Wkt, g_Wkt);
    cudaGetSymbolAddress((void**)&p_Wvt, g_Wvt);
    cudaGetSymbolAddress((void**)&p_Wot, g_Wot);
    cudaGetSymbolAddress((void**)&p_Wgt, g_Wgt);

    cudaFuncSetAttribute(gemm_tf32_r2, cudaFuncAttributeMaxDynamicSharedMemorySize, GEMM_SMEM);

    // 0) pre-round GEMM operands to tf32
    const int wElems = Cc * Cc;
    cvt_tf32_kernel<<<wElems / 1024, 256>>>(Wq, p_Wqt);
    cvt_tf32_kernel<<<wElems / 1024, 256>>>(Wk, p_Wkt);
    cvt_tf32_kernel<<<wElems / 1024, 256>>>(Wv, p_Wvt);
    cvt_tf32_kernel<<<wElems / 1024, 256>>>(Wo, p_Wot);
    cvt_tf32_kernel<<<wElems / 1024, 256>>>(gate_w, p_Wgt);
    cvt_tf32_kernel<<<(Mrows * Cc) / 1024, 256>>>(x, p_xt);

    // 1) depthwise conv + SiLU
    conv_silu_kernel<<<(Mrows * Cc) / 256, 256>>>(x, conv_w, conv_b);

    // 2) projections.  mode: 0 plain, 1 sigmoid+bias, 2 fused l2norm (1 head/tile)
    dim3 ggrid(Cc / 128, Mrows / 128);   // (16, 128)
    gemm_tf32_r2<<<ggrid, 256, GEMM_SMEM>>>(p_xt,    p_Wqt, p_q,    nullptr, 2);
    gemm_tf32_r2<<<ggrid, 256, GEMM_SMEM>>>(p_xt,    p_Wkt, p_k,    nullptr, 2);
    gemm_tf32_r2<<<ggrid, 256, GEMM_SMEM>>>(p_xt,    p_Wvt, p_v,    nullptr, 0);
    gemm_tf32_r2<<<ggrid, 256, GEMM_SMEM>>>(p_xconv, p_Wgt, p_gate, gate_b, 1);

    // 3) decayed scan (chunked, exact); q/k already l2-normalized in epilogue
    scan_pass1<<<Bb * Hh * NCHUNK, DhD>>>(p_k, p_v, gamma);
    scan_pass2<<<(Bb * Hh * DhD + 127) / 128, 128>>>(gamma);
    scan_pass3<<<Bb * Hh * NCHUNK, DhD>>>(p_k, p_v, p_q, p_gate, gamma);

    // 4) output projection + LayerNorm
    gemm_tf32_r2<<<ggrid, 256, GEMM_SMEM>>>(p_att, p_Wot, p_y, nullptr, 0);
    ln_kernel<<<Mrows, 256>>>(p_y, ln_w, ln_b, (float*)d_out);
}

// round 6
// speedup vs baseline: 1.1621x; 1.1621x over previous
#include <cuda_runtime.h>
#include <cstdint>
#include <cstdio>

// Problem constants
namespace {
constexpr int Bb = 4, Tt = 4096, Cc = 2048, Hh = 16, DhD = 128;
constexpr int Mrows = Bb * Tt;            // 16384
constexpr int NCHUNK = 64;                // scan chunks
constexpr int LCH = Tt / NCHUNK;          // 64 steps per chunk
// GEMM tiling: block 128x256, 8 warps of 64x64, 3-stage cp.async, BK=16
constexpr int BM = 128, BN = 256, BKk = 16, NST = 3;
constexpr int KCH = Cc / BKk;             // 128 stages
constexpr int AW = BM * BKk;              // 2048 words per A stage
constexpr int BW = BN * BKk;              // 4096 words per B stage
constexpr int GEMM_SMEM = NST * (AW + BW) * 4;   // 73728 B
}

// ---------------- scratch (static device globals; no allocation allowed) ---
__device__ float g_xconv[(size_t)Bb * Tt * Cc];
__device__ float g_q   [(size_t)Bb * Tt * Cc];
__device__ float g_k   [(size_t)Bb * Tt * Cc];
__device__ float g_v   [(size_t)Bb * Tt * Cc];
__device__ float g_gate[(size_t)Bb * Tt * Cc];
__device__ float g_att [(size_t)Bb * Tt * Cc];
__device__ float g_y   [(size_t)Bb * Tt * Cc];
__device__ float g_xt  [(size_t)Bb * Tt * Cc];      // tf32-rounded x
__device__ float g_Wqt [(size_t)Cc * Cc];
__device__ float g_Wkt [(size_t)Cc * Cc];
__device__ float g_Wvt [(size_t)Cc * Cc];
__device__ float g_Wot [(size_t)Cc * Cc];
__device__ float g_Wgt [(size_t)Cc * Cc];
__device__ float g_F    [(size_t)Bb * Hh * NCHUNK * DhD];
__device__ float g_carry[(size_t)Bb * Hh * NCHUNK * DhD];

// ---------------- helpers --------------------------------------------------
__device__ __forceinline__ uint32_t f2tf32(float f) {
    uint32_t u;
    asm("cvt.rna.tf32.f32 %0, %1;" : "=r"(u) : "f"(f));
    return u;
}
__device__ __forceinline__ float tf32r(float f) { return __uint_as_float(f2tf32(f)); }

__device__ __forceinline__ void mma_tf32(float& d0, float& d1, float& d2, float& d3,
                                         uint32_t a0, uint32_t a1, uint32_t a2, uint32_t a3,
                                         uint32_t b0, uint32_t b1) {
    asm volatile(
        "mma.sync.aligned.m16n8k8.row.col.f32.tf32.tf32.f32 "
        "{%0,%1,%2,%3}, {%4,%5,%6,%7}, {%8,%9}, {%0,%1,%2,%3};\n"
        : "+f"(d0), "+f"(d1), "+f"(d2), "+f"(d3)
        : "r"(a0), "r"(a1), "r"(a2), "r"(a3), "r"(b0), "r"(b1));
}

// ---------------- 0) tf32 pre-round (vectorized) ----------------------------
__global__ void cvt_tf32_kernel(const float* __restrict__ in, float* __restrict__ out) {
    int i = blockIdx.x * blockDim.x + threadIdx.x;
    float4 v = reinterpret_cast<const float4*>(in)[i];
    v.x = tf32r(v.x); v.y = tf32r(v.y); v.z = tf32r(v.z); v.w = tf32r(v.w);
    reinterpret_cast<float4*>(out)[i] = v;
}

// ---------------- 1) causal depthwise conv (K=4) + SiLU (tf32-rounded out) --
__global__ void conv_silu_kernel(const float* __restrict__ x,
                                 const float* __restrict__ w,
                                 const float* __restrict__ bias) {
    int idx = blockIdx.x * blockDim.x + threadIdx.x;
    int c  = idx & (Cc - 1);
    int bt = idx >> 11;
    int t  = bt & (Tt - 1);
    float acc = bias[c];
    const float* wr = w + c * 4;
    int base = (bt - t) * Cc + c;
    #pragma unroll
    for (int j = 0; j < 4; j++) {
        int tt = t - 3 + j;
        if (tt >= 0) acc = fmaf(x[base + tt * Cc], wr[j], acc);
    }
    float s = acc / (1.0f + expf(-acc));
    g_xconv[idx] = tf32r(s);
}

// ---------------- 2) TF32 mma.sync GEMM (round-2 skeleton, 64x64 warp tile) -
// Out = A[M,K] * W[N,K]^T.  A, W pre-rounded to tf32.
// mode 0: plain.  mode 1: sigmoid(out+bias[col]).  mode 2: per-row l2norm per
// 128-col head (BN=256 = 2 heads).
// smem per (matrix,stage): rows x 16 words, XOR-swizzled chunks:
//   word(row,k) at row*16 + (((k>>2) ^ ((row>>1)&3))<<2) + (k&3)
__global__ __launch_bounds__(256, 1)
void gemm_tf32_w64(const float* __restrict__ A, const float* __restrict__ W,
                   float* __restrict__ Out, const float* __restrict__ bias, int mode) {
    extern __shared__ uint32_t dyn[];
    uint32_t* AsB = dyn;                  // NST * AW
    uint32_t* BsB = dyn + NST * AW;       // NST * BW
    float*    red = (float*)dyn;          // reused after mainloop (post-sync)

    const int tid  = threadIdx.x;
    const int warp = tid >> 5, lane = tid & 31;
    const int gid  = lane >> 2, tg = lane & 3;
    const int wm   = warp & 1;            // 2 slabs of 64 rows
    const int wn   = warp >> 1;           // 4 slabs of 64 cols
    const int bm   = blockIdx.y * BM;
    const int bn   = blockIdx.x * BN;

    const int lr = tid >> 2;              // 0..63 loader row
    const int lc = tid & 3;               // chunk 0..3

    const uint32_t sA = (uint32_t)__cvta_generic_to_shared(AsB);
    const uint32_t sB = (uint32_t)__cvta_generic_to_shared(BsB);

    auto issue = [&](int s, int k0) {
        // A: 128 rows (2 per thread)
        #pragma unroll
        for (int r = 0; r < 2; r++) {
            int row = lr + r * 64;
            int sw  = (row >> 1) & 3;
            uint32_t off = (uint32_t)(s * AW + row * 16 + ((lc ^ sw) << 2)) * 4u;
            const float* gA = A + (size_t)(bm + row) * Cc + k0 + lc * 4;
            asm volatile("cp.async.cg.shared.global [%0], [%1], 16;\n" :: "r"(sA + off), "l"(gA));
        }
        // B: 256 rows (4 per thread)
        #pragma unroll
        for (int r = 0; r < 4; r++) {
            int row = lr + r * 64;
            int sw  = (row >> 1) & 3;
            uint32_t off = (uint32_t)(s * BW + row * 16 + ((lc ^ sw) << 2)) * 4u;
            const float* gB = W + (size_t)(bn + row) * Cc + k0 + lc * 4;
            asm volatile("cp.async.cg.shared.global [%0], [%1], 16;\n" :: "r"(sB + off), "l"(gB));
        }
        asm volatile("cp.async.commit_group;\n" ::: "memory");
    };

    float acc[4][8][4] = {};

    issue(0, 0);
    issue(1, BKk);

    for (int i = 0; i < KCH; i++) {
        const int s = i % NST;
        if (i < KCH - 1) asm volatile("cp.async.wait_group 1;\n" ::: "memory");
        else             asm volatile("cp.async.wait_group 0;\n" ::: "memory");
        __syncthreads();

        if (i + 2 < KCH) {
            int s2 = s + 2; if (s2 >= NST) s2 -= NST;
            issue(s2, (i + 2) * BKk);
        }

        const uint32_t* Ab = &AsB[s * AW];
        const uint32_t* Bs = &BsB[s * BW];
        #pragma unroll
        for (int half = 0; half < 2; half++) {
            const int c0 = half * 2;
            uint32_t af[4][4], bf[8][2];
            #pragma unroll
            for (int mt = 0; mt < 4; mt++) {
                int row = wm * 64 + mt * 16 + gid;
                int sw  = (row >> 1) & 3;
                int b0i = row * 16 + tg;
                int b1i = (row + 8) * 16 + tg;
                af[mt][0] = Ab[b0i + ((c0 ^ sw) << 2)];
                af[mt][1] = Ab[b1i + ((c0 ^ sw) << 2)];
                af[mt][2] = Ab[b0i + (((c0 + 1) ^ sw) << 2)];
                af[mt][3] = Ab[b1i + (((c0 + 1) ^ sw) << 2)];
            }
            #pragma unroll
            for (int nt = 0; nt < 8; nt++) {
                int col = wn * 64 + nt * 8 + gid;
                int sw  = (col >> 1) & 3;
                int bi  = col * 16 + tg;
                bf[nt][0] = Bs[bi + ((c0 ^ sw) << 2)];
                bf[nt][1] = Bs[bi + (((c0 + 1) ^ sw) << 2)];
            }
            #pragma unroll
            for (int mt = 0; mt < 4; mt++)
                #pragma unroll
                for (int nt = 0; nt < 8; nt++)
                    mma_tf32(acc[mt][nt][0], acc[mt][nt][1], acc[mt][nt][2], acc[mt][nt][3],
                             af[mt][0], af[mt][1], af[mt][2], af[mt][3],
                             bf[nt][0], bf[nt][1]);
        }
    }
    __syncthreads();

    // ---- fused per-head l2norm (mode 2): head = 128 cols = 2 wn slabs -------
    if (mode == 2) {
        #pragma unroll
        for (int mt = 0; mt < 4; mt++) {
            float slo = 0.0f, shi = 0.0f;
            #pragma unroll
            for (int nt = 0; nt < 8; nt++) {
                slo = fmaf(acc[mt][nt][0], acc[mt][nt][0], slo);
                slo = fmaf(acc[mt][nt][1], acc[mt][nt][1], slo);
                shi = fmaf(acc[mt][nt][2], acc[mt][nt][2], shi);
                shi = fmaf(acc[mt][nt][3], acc[mt][nt][3], shi);
            }
            slo += __shfl_xor_sync(0xffffffffu, slo, 1);
            slo += __shfl_xor_sync(0xffffffffu, slo, 2);
            shi += __shfl_xor_sync(0xffffffffu, shi, 1);
            shi += __shfl_xor_sync(0xffffffffu, shi, 2);
            if (tg == 0) {
                int r = wm * 64 + mt * 16 + gid;
                red[r * 4 + wn]       = slo;   // warp-partial sum over its 64 cols
                red[(r + 8) * 4 + wn] = shi;
            }
        }
        __syncthreads();
        const int h2 = (wn >> 1) << 1;        // head base slab (0 or 2)
        #pragma unroll
        for (int mt = 0; mt < 4; mt++) {
            int r = wm * 64 + mt * 16 + gid;
            float slo = red[r * 4 + h2] + red[r * 4 + h2 + 1];
            float shi = red[(r + 8) * 4 + h2] + red[(r + 8) * 4 + h2 + 1];
            float invLo = 1.0f / fmaxf(sqrtf(slo), 1e-12f);
            float invHi = 1.0f / fmaxf(sqrtf(shi), 1e-12f);
            #pragma unroll
            for (int nt = 0; nt < 8; nt++) {
                acc[mt][nt][0] *= invLo;
                acc[mt][nt][1] *= invLo;
                acc[mt][nt][2] *= invHi;
                acc[mt][nt][3] *= invHi;
            }
        }
    }

    // ---- stores --------------------------------------------------------------
    #pragma unroll
    for (int mt = 0; mt < 4; mt++) {
        #pragma unroll
        for (int nt = 0; nt < 8; nt++) {
            int row = bm + wm * 64 + mt * 16 + gid;
            int col = bn + wn * 64 + nt * 8 + tg * 2;
            float v0 = acc[mt][nt][0], v1 = acc[mt][nt][1];
            float v2 = acc[mt][nt][2], v3 = acc[mt][nt][3];
            if (mode == 1) {
                float b0 = bias[col], b1 = bias[col + 1];
                v0 = 1.0f / (1.0f + expf(-(v0 + b0)));
                v1 = 1.0f / (1.0f + expf(-(v1 + b1)));
                v2 = 1.0f / (1.0f + expf(-(v2 + b0)));
                v3 = 1.0f / (1.0f + expf(-(v3 + b1)));
            }
            *reinterpret_cast<float2*>(&Out[(size_t)row * Cc + col])       = make_float2(v0, v1);
            *reinterpret_cast<float2*>(&Out[(size_t)(row + 8) * Cc + col]) = make_float2(v2, v3);
        }
    }
}

// ---------------- 4) chunked decayed scan ----------------------------------
__global__ void scan_pass1(const float* __restrict__ k, const float* __restrict__ v,
                           const float* __restrict__ gamma) {
    int blk = blockIdx.x;
    int c  = blk % NCHUNK;
    int bh = blk / NCHUNK;
    int h  = bh % Hh;
    int b  = bh / Hh;
    int d  = threadIdx.x;
    float g = gamma[h];
    size_t idx = ((size_t)(b * Tt + c * LCH)) * Cc + h * DhD + d;
    float S = 0.0f;
    #pragma unroll 4
    for (int i = 0; i < LCH; i++) {
        S = fmaf(g, S, k[idx] * v[idx]);
        idx += Cc;
    }
    g_F[((size_t)bh * NCHUNK + c) * DhD + d] = S;
}

__global__ void scan_pass2(const float* __restrict__ gamma) {
    int tid = blockIdx.x * blockDim.x + threadIdx.x;
    if (tid >= Bb * Hh * DhD) return;
    int d  = tid & (DhD - 1);
    int bh = tid >> 7;
    int h  = bh % Hh;
    float g  = gamma[h];
    float gL = powf(g, (float)LCH);
    float carry = 0.0f;
    for (int c = 0; c < NCHUNK; c++) {
        size_t o = ((size_t)bh * NCHUNK + c) * DhD + d;
        g_carry[o] = carry;
        carry = fmaf(gL, carry, g_F[o]);
    }
}

__global__ void scan_pass3(const float* __restrict__ k, const float* __restrict__ v,
                           const float* __restrict__ q, const float* __restrict__ gate,
                           const float* __restrict__ gamma) {
    int blk = blockIdx.x;
    int c  = blk % NCHUNK;
    int bh = blk / NCHUNK;
    int h  = bh % Hh;
    int b  = bh / Hh;
    int d  = threadIdx.x;
    float g = gamma[h];
    float S = g_carry[((size_t)bh * NCHUNK + c) * DhD + d];
    size_t idx = ((size_t)(b * Tt + c * LCH)) * Cc + h * DhD + d;
    #pragma unroll 4
    for (int i = 0; i < LCH; i++) {
        S = fmaf(g, S, k[idx] * v[idx]);
        g_att[idx] = tf32r(gate[idx] * S * q[idx]);
        idx += Cc;
    }
}

// ---------------- 5) LayerNorm over C=2048 ---------------------------------
__global__ __launch_bounds__(256)
void ln_kernel(const float* __restrict__ y, const float* __restrict__ lw,
               const float* __restrict__ lb, float* __restrict__ out) {
    int row = blockIdx.x;
    int tid = threadIdx.x;
    const float4* yr = reinterpret_cast<const float4*>(y + (size_t)row * Cc);
    float4* orow     = reinterpret_cast<float4*>(out + (size_t)row * Cc);

    float4 v0 = yr[tid];
    float4 v1 = yr[tid + 256];
    float sum = v0.x + v0.y + v0.z + v0.w + v1.x + v1.y + v1.z + v1.w;
    float sq  = v0.x * v0.x + v0.y * v0.y + v0.z * v0.z + v0.w * v0.w
              + v1.x * v1.x + v1.y * v1.y + v1.z * v1.z + v1.w * v1.w;

    #pragma unroll
    for (int o = 16; o; o >>= 1) {
        sum += __shfl_xor_sync(0xffffffffu, sum, o);
        sq  += __shfl_xor_sync(0xffffffffu, sq, o);
    }
    __shared__ float ssum[8], ssq[8];
    __shared__ float s_mu, s_inv;
    int warp = tid >> 5, lane = tid & 31;
    if (lane == 0) { ssum[warp] = sum; ssq[warp] = sq; }
    __syncthreads();
    if (tid == 0) {
        float ts = 0.0f, tq = 0.0f;
        #pragma unroll
        for (int i = 0; i < 8; i++) { ts += ssum[i]; tq += ssq[i]; }
        float mu  = ts / (float)Cc;
        float var = tq / (float)Cc - mu * mu;
        s_mu  = mu;
        s_inv = rsqrtf(var + 1e-5f);
    }
    __syncthreads();
    float mu = s_mu, inv = s_inv;

    const float4 w0 = reinterpret_cast<const float4*>(lw)[tid];
    const float4 w1 = reinterpret_cast<const float4*>(lw)[tid + 256];
    const float4 b0 = reinterpret_cast<const float4*>(lb)[tid];
    const float4 b1 = reinterpret_cast<const float4*>(lb)[tid + 256];

    float4 o0, o1;
    o0.x = (v0.x - mu) * inv * w0.x + b0.x;
    o0.y = (v0.y - mu) * inv * w0.y + b0.y;
    o0.z = (v0.z - mu) * inv * w0.z + b0.z;
    o0.w = (v0.w - mu) * inv * w0.w + b0.w;
    o1.x = (v1.x - mu) * inv * w1.x + b1.x;
    o1.y = (v1.y - mu) * inv * w1.y + b1.y;
    o1.z = (v1.z - mu) * inv * w1.z + b1.z;
    o1.w = (v1.w - mu) * inv * w1.w + b1.w;
    orow[tid]       = o0;
    orow[tid + 256] = o1;
}

// ---------------- host orchestration ---------------------------------------
extern "C" void kernel_launch(void* const* d_in, const int* in_sizes, int n_in,
                              void* d_out, int out_size) {
    (void)in_sizes; (void)n_in; (void)out_size;
    const float* x      = (const float*)d_in[0];
    const float* Wq     = (const float*)d_in[1];
    const float* Wk     = (const float*)d_in[2];
    const float* Wv     = (const float*)d_in[3];
    const float* Wo     = (const float*)d_in[4];
    const float* conv_w = (const float*)d_in[5];
    const float* conv_b = (const float*)d_in[6];
    const float* gate_w = (const float*)d_in[7];
    const float* gate_b = (const float*)d_in[8];
    const float* ln_w   = (const float*)d_in[9];
    const float* ln_b   = (const float*)d_in[10];
    const float* gamma  = (const float*)d_in[11];

    float *p_xconv, *p_q, *p_k, *p_v, *p_gate, *p_att, *p_y;
    float *p_xt, *p_Wqt, *p_Wkt, *p_Wvt, *p_Wot, *p_Wgt;
    cudaGetSymbolAddress((void**)&p_xconv, g_xconv);
    cudaGetSymbolAddress((void**)&p_q, g_q);
    cudaGetSymbolAddress((void**)&p_k, g_k);
    cudaGetSymbolAddress((void**)&p_v, g_v);
    cudaGetSymbolAddress((void**)&p_gate, g_gate);
    cudaGetSymbolAddress((void**)&p_att, g_att);
    cudaGetSymbolAddress((void**)&p_y, g_y);
    cudaGetSymbolAddress((void**)&p_xt, g_xt);
    cudaGetSymbolAddress((void**)&p_Wqt, g_Wqt);
    cudaGetSymbolAddress((void**)&p_Wkt, g_Wkt);
    cudaGetSymbolAddress((void**)&p_Wvt, g_Wvt);
    cudaGetSymbolAddress((void**)&p_Wot, g_Wot);
    cudaGetSymbolAddress((void**)&p_Wgt, g_Wgt);

    cudaFuncSetAttribute(gemm_tf32_w64, cudaFuncAttributeMaxDynamicSharedMemorySize, GEMM_SMEM);

    // 0) pre-round GEMM operands to tf32
    const int wElems = Cc * Cc;
    cvt_tf32_kernel<<<wElems / 1024, 256>>>(Wq, p_Wqt);
    cvt_tf32_kernel<<<wElems / 1024, 256>>>(Wk, p_Wkt);
    cvt_tf32_kernel<<<wElems / 1024, 256>>>(Wv, p_Wvt);
    cvt_tf32_kernel<<<wElems / 1024, 256>>>(Wo, p_Wot);
    cvt_tf32_kernel<<<wElems / 1024, 256>>>(gate_w, p_Wgt);
    cvt_tf32_kernel<<<(Mrows * Cc) / 1024, 256>>>(x, p_xt);

    // 1) depthwise conv + SiLU
    conv_silu_kernel<<<(Mrows * Cc) / 256, 256>>>(x, conv_w, conv_b);

    // 2) projections.  mode: 0 plain, 1 sigmoid+bias, 2 fused per-head l2norm
    dim3 ggrid(Cc / BN, Mrows / BM);   // (8, 128)
    gemm_tf32_w64<<<ggrid, 256, GEMM_SMEM>>>(p_xt,    p_Wqt, p_q,    nullptr, 2);
    gemm_tf32_w64<<<ggrid, 256, GEMM_SMEM>>>(p_xt,    p_Wkt, p_k,    nullptr, 2);
    gemm_tf32_w64<<<ggrid, 256, GEMM_SMEM>>>(p_xt,    p_Wvt, p_v,    nullptr, 0);
    gemm_tf32_w64<<<ggrid, 256, GEMM_SMEM>>>(p_xconv, p_Wgt, p_gate, gate_b, 1);

    // 3) decayed scan (chunked, exact); q/k already l2-normalized in epilogue
    scan_pass1<<<Bb * Hh * NCHUNK, DhD>>>(p_k, p_v, gamma);
    scan_pass2<<<(Bb * Hh * DhD + 127) / 128, 128>>>(gamma);
    scan_pass3<<<Bb * Hh * NCHUNK, DhD>>>(p_k, p_v, p_q, p_gate, gamma);

    // 4) output projection + LayerNorm
    gemm_tf32_w64<<<ggrid, 256, GEMM_SMEM>>>(p_att, p_Wot, p_y, nullptr, 0);
    ln_kernel<<<Mrows, 256>>>(p_y, ln_w, ln_b, (float*)d_out);
}

// round 7
// speedup vs baseline: 1.7913x; 1.5415x over previous
#include <cuda_runtime.h>
#include <cstdint>
#include <cstdio>

// Problem constants
namespace {
constexpr int Bb = 4, Tt = 4096, Cc = 2048, Hh = 16, DhD = 128;
constexpr int Mrows = Bb * Tt;            // 16384
constexpr int NCHUNK = 64;                // scan chunks
constexpr int LCH = Tt / NCHUNK;          // 64 steps per chunk
}

// ---------------- scratch (static device globals; no allocation allowed) ---
__device__ float g_xconv[(size_t)Bb * Tt * Cc];
__device__ float g_q   [(size_t)Bb * Tt * Cc];
__device__ float g_k   [(size_t)Bb * Tt * Cc];
__device__ float g_v   [(size_t)Bb * Tt * Cc];
__device__ float g_gate[(size_t)Bb * Tt * Cc];
__device__ float g_att [(size_t)Bb * Tt * Cc];
__device__ float g_y   [(size_t)Bb * Tt * Cc];
__device__ float g_xt  [(size_t)Bb * Tt * Cc];      // tf32-rounded x
__device__ float g_Wqt [(size_t)Cc * Cc];
__device__ float g_Wkt [(size_t)Cc * Cc];
__device__ float g_Wvt [(size_t)Cc * Cc];
__device__ float g_Wot [(size_t)Cc * Cc];
__device__ float g_Wgt [(size_t)Cc * Cc];
__device__ float g_F    [(size_t)Bb * Hh * NCHUNK * DhD];
__device__ float g_carry[(size_t)Bb * Hh * NCHUNK * DhD];

// ---------------- helpers --------------------------------------------------
__device__ __forceinline__ uint32_t f2tf32(float f) {
    uint32_t u;
    asm("cvt.rna.tf32.f32 %0, %1;" : "=r"(u) : "f"(f));
    return u;
}

__device__ __forceinline__ float tf32r(float f) { return __uint_as_float(f2tf32(f)); }

__device__ __forceinline__ void mma_tf32(float& d0, float& d1, float& d2, float& d3,
                                         uint32_t a0, uint32_t a1, uint32_t a2, uint32_t a3,
                                         uint32_t b0, uint32_t b1) {
    asm volatile(
        "mma.sync.aligned.m16n8k8.row.col.f32.tf32.tf32.f32 "
        "{%0,%1,%2,%3}, {%4,%5,%6,%7}, {%8,%9}, {%0,%1,%2,%3};\n"
        : "+f"(d0), "+f"(d1), "+f"(d2), "+f"(d3)
        : "r"(a0), "r"(a1), "r"(a2), "r"(a3), "r"(b0), "r"(b1));
}

// ---------------- 0) tf32 pre-round (vectorized) ----------------------------
__global__ void cvt_tf32_kernel(const float* __restrict__ in, float* __restrict__ out) {
    int i = blockIdx.x * blockDim.x + threadIdx.x;
    float4 v = reinterpret_cast<const float4*>(in)[i];
    v.x = tf32r(v.x); v.y = tf32r(v.y); v.z = tf32r(v.z); v.w = tf32r(v.w);
    reinterpret_cast<float4*>(out)[i] = v;
}

// ---------------- 1) causal depthwise conv (K=4) + SiLU (tf32-rounded out) --
__global__ void conv_silu_kernel(const float* __restrict__ x,
                                 const float* __restrict__ w,
                                 const float* __restrict__ bias) {
    int idx = blockIdx.x * blockDim.x + threadIdx.x;   // over B*T*C
    int c  = idx & (Cc - 1);
    int bt = idx >> 11;                                 // /2048
    int t  = bt & (Tt - 1);
    float acc = bias[c];
    const float* wr = w + c * 4;
    int base = (bt - t) * Cc + c;                       // b*T*C + c
    #pragma unroll
    for (int j = 0; j < 4; j++) {
        int tt = t - 3 + j;
        if (tt >= 0) acc = fmaf(x[base + tt * Cc], wr[j], acc);
    }
    float s = acc / (1.0f + expf(-acc));                // SiLU
    g_xconv[idx] = tf32r(s);                            // pre-round for GEMM
}

// ---------------- 2) TF32 tensor-core GEMM, cp.async 3-stage pipeline ------
// EXACT round-2 mainloop (proven fastest). Out = A[M,K] * W[N,K]^T.
// mode 0: plain.  mode 1: sigmoid(out + bias[col]).  mode 2: per-row l2norm
// over the 128-col tile (tile == one head since BN=128).
// smem layout per (matrix,stage): 128 rows x 16 words, XOR-swizzled chunks:
//   word(row,k) at row*16 + (((k>>2) ^ ((row>>1)&3))<<2) + (k&3)
__global__ __launch_bounds__(256)
void gemm_tf32_pipe(const float* __restrict__ A, const float* __restrict__ W,
                    float* __restrict__ Out, int M, int N, int K,
                    const float* __restrict__ bias, int mode) {
    constexpr int BM = 128, BN = 128, BKk = 16, ST = 3;
    __shared__ uint32_t As[ST][BM * BKk];
    __shared__ uint32_t Bs[ST][BN * BKk];
    __shared__ float red[128 * 4];

    const int tid  = threadIdx.x;
    const int warp = tid >> 5, lane = tid & 31;
    const int gid  = lane >> 2, tg = lane & 3;
    const int wm   = warp & 1;       // 0..1  -> 64-row slab
    const int wn   = warp >> 1;      // 0..3  -> 32-col slab
    const int bm   = blockIdx.y * BM;
    const int bn   = blockIdx.x * BN;

    const int lr = tid >> 2;         // 0..63  (loader row)
    const int lc = tid & 3;          // chunk 0..3

    uint32_t sA = (uint32_t)__cvta_generic_to_shared(&As[0][0]);
    uint32_t sB = (uint32_t)__cvta_generic_to_shared(&Bs[0][0]);

    auto issue = [&](int s, int k0) {
        #pragma unroll
        for (int r = 0; r < 2; r++) {
            int row = lr + r * 64;
            int sw  = (row >> 1) & 3;
            uint32_t off = (uint32_t)(s * BM * BKk + row * 16 + ((lc ^ sw) << 2)) * 4u;
            const float* gA = A + (size_t)(bm + row) * K + k0 + lc * 4;
            asm volatile("cp.async.cg.shared.global [%0], [%1], 16;\n"
                         :: "r"(sA + off), "l"(gA));
            const float* gB = W + (size_t)(bn + row) * K + k0 + lc * 4;
            asm volatile("cp.async.cg.shared.global [%0], [%1], 16;\n"
                         :: "r"(sB + off), "l"(gB));
        }
        asm volatile("cp.async.commit_group;\n");
    };

    float acc[4][4][4] = {};

    issue(0, 0);
    issue(1, BKk);

    int s = 0;
    for (int k0 = 0; k0 < K; k0 += BKk) {
        asm volatile("cp.async.wait_group 1;\n" ::: "memory");
        __syncthreads();

        int kn = k0 + 2 * BKk;
        if (kn < K) {
            int s2 = s + 2; if (s2 >= ST) s2 -= ST;
            issue(s2, kn);
        }

        const uint32_t* Ab = &As[s][0];
        const uint32_t* Bb = &Bs[s][0];
        #pragma unroll
        for (int kk = 0; kk < BKk; kk += 8) {
            const int c0 = kk >> 2;
            uint32_t af[4][4], bf[4][2];
            #pragma unroll
            for (int mt = 0; mt < 4; mt++) {
                int row = wm * 64 + mt * 16 + gid;        // row&15 == gid
                int sw  = (row >> 1) & 3;
                int b0i = row * 16 + tg;
                int b1i = (row + 8) * 16 + tg;
                af[mt][0] = Ab[b0i + ((c0 ^ sw) << 2)];
                af[mt][1] = Ab[b1i + ((c0 ^ sw) << 2)];
                af[mt][2] = Ab[b0i + (((c0 + 1) ^ sw) << 2)];
                af[mt][3] = Ab[b1i + (((c0 + 1) ^ sw) << 2)];
            }
            #pragma unroll
            for (int nt = 0; nt < 4; nt++) {
                int col = wn * 32 + nt * 8 + gid;
                int sw  = (col >> 1) & 3;
                int bi  = col * 16 + tg;
                bf[nt][0] = Bb[bi + ((c0 ^ sw) << 2)];
                bf[nt][1] = Bb[bi + (((c0 + 1) ^ sw) << 2)];
            }
            #pragma unroll
            for (int mt = 0; mt < 4; mt++)
                #pragma unroll
                for (int nt = 0; nt < 4; nt++)
                    mma_tf32(acc[mt][nt][0], acc[mt][nt][1], acc[mt][nt][2], acc[mt][nt][3],
                             af[mt][0], af[mt][1], af[mt][2], af[mt][3],
                             bf[nt][0], bf[nt][1]);
        }
        s++; if (s >= ST) s = 0;
    }

    // ---- fused l2norm over the 128-col tile (mode 2, tile == one head) -----
    if (mode == 2) {
        __syncthreads();   // all warps done with As/Bs; red reuse safe
        float invLo[4], invHi[4];
        #pragma unroll
        for (int mt = 0; mt < 4; mt++) {
            float slo = 0.0f, shi = 0.0f;
            #pragma unroll
            for (int nt = 0; nt < 4; nt++) {
                slo = fmaf(acc[mt][nt][0], acc[mt][nt][0], slo);
                slo = fmaf(acc[mt][nt][1], acc[mt][nt][1], slo);
                shi = fmaf(acc[mt][nt][2], acc[mt][nt][2], shi);
                shi = fmaf(acc[mt][nt][3], acc[mt][nt][3], shi);
            }
            // quad reduction: lanes tg=0..3 hold same row
            slo += __shfl_xor_sync(0xffffffffu, slo, 1);
            slo += __shfl_xor_sync(0xffffffffu, slo, 2);
            shi += __shfl_xor_sync(0xffffffffu, shi, 1);
            shi += __shfl_xor_sync(0xffffffffu, shi, 2);
            if (tg == 0) {
                int r = wm * 64 + mt * 16 + gid;
                red[r * 4 + wn]       = slo;
                red[(r + 8) * 4 + wn] = shi;
            }
        }
        __syncthreads();
        #pragma unroll
        for (int mt = 0; mt < 4; mt++) {
            int r = wm * 64 + mt * 16 + gid;
            float slo = red[r * 4 + 0] + red[r * 4 + 1] + red[r * 4 + 2] + red[r * 4 + 3];
            float shi = red[(r + 8) * 4 + 0] + red[(r + 8) * 4 + 1]
                      + red[(r + 8) * 4 + 2] + red[(r + 8) * 4 + 3];
            invLo[mt] = 1.0f / fmaxf(sqrtf(slo), 1e-12f);
            invHi[mt] = 1.0f / fmaxf(sqrtf(shi), 1e-12f);
        }
        #pragma unroll
        for (int mt = 0; mt < 4; mt++)
            #pragma unroll
            for (int nt = 0; nt < 4; nt++) {
                acc[mt][nt][0] *= invLo[mt];
                acc[mt][nt][1] *= invLo[mt];
                acc[mt][nt][2] *= invHi[mt];
                acc[mt][nt][3] *= invHi[mt];
            }
    }

    // epilogue stores
    #pragma unroll
    for (int mt = 0; mt < 4; mt++) {
        #pragma unroll
        for (int nt = 0; nt < 4; nt++) {
            int row = bm + wm * 64 + mt * 16 + gid;
            int col = bn + wn * 32 + nt * 8 + tg * 2;
            float v0 = acc[mt][nt][0], v1 = acc[mt][nt][1];
            float v2 = acc[mt][nt][2], v3 = acc[mt][nt][3];
            if (mode == 1) {
                float b0 = bias[col], b1 = bias[col + 1];
                v0 = 1.0f / (1.0f + expf(-(v0 + b0)));
                v1 = 1.0f / (1.0f + expf(-(v1 + b1)));
                v2 = 1.0f / (1.0f + expf(-(v2 + b0)));
                v3 = 1.0f / (1.0f + expf(-(v3 + b1)));
            }
            *reinterpret_cast<float2*>(&Out[(size_t)row * N + col])       = make_float2(v0, v1);
            *reinterpret_cast<float2*>(&Out[(size_t)(row + 8) * N + col]) = make_float2(v2, v3);
        }
    }
}

// ---------------- 4) chunked decayed scan ----------------------------------
__global__ void scan_pass1(const float* __restrict__ k, const float* __restrict__ v,
                           const float* __restrict__ gamma) {
    int blk = blockIdx.x;
    int c  = blk % NCHUNK;
    int bh = blk / NCHUNK;
    int h  = bh % Hh;
    int b  = bh / Hh;
    int d  = threadIdx.x;
    float g = gamma[h];
    size_t idx = ((size_t)(b * Tt + c * LCH)) * Cc + h * DhD + d;
    float S = 0.0f;
    #pragma unroll 4
    for (int i = 0; i < LCH; i++) {
        S = fmaf(g, S, k[idx] * v[idx]);
        idx += Cc;
    }
    g_F[((size_t)bh * NCHUNK + c) * DhD + d] = S;
}

__global__ void scan_pass2(const float* __restrict__ gamma) {
    int tid = blockIdx.x * blockDim.x + threadIdx.x;
    if (tid >= Bb * Hh * DhD) return;
    int d  = tid & (DhD - 1);
    int bh = tid >> 7;
    int h  = bh % Hh;
    float g  = gamma[h];
    float gL = powf(g, (float)LCH);     // exact 1.0 for gamma=1 head
    float carry = 0.0f;
    for (int c = 0; c < NCHUNK; c++) {
        size_t o = ((size_t)bh * NCHUNK + c) * DhD + d;
        g_carry[o] = carry;
        carry = fmaf(gL, carry, g_F[o]);
    }
}

__global__ void scan_pass3(const float* __restrict__ k, const float* __restrict__ v,
                           const float* __restrict__ q, const float* __restrict__ gate,
                           const float* __restrict__ gamma) {
    int blk = blockIdx.x;
    int c  = blk % NCHUNK;
    int bh = blk / NCHUNK;
    int h  = bh % Hh;
    int b  = bh / Hh;
    int d  = threadIdx.x;
    float g = gamma[h];
    float S = g_carry[((size_t)bh * NCHUNK + c) * DhD + d];
    size_t idx = ((size_t)(b * Tt + c * LCH)) * Cc + h * DhD + d;
    #pragma unroll 4
    for (int i = 0; i < LCH; i++) {
        S = fmaf(g, S, k[idx] * v[idx]);
        g_att[idx] = tf32r(gate[idx] * S * q[idx]);
        idx += Cc;
    }
}

// ---------------- 5) LayerNorm over C=2048 ---------------------------------
__global__ __launch_bounds__(256)
void ln_kernel(const float* __restrict__ y, const float* __restrict__ lw,
               const float* __restrict__ lb, float* __restrict__ out) {
    int row = blockIdx.x;
    int tid = threadIdx.x;
    const float4* yr = reinterpret_cast<const float4*>(y + (size_t)row * Cc);
    float4* orow     = reinterpret_cast<float4*>(out + (size_t)row * Cc);

    float4 v0 = yr[tid];
    float4 v1 = yr[tid + 256];
    float sum = v0.x + v0.y + v0.z + v0.w + v1.x + v1.y + v1.z + v1.w;
    float sq  = v0.x * v0.x + v0.y * v0.y + v0.z * v0.z + v0.w * v0.w
              + v1.x * v1.x + v1.y * v1.y + v1.z * v1.z + v1.w * v1.w;

    #pragma unroll
    for (int o = 16; o; o >>= 1) {
        sum += __shfl_xor_sync(0xffffffffu, sum, o);
        sq  += __shfl_xor_sync(0xffffffffu, sq, o);
    }
    __shared__ float ssum[8], ssq[8];
    __shared__ float s_mu, s_inv;
    int warp = tid >> 5, lane = tid & 31;
    if (lane == 0) { ssum[warp] = sum; ssq[warp] = sq; }
    __syncthreads();
    if (tid == 0) {
        float ts = 0.0f, tq = 0.0f;
        #pragma unroll
        for (int i = 0; i < 8; i++) { ts += ssum[i]; tq += ssq[i]; }
        float mu  = ts / (float)Cc;
        float var = tq / (float)Cc - mu * mu;
        s_mu  = mu;
        s_inv = rsqrtf(var + 1e-5f);
    }
    __syncthreads();
    float mu = s_mu, inv = s_inv;

    const float4 w0 = reinterpret_cast<const float4*>(lw)[tid];
    const float4 w1 = reinterpret_cast<const float4*>(lw)[tid + 256];
    const float4 b0 = reinterpret_cast<const float4*>(lb)[tid];
    const float4 b1 = reinterpret_cast<const float4*>(lb)[tid + 256];

    float4 o0, o1;
    o0.x = (v0.x - mu) * inv * w0.x + b0.x;
    o0.y = (v0.y - mu) * inv * w0.y + b0.y;
    o0.z = (v0.z - mu) * inv * w0.z + b0.z;
    o0.w = (v0.w - mu) * inv * w0.w + b0.w;
    o1.x = (v1.x - mu) * inv * w1.x + b1.x;
    o1.y = (v1.y - mu) * inv * w1.y + b1.y;
    o1.z = (v1.z - mu) * inv * w1.z + b1.z;
    o1.w = (v1.w - mu) * inv * w1.w + b1.w;
    orow[tid]       = o0;
    orow[tid + 256] = o1;
}

// ---------------- host orchestration ---------------------------------------
extern "C" void kernel_launch(void* const* d_in, const int* in_sizes, int n_in,
                              void* d_out, int out_size) {
    (void)in_sizes; (void)n_in; (void)out_size;
    const float* x      = (const float*)d_in[0];
    const float* Wq     = (const float*)d_in[1];
    const float* Wk     = (const float*)d_in[2];
    const float* Wv     = (const float*)d_in[3];
    const float* Wo     = (const float*)d_in[4];
    const float* conv_w = (const float*)d_in[5];
    const float* conv_b = (const float*)d_in[6];
    const float* gate_w = (const float*)d_in[7];
    const float* gate_b = (const float*)d_in[8];
    const float* ln_w   = (const float*)d_in[9];
    const float* ln_b   = (const float*)d_in[10];
    const float* gamma  = (const float*)d_in[11];

    float *p_xconv, *p_q, *p_k, *p_v, *p_gate, *p_att, *p_y;
    float *p_xt, *p_Wqt, *p_Wkt, *p_Wvt, *p_Wot, *p_Wgt;
    cudaGetSymbolAddress((void**)&p_xconv, g_xconv);
    cudaGetSymbolAddress((void**)&p_q, g_q);
    cudaGetSymbolAddress((void**)&p_k, g_k);
    cudaGetSymbolAddress((void**)&p_v, g_v);
    cudaGetSymbolAddress((void**)&p_gate, g_gate);
    cudaGetSymbolAddress((void**)&p_att, g_att);
    cudaGetSymbolAddress((void**)&p_y, g_y);
    cudaGetSymbolAddress((void**)&p_xt, g_xt);
    cudaGetSymbolAddress((void**)&p_Wqt, g_Wqt);
    cudaGetSymbolAddress((void**)&p_Wkt, g_Wkt);
    cudaGetSymbolAddress((void**)&p_Wvt, g_Wvt);
    cudaGetSymbolAddress((void**)&p_Wot, g_Wot);
    cudaGetSymbolAddress((void**)&p_Wgt, g_Wgt);

    // 0) pre-round GEMM operands to tf32 (pure-bandwidth passes)
    const int wElems = Cc * Cc;            // 4.19M
    cvt_tf32_kernel<<<wElems / 1024, 256>>>(Wq, p_Wqt);
    cvt_tf32_kernel<<<wElems / 1024, 256>>>(Wk, p_Wkt);
    cvt_tf32_kernel<<<wElems / 1024, 256>>>(Wv, p_Wvt);
    cvt_tf32_kernel<<<wElems / 1024, 256>>>(Wo, p_Wot);
    cvt_tf32_kernel<<<wElems / 1024, 256>>>(gate_w, p_Wgt);
    cvt_tf32_kernel<<<(Mrows * Cc) / 1024, 256>>>(x, p_xt);

    // 1) depthwise conv + SiLU (tf32-rounded output)
    conv_silu_kernel<<<(Mrows * Cc) / 256, 256>>>(x, conv_w, conv_b);

    // 2) projections (TF32 tensor cores, cp.async pipelined)
    //    mode: 0 plain, 1 sigmoid+bias, 2 fused per-head l2norm
    dim3 ggrid(Cc / 128, Mrows / 128);   // (16, 128)
    gemm_tf32_pipe<<<ggrid, 256>>>(p_xt,    p_Wqt, p_q,    Mrows, Cc, Cc, nullptr, 2);
    gemm_tf32_pipe<<<ggrid, 256>>>(p_xt,    p_Wkt, p_k,    Mrows, Cc, Cc, nullptr, 2);
    gemm_tf32_pipe<<<ggrid, 256>>>(p_xt,    p_Wvt, p_v,    Mrows, Cc, Cc, nullptr, 0);
    gemm_tf32_pipe<<<ggrid, 256>>>(p_xconv, p_Wgt, p_gate, Mrows, Cc, Cc, gate_b, 1);

    // 3) decayed scan (chunked, exact); q/k already l2-normalized in epilogue
    scan_pass1<<<Bb * Hh * NCHUNK, DhD>>>(p_k, p_v, gamma);
    scan_pass2<<<(Bb * Hh * DhD + 127) / 128, 128>>>(gamma);
    scan_pass3<<<Bb * Hh * NCHUNK, DhD>>>(p_k, p_v, p_q, p_gate, gamma);

    // 4) output projection + LayerNorm
    gemm_tf32_pipe<<<ggrid, 256>>>(p_att, p_Wot, p_y, Mrows, Cc, Cc, nullptr, 0);
    ln_kernel<<<Mrows, 256>>>(p_y, ln_w, ln_b, (float*)d_out);
}

// round 8
// speedup vs baseline: 1.8011x; 1.0055x over previous
#include <cuda_runtime.h>
#include <cstdint>
#include <cstdio>

// Problem constants
namespace {
constexpr int Bb = 4, Tt = 4096, Cc = 2048, Hh = 16, DhD = 128;
constexpr int Mrows = Bb * Tt;            // 16384
constexpr int NCHUNK = 64;                // scan chunks
constexpr int LCH = Tt / NCHUNK;          // 64 steps per chunk
}

// ---------------- scratch (static device globals; no allocation allowed) ---
__device__ float g_xconv[(size_t)Bb * Tt * Cc];
__device__ float g_q   [(size_t)Bb * Tt * Cc];
__device__ float g_k   [(size_t)Bb * Tt * Cc];
__device__ float g_v   [(size_t)Bb * Tt * Cc];
__device__ float g_gate[(size_t)Bb * Tt * Cc];
__device__ float g_att [(size_t)Bb * Tt * Cc];
__device__ float g_y   [(size_t)Bb * Tt * Cc];
__device__ float g_xt  [(size_t)Bb * Tt * Cc];      // tf32-rounded x
__device__ float g_Wqt [(size_t)Cc * Cc];
__device__ float g_Wkt [(size_t)Cc * Cc];
__device__ float g_Wvt [(size_t)Cc * Cc];
__device__ float g_Wot [(size_t)Cc * Cc];
__device__ float g_Wgt [(size_t)Cc * Cc];
__device__ float g_F    [(size_t)Bb * Hh * NCHUNK * DhD];
__device__ float g_carry[(size_t)Bb * Hh * NCHUNK * DhD];

// ---------------- helpers --------------------------------------------------
__device__ __forceinline__ uint32_t f2tf32(float f) {
    uint32_t u;
    asm("cvt.rna.tf32.f32 %0, %1;" : "=r"(u) : "f"(f));
    return u;
}

__device__ __forceinline__ float tf32r(float f) { return __uint_as_float(f2tf32(f)); }

__device__ __forceinline__ void mma_tf32(float& d0, float& d1, float& d2, float& d3,
                                         uint32_t a0, uint32_t a1, uint32_t a2, uint32_t a3,
                                         uint32_t b0, uint32_t b1) {
    asm volatile(
        "mma.sync.aligned.m16n8k8.row.col.f32.tf32.tf32.f32 "
        "{%0,%1,%2,%3}, {%4,%5,%6,%7}, {%8,%9}, {%0,%1,%2,%3};\n"
        : "+f"(d0), "+f"(d1), "+f"(d2), "+f"(d3)
        : "r"(a0), "r"(a1), "r"(a2), "r"(a3), "r"(b0), "r"(b1));
}

// ---------------- 0) tf32 pre-round for the 5 weight matrices (one launch) --
__global__ void cvt5_tf32_kernel(const float* __restrict__ w0, float* __restrict__ o0,
                                 const float* __restrict__ w1, float* __restrict__ o1,
                                 const float* __restrict__ w2, float* __restrict__ o2,
                                 const float* __restrict__ w3, float* __restrict__ o3,
                                 const float* __restrict__ w4, float* __restrict__ o4) {
    // 4096 blocks per weight segment (Cc*Cc/1024 = 4096)
    const int seg = blockIdx.x >> 12;
    const int i   = (blockIdx.x & 4095) * 256 + threadIdx.x;
    const float* in;
    float* out;
    switch (seg) {
        case 0: in = w0; out = o0; break;
        case 1: in = w1; out = o1; break;
        case 2: in = w2; out = o2; break;
        case 3: in = w3; out = o3; break;
        default: in = w4; out = o4; break;
    }
    float4 v = reinterpret_cast<const float4*>(in)[i];
    v.x = tf32r(v.x); v.y = tf32r(v.y); v.z = tf32r(v.z); v.w = tf32r(v.w);
    reinterpret_cast<float4*>(out)[i] = v;
}

// ---------------- 1) causal depthwise conv (K=4) + SiLU + x tf32 side-out ---
// float4 over channels: each thread does 4 consecutive channels at one (b,t).
__global__ void conv_silu_kernel(const float* __restrict__ x,
                                 const float* __restrict__ w,
                                 const float* __restrict__ bias) {
    int vid = blockIdx.x * blockDim.x + threadIdx.x;    // over B*T*C/4
    int cq  = vid & (Cc / 4 - 1);                       // channel quad
    int bt  = vid >> 9;                                 // /(2048/4)
    int t   = bt & (Tt - 1);
    int c   = cq * 4;

    const float4* x4 = reinterpret_cast<const float4*>(x);
    int base = (bt - t) * (Cc / 4) + cq;                // b*T*C/4 + cq

    // weights: rows c..c+3, 4 taps each (row-contiguous float4)
    float4 wr0 = reinterpret_cast<const float4*>(w)[c + 0];
    float4 wr1 = reinterpret_cast<const float4*>(w)[c + 1];
    float4 wr2 = reinterpret_cast<const float4*>(w)[c + 2];
    float4 wr3 = reinterpret_cast<const float4*>(w)[c + 3];
    float4 bb  = reinterpret_cast<const float4*>(bias)[cq];

    float4 a = bb;
    float4 xt3;   // the j=3 tap = x at time t (also the tf32 side output)
    #pragma unroll
    for (int j = 0; j < 4; j++) {
        int tt = t - 3 + j;
        if (tt >= 0) {
            float4 xv = x4[base + tt * (Cc / 4)];
            if (j == 3) xt3 = xv;
            float wj0 = (&wr0.x)[j], wj1 = (&wr1.x)[j], wj2 = (&wr2.x)[j], wj3 = (&wr3.x)[j];
            a.x = fmaf(xv.x, wj0, a.x);
            a.y = fmaf(xv.y, wj1, a.y);
            a.z = fmaf(xv.z, wj2, a.z);
            a.w = fmaf(xv.w, wj3, a.w);
        }
    }
    // (t >= 3 always hits j==3; for t<3, j==3 means tt=t>=0 so xt3 always set)

    float4 s;
    s.x = tf32r(a.x / (1.0f + expf(-a.x)));
    s.y = tf32r(a.y / (1.0f + expf(-a.y)));
    s.z = tf32r(a.z / (1.0f + expf(-a.z)));
    s.w = tf32r(a.w / (1.0f + expf(-a.w)));
    reinterpret_cast<float4*>(g_xconv)[vid] = s;

    float4 xr;
    xr.x = tf32r(xt3.x); xr.y = tf32r(xt3.y); xr.z = tf32r(xt3.z); xr.w = tf32r(xt3.w);
    reinterpret_cast<float4*>(g_xt)[vid] = xr;
}

// ---------------- 2) TF32 tensor-core GEMM, cp.async 3-stage pipeline ------
// EXACT round-2 mainloop (proven fastest). Out = A[M,K] * W[N,K]^T.
// mode 0: plain.  mode 1: sigmoid(out + bias[col]).  mode 2: per-row l2norm
// over the 128-col tile (tile == one head since BN=128).
// smem layout per (matrix,stage): 128 rows x 16 words, XOR-swizzled chunks:
//   word(row,k) at row*16 + (((k>>2) ^ ((row>>1)&3))<<2) + (k&3)
__global__ __launch_bounds__(256)
void gemm_tf32_pipe(const float* __restrict__ A, const float* __restrict__ W,
                    float* __restrict__ Out, int M, int N, int K,
                    const float* __restrict__ bias, int mode) {
    constexpr int BM = 128, BN = 128, BKk = 16, ST = 3;
    __shared__ uint32_t As[ST][BM * BKk];
    __shared__ uint32_t Bs[ST][BN * BKk];
    __shared__ float red[128 * 4];

    const int tid  = threadIdx.x;
    const int warp = tid >> 5, lane = tid & 31;
    const int gid  = lane >> 2, tg = lane & 3;
    const int wm   = warp & 1;       // 0..1  -> 64-row slab
    const int wn   = warp >> 1;      // 0..3  -> 32-col slab
    const int bm   = blockIdx.y * BM;
    const int bn   = blockIdx.x * BN;

    const int lr = tid >> 2;         // 0..63  (loader row)
    const int lc = tid & 3;          // chunk 0..3

    uint32_t sA = (uint32_t)__cvta_generic_to_shared(&As[0][0]);
    uint32_t sB = (uint32_t)__cvta_generic_to_shared(&Bs[0][0]);

    auto issue = [&](int s, int k0) {
        #pragma unroll
        for (int r = 0; r < 2; r++) {
            int row = lr + r * 64;
            int sw  = (row >> 1) & 3;
            uint32_t off = (uint32_t)(s * BM * BKk + row * 16 + ((lc ^ sw) << 2)) * 4u;
            const float* gA = A + (size_t)(bm + row) * K + k0 + lc * 4;
            asm volatile("cp.async.cg.shared.global [%0], [%1], 16;\n"
                         :: "r"(sA + off), "l"(gA));
            const float* gB = W + (size_t)(bn + row) * K + k0 + lc * 4;
            asm volatile("cp.async.cg.shared.global [%0], [%1], 16;\n"
                         :: "r"(sB + off), "l"(gB));
        }
        asm volatile("cp.async.commit_group;\n");
    };

    float acc[4][4][4] = {};

    issue(0, 0);
    issue(1, BKk);

    int s = 0;
    for (int k0 = 0; k0 < K; k0 += BKk) {
        asm volatile("cp.async.wait_group 1;\n" ::: "memory");
        __syncthreads();

        int kn = k0 + 2 * BKk;
        if (kn < K) {
            int s2 = s + 2; if (s2 >= ST) s2 -= ST;
            issue(s2, kn);
        }

        const uint32_t* Ab = &As[s][0];
        const uint32_t* Bb = &Bs[s][0];
        #pragma unroll
        for (int kk = 0; kk < BKk; kk += 8) {
            const int c0 = kk >> 2;
            uint32_t af[4][4], bf[4][2];
            #pragma unroll
            for (int mt = 0; mt < 4; mt++) {
                int row = wm * 64 + mt * 16 + gid;        // row&15 == gid
                int sw  = (row >> 1) & 3;
                int b0i = row * 16 + tg;
                int b1i = (row + 8) * 16 + tg;
                af[mt][0] = Ab[b0i + ((c0 ^ sw) << 2)];
                af[mt][1] = Ab[b1i + ((c0 ^ sw) << 2)];
                af[mt][2] = Ab[b0i + (((c0 + 1) ^ sw) << 2)];
                af[mt][3] = Ab[b1i + (((c0 + 1) ^ sw) << 2)];
            }
            #pragma unroll
            for (int nt = 0; nt < 4; nt++) {
                int col = wn * 32 + nt * 8 + gid;
                int sw  = (col >> 1) & 3;
                int bi  = col * 16 + tg;
                bf[nt][0] = Bb[bi + ((c0 ^ sw) << 2)];
                bf[nt][1] = Bb[bi + (((c0 + 1) ^ sw) << 2)];
            }
            #pragma unroll
            for (int mt = 0; mt < 4; mt++)
                #pragma unroll
                for (int nt = 0; nt < 4; nt++)
                    mma_tf32(acc[mt][nt][0], acc[mt][nt][1], acc[mt][nt][2], acc[mt][nt][3],
                             af[mt][0], af[mt][1], af[mt][2], af[mt][3],
                             bf[nt][0], bf[nt][1]);
        }
        s++; if (s >= ST) s = 0;
    }

    // ---- fused l2norm over the 128-col tile (mode 2, tile == one head) -----
    if (mode == 2) {
        __syncthreads();   // all warps done with As/Bs; red reuse safe
        float invLo[4], invHi[4];
        #pragma unroll
        for (int mt = 0; mt < 4; mt++) {
            float slo = 0.0f, shi = 0.0f;
            #pragma unroll
            for (int nt = 0; nt < 4; nt++) {
                slo = fmaf(acc[mt][nt][0], acc[mt][nt][0], slo);
                slo = fmaf(acc[mt][nt][1], acc[mt][nt][1], slo);
                shi = fmaf(acc[mt][nt][2], acc[mt][nt][2], shi);
                shi = fmaf(acc[mt][nt][3], acc[mt][nt][3], shi);
            }
            // quad reduction: lanes tg=0..3 hold same row
            slo += __shfl_xor_sync(0xffffffffu, slo, 1);
            slo += __shfl_xor_sync(0xffffffffu, slo, 2);
            shi += __shfl_xor_sync(0xffffffffu, shi, 1);
            shi += __shfl_xor_sync(0xffffffffu, shi, 2);
            if (tg == 0) {
                int r = wm * 64 + mt * 16 + gid;
                red[r * 4 + wn]       = slo;
                red[(r + 8) * 4 + wn] = shi;
            }
        }
        __syncthreads();
        #pragma unroll
        for (int mt = 0; mt < 4; mt++) {
            int r = wm * 64 + mt * 16 + gid;
            float slo = red[r * 4 + 0] + red[r * 4 + 1] + red[r * 4 + 2] + red[r * 4 + 3];
            float shi = red[(r + 8) * 4 + 0] + red[(r + 8) * 4 + 1]
                      + red[(r + 8) * 4 + 2] + red[(r + 8) * 4 + 3];
            invLo[mt] = 1.0f / fmaxf(sqrtf(slo), 1e-12f);
            invHi[mt] = 1.0f / fmaxf(sqrtf(shi), 1e-12f);
        }
        #pragma unroll
        for (int mt = 0; mt < 4; mt++)
            #pragma unroll
            for (int nt = 0; nt < 4; nt++) {
                acc[mt][nt][0] *= invLo[mt];
                acc[mt][nt][1] *= invLo[mt];
                acc[mt][nt][2] *= invHi[mt];
                acc[mt][nt][3] *= invHi[mt];
            }
    }

    // epilogue stores
    #pragma unroll
    for (int mt = 0; mt < 4; mt++) {
        #pragma unroll
        for (int nt = 0; nt < 4; nt++) {
            int row = bm + wm * 64 + mt * 16 + gid;
            int col = bn + wn * 32 + nt * 8 + tg * 2;
            float v0 = acc[mt][nt][0], v1 = acc[mt][nt][1];
            float v2 = acc[mt][nt][2], v3 = acc[mt][nt][3];
            if (mode == 1) {
                float b0 = bias[col], b1 = bias[col + 1];
                v0 = 1.0f / (1.0f + expf(-(v0 + b0)));
                v1 = 1.0f / (1.0f + expf(-(v1 + b1)));
                v2 = 1.0f / (1.0f + expf(-(v2 + b0)));
                v3 = 1.0f / (1.0f + expf(-(v3 + b1)));
            }
            *reinterpret_cast<float2*>(&Out[(size_t)row * N + col])       = make_float2(v0, v1);
            *reinterpret_cast<float2*>(&Out[(size_t)(row + 8) * N + col]) = make_float2(v2, v3);
        }
    }
}

// ---------------- 4) chunked decayed scan ----------------------------------
__global__ void scan_pass1(const float* __restrict__ k, const float* __restrict__ v,
                           const float* __restrict__ gamma) {
    int blk = blockIdx.x;
    int c  = blk % NCHUNK;
    int bh = blk / NCHUNK;
    int h  = bh % Hh;
    int b  = bh / Hh;
    int d  = threadIdx.x;
    float g = gamma[h];
    size_t idx = ((size_t)(b * Tt + c * LCH)) * Cc + h * DhD + d;
    float S = 0.0f;
    #pragma unroll 4
    for (int i = 0; i < LCH; i++) {
        S = fmaf(g, S, k[idx] * v[idx]);
        idx += Cc;
    }
    g_F[((size_t)bh * NCHUNK + c) * DhD + d] = S;
}

__global__ void scan_pass2(const float* __restrict__ gamma) {
    int tid = blockIdx.x * blockDim.x + threadIdx.x;
    if (tid >= Bb * Hh * DhD) return;
    int d  = tid & (DhD - 1);
    int bh = tid >> 7;
    int h  = bh % Hh;
    float g  = gamma[h];
    float gL = powf(g, (float)LCH);     // exact 1.0 for gamma=1 head
    float carry = 0.0f;
    for (int c = 0; c < NCHUNK; c++) {
        size_t o = ((size_t)bh * NCHUNK + c) * DhD + d;
        g_carry[o] = carry;
        carry = fmaf(gL, carry, g_F[o]);
    }
}

__global__ void scan_pass3(const float* __restrict__ k, const float* __restrict__ v,
                           const float* __restrict__ q, const float* __restrict__ gate,
                           const float* __restrict__ gamma) {
    int blk = blockIdx.x;
    int c  = blk % NCHUNK;
    int bh = blk / NCHUNK;
    int h  = bh % Hh;
    int b  = bh / Hh;
    int d  = threadIdx.x;
    float g = gamma[h];
    float S = g_carry[((size_t)bh * NCHUNK + c) * DhD + d];
    size_t idx = ((size_t)(b * Tt + c * LCH)) * Cc + h * DhD + d;
    #pragma unroll 4
    for (int i = 0; i < LCH; i++) {
        S = fmaf(g, S, k[idx] * v[idx]);
        g_att[idx] = tf32r(gate[idx] * S * q[idx]);
        idx += Cc;
    }
}

// ---------------- 5) LayerNorm over C=2048 ---------------------------------
__global__ __launch_bounds__(256)
void ln_kernel(const float* __restrict__ y, const float* __restrict__ lw,
               const float* __restrict__ lb, float* __restrict__ out) {
    int row = blockIdx.x;
    int tid = threadIdx.x;
    const float4* yr = reinterpret_cast<const float4*>(y + (size_t)row * Cc);
    float4* orow     = reinterpret_cast<float4*>(out + (size_t)row * Cc);

    float4 v0 = yr[tid];
    float4 v1 = yr[tid + 256];
    float sum = v0.x + v0.y + v0.z + v0.w + v1.x + v1.y + v1.z + v1.w;
    float sq  = v0.x * v0.x + v0.y * v0.y + v0.z * v0.z + v0.w * v0.w
              + v1.x * v1.x + v1.y * v1.y + v1.z * v1.z + v1.w * v1.w;

    #pragma unroll
    for (int o = 16; o; o >>= 1) {
        sum += __shfl_xor_sync(0xffffffffu, sum, o);
        sq  += __shfl_xor_sync(0xffffffffu, sq, o);
    }
    __shared__ float ssum[8], ssq[8];
    __shared__ float s_mu, s_inv;
    int warp = tid >> 5, lane = tid & 31;
    if (lane == 0) { ssum[warp] = sum; ssq[warp] = sq; }
    __syncthreads();
    if (tid == 0) {
        float ts = 0.0f, tq = 0.0f;
        #pragma unroll
        for (int i = 0; i < 8; i++) { ts += ssum[i]; tq += ssq[i]; }
        float mu  = ts / (float)Cc;
        float var = tq / (float)Cc - mu * mu;
        s_mu  = mu;
        s_inv = rsqrtf(var + 1e-5f);
    }
    __syncthreads();
    float mu = s_mu, inv = s_inv;

    const float4 w0 = reinterpret_cast<const float4*>(lw)[tid];
    const float4 w1 = reinterpret_cast<const float4*>(lw)[tid + 256];
    const float4 b0 = reinterpret_cast<const float4*>(lb)[tid];
    const float4 b1 = reinterpret_cast<const float4*>(lb)[tid + 256];

    float4 o0, o1;
    o0.x = (v0.x - mu) * inv * w0.x + b0.x;
    o0.y = (v0.y - mu) * inv * w0.y + b0.y;
    o0.z = (v0.z - mu) * inv * w0.z + b0.z;
    o0.w = (v0.w - mu) * inv * w0.w + b0.w;
    o1.x = (v1.x - mu) * inv * w1.x + b1.x;
    o1.y = (v1.y - mu) * inv * w1.y + b1.y;
    o1.z = (v1.z - mu) * inv * w1.z + b1.z;
    o1.w = (v1.w - mu) * inv * w1.w + b1.w;
    orow[tid]       = o0;
    orow[tid + 256] = o1;
}

// ---------------- host orchestration ---------------------------------------
extern "C" void kernel_launch(void* const* d_in, const int* in_sizes, int n_in,
                              void* d_out, int out_size) {
    (void)in_sizes; (void)n_in; (void)out_size;
    const float* x      = (const float*)d_in[0];
    const float* Wq     = (const float*)d_in[1];
    const float* Wk     = (const float*)d_in[2];
    const float* Wv     = (const float*)d_in[3];
    const float* Wo     = (const float*)d_in[4];
    const float* conv_w = (const float*)d_in[5];
    const float* conv_b = (const float*)d_in[6];
    const float* gate_w = (const float*)d_in[7];
    const float* gate_b = (const float*)d_in[8];
    const float* ln_w   = (const float*)d_in[9];
    const float* ln_b   = (const float*)d_in[10];
    const float* gamma  = (const float*)d_in[11];

    float *p_xconv, *p_q, *p_k, *p_v, *p_gate, *p_att, *p_y;
    float *p_xt, *p_Wqt, *p_Wkt, *p_Wvt, *p_Wot, *p_Wgt;
    cudaGetSymbolAddress((void**)&p_xconv, g_xconv);
    cudaGetSymbolAddress((void**)&p_q, g_q);
    cudaGetSymbolAddress((void**)&p_k, g_k);
    cudaGetSymbolAddress((void**)&p_v, g_v);
    cudaGetSymbolAddress((void**)&p_gate, g_gate);
    cudaGetSymbolAddress((void**)&p_att, g_att);
    cudaGetSymbolAddress((void**)&p_y, g_y);
    cudaGetSymbolAddress((void**)&p_xt, g_xt);
    cudaGetSymbolAddress((void**)&p_Wqt, g_Wqt);
    cudaGetSymbolAddress((void**)&p_Wkt, g_Wkt);
    cudaGetSymbolAddress((void**)&p_Wvt, g_Wvt);
    cudaGetSymbolAddress((void**)&p_Wot, g_Wot);
    cudaGetSymbolAddress((void**)&p_Wgt, g_Wgt);

    // 0) pre-round the 5 weight matrices to tf32 in one launch
    const int wBlocks = (Cc * Cc) / 1024;  // 4096 per weight
    cvt5_tf32_kernel<<<5 * wBlocks, 256>>>(Wq, p_Wqt, Wk, p_Wkt, Wv, p_Wvt,
                                           Wo, p_Wot, gate_w, p_Wgt);

    // 1) depthwise conv + SiLU (float4); also emits tf32-rounded x (g_xt)
    conv_silu_kernel<<<(Mrows * Cc / 4) / 256, 256>>>(x, conv_w, conv_b);

    // 2) projections (TF32 tensor cores, cp.async pipelined)
    //    mode: 0 plain, 1 sigmoid+bias, 2 fused per-head l2norm
    dim3 ggrid(Cc / 128, Mrows / 128);   // (16, 128)
    gemm_tf32_pipe<<<ggrid, 256>>>(p_xt,    p_Wqt, p_q,    Mrows, Cc, Cc, nullptr, 2);
    gemm_tf32_pipe<<<ggrid, 256>>>(p_xt,    p_Wkt, p_k,    Mrows, Cc, Cc, nullptr, 2);
    gemm_tf32_pipe<<<ggrid, 256>>>(p_xt,    p_Wvt, p_v,    Mrows, Cc, Cc, nullptr, 0);
    gemm_tf32_pipe<<<ggrid, 256>>>(p_xconv, p_Wgt, p_gate, Mrows, Cc, Cc, gate_b, 1);

    // 3) decayed scan (chunked, exact); q/k already l2-normalized in epilogue
    scan_pass1<<<Bb * Hh * NCHUNK, DhD>>>(p_k, p_v, gamma);
    scan_pass2<<<(Bb * Hh * DhD + 127) / 128, 128>>>(gamma);
    scan_pass3<<<Bb * Hh * NCHUNK, DhD>>>(p_k, p_v, p_q, p_gate, gamma);

    // 4) output projection + LayerNorm
    gemm_tf32_pipe<<<ggrid, 256>>>(p_att, p_Wot, p_y, Mrows, Cc, Cc, nullptr, 0);
    ln_kernel<<<Mrows, 256>>>(p_y, ln_w, ln_b, (float*)d_out);
}

// round 9
// speedup vs baseline: 1.9052x; 1.0578x over previous
#include <cuda_runtime.h>
#include <cstdint>
#include <cstdio>

// Problem constants
namespace {
constexpr int Bb = 4, Tt = 4096, Cc = 2048, Hh = 16, DhD = 128;
constexpr int Mrows = Bb * Tt;            // 16384
constexpr int NCHUNK = 64;                // scan chunks
constexpr int LCH = Tt / NCHUNK;          // 64 steps per chunk
}

// ---------------- scratch (static device globals; no allocation allowed) ---
__device__ float g_xconv[(size_t)Bb * Tt * Cc];
__device__ float g_q   [(size_t)Bb * Tt * Cc];
__device__ float g_k   [(size_t)Bb * Tt * Cc];
__device__ float g_v   [(size_t)Bb * Tt * Cc];
__device__ float g_gate[(size_t)Bb * Tt * Cc];
__device__ float g_att [(size_t)Bb * Tt * Cc];
__device__ float g_y   [(size_t)Bb * Tt * Cc];
__device__ float g_xt  [(size_t)Bb * Tt * Cc];      // tf32-rounded x
__device__ float g_Wqt [(size_t)Cc * Cc];
__device__ float g_Wkt [(size_t)Cc * Cc];
__device__ float g_Wvt [(size_t)Cc * Cc];
__device__ float g_Wot [(size_t)Cc * Cc];
__device__ float g_Wgt [(size_t)Cc * Cc];
__device__ float g_F    [(size_t)Bb * Hh * NCHUNK * DhD];
__device__ float g_carry[(size_t)Bb * Hh * NCHUNK * DhD];

// ---------------- helpers --------------------------------------------------
__device__ __forceinline__ uint32_t f2tf32(float f) {
    uint32_t u;
    asm("cvt.rna.tf32.f32 %0, %1;" : "=r"(u) : "f"(f));
    return u;
}

__device__ __forceinline__ float tf32r(float f) { return __uint_as_float(f2tf32(f)); }

__device__ __forceinline__ void mma_tf32(float& d0, float& d1, float& d2, float& d3,
                                         uint32_t a0, uint32_t a1, uint32_t a2, uint32_t a3,
                                         uint32_t b0, uint32_t b1) {
    asm volatile(
        "mma.sync.aligned.m16n8k8.row.col.f32.tf32.tf32.f32 "
        "{%0,%1,%2,%3}, {%4,%5,%6,%7}, {%8,%9}, {%0,%1,%2,%3};\n"
        : "+f"(d0), "+f"(d1), "+f"(d2), "+f"(d3)
        : "r"(a0), "r"(a1), "r"(a2), "r"(a3), "r"(b0), "r"(b1));
}

// ---------------- 0) tf32 pre-round for the 5 weight matrices (one launch) --
__global__ void cvt5_tf32_kernel(const float* __restrict__ w0, float* __restrict__ o0,
                                 const float* __restrict__ w1, float* __restrict__ o1,
                                 const float* __restrict__ w2, float* __restrict__ o2,
                                 const float* __restrict__ w3, float* __restrict__ o3,
                                 const float* __restrict__ w4, float* __restrict__ o4) {
    const int seg = blockIdx.x >> 12;
    const int i   = (blockIdx.x & 4095) * 256 + threadIdx.x;
    const float* in;
    float* out;
    switch (seg) {
        case 0: in = w0; out = o0; break;
        case 1: in = w1; out = o1; break;
        case 2: in = w2; out = o2; break;
        case 3: in = w3; out = o3; break;
        default: in = w4; out = o4; break;
    }
    float4 v = reinterpret_cast<const float4*>(in)[i];
    v.x = tf32r(v.x); v.y = tf32r(v.y); v.z = tf32r(v.z); v.w = tf32r(v.w);
    reinterpret_cast<float4*>(out)[i] = v;
}

// ---------------- 1) causal depthwise conv (K=4) + SiLU + x tf32 side-out ---
__global__ void conv_silu_kernel(const float* __restrict__ x,
                                 const float* __restrict__ w,
                                 const float* __restrict__ bias) {
    int vid = blockIdx.x * blockDim.x + threadIdx.x;    // over B*T*C/4
    int cq  = vid & (Cc / 4 - 1);                       // channel quad
    int bt  = vid >> 9;                                 // /(2048/4)
    int t   = bt & (Tt - 1);
    int c   = cq * 4;

    const float4* x4 = reinterpret_cast<const float4*>(x);
    int base = (bt - t) * (Cc / 4) + cq;                // b*T*C/4 + cq

    float4 wr0 = reinterpret_cast<const float4*>(w)[c + 0];
    float4 wr1 = reinterpret_cast<const float4*>(w)[c + 1];
    float4 wr2 = reinterpret_cast<const float4*>(w)[c + 2];
    float4 wr3 = reinterpret_cast<const float4*>(w)[c + 3];
    float4 bb  = reinterpret_cast<const float4*>(bias)[cq];

    float4 a = bb;
    float4 xt3;
    #pragma unroll
    for (int j = 0; j < 4; j++) {
        int tt = t - 3 + j;
        if (tt >= 0) {
            float4 xv = x4[base + tt * (Cc / 4)];
            if (j == 3) xt3 = xv;
            float wj0 = (&wr0.x)[j], wj1 = (&wr1.x)[j], wj2 = (&wr2.x)[j], wj3 = (&wr3.x)[j];
            a.x = fmaf(xv.x, wj0, a.x);
            a.y = fmaf(xv.y, wj1, a.y);
            a.z = fmaf(xv.z, wj2, a.z);
            a.w = fmaf(xv.w, wj3, a.w);
        }
    }

    float4 s;
    s.x = tf32r(a.x / (1.0f + expf(-a.x)));
    s.y = tf32r(a.y / (1.0f + expf(-a.y)));
    s.z = tf32r(a.z / (1.0f + expf(-a.z)));
    s.w = tf32r(a.w / (1.0f + expf(-a.w)));
    reinterpret_cast<float4*>(g_xconv)[vid] = s;

    float4 xr;
    xr.x = tf32r(xt3.x); xr.y = tf32r(xt3.y); xr.z = tf32r(xt3.z); xr.w = tf32r(xt3.w);
    reinterpret_cast<float4*>(g_xt)[vid] = xr;
}

// ---------------- 2) TF32 GEMM tile body (EXACT round-2 mainloop) -----------
// Computes one 128x128 tile of Out = A[M,2048] * W[128-col slab]^T.
// mode 0: plain.  mode 1: sigmoid(out + bias[col]).  mode 2: per-row l2norm
// over the 128-col tile (tile == one head since BN=128).
__device__ __forceinline__
void gemm_tile_body(const float* __restrict__ A, const float* __restrict__ W,
                    float* __restrict__ Out, const float* __restrict__ bias,
                    int mode, int bm, int bn) {
    constexpr int BM = 128, BKk = 16, ST = 3;
    constexpr int K = Cc, N = Cc;
    __shared__ uint32_t As[ST][BM * BKk];
    __shared__ uint32_t Bs[ST][BM * BKk];
    __shared__ float red[128 * 4];

    const int tid  = threadIdx.x;
    const int warp = tid >> 5, lane = tid & 31;
    const int gid  = lane >> 2, tg = lane & 3;
    const int wm   = warp & 1;       // 0..1  -> 64-row slab
    const int wn   = warp >> 1;      // 0..3  -> 32-col slab

    const int lr = tid >> 2;         // 0..63  (loader row)
    const int lc = tid & 3;          // chunk 0..3

    uint32_t sA = (uint32_t)__cvta_generic_to_shared(&As[0][0]);
    uint32_t sB = (uint32_t)__cvta_generic_to_shared(&Bs[0][0]);

    auto issue = [&](int s, int k0) {
        #pragma unroll
        for (int r = 0; r < 2; r++) {
            int row = lr + r * 64;
            int sw  = (row >> 1) & 3;
            uint32_t off = (uint32_t)(s * BM * BKk + row * 16 + ((lc ^ sw) << 2)) * 4u;
            const float* gA = A + (size_t)(bm + row) * K + k0 + lc * 4;
            asm volatile("cp.async.cg.shared.global [%0], [%1], 16;\n"
                         :: "r"(sA + off), "l"(gA));
            const float* gB = W + (size_t)(bn + row) * K + k0 + lc * 4;
            asm volatile("cp.async.cg.shared.global [%0], [%1], 16;\n"
                         :: "r"(sB + off), "l"(gB));
        }
        asm volatile("cp.async.commit_group;\n");
    };

    float acc[4][4][4] = {};

    issue(0, 0);
    issue(1, BKk);

    int s = 0;
    for (int k0 = 0; k0 < K; k0 += BKk) {
        asm volatile("cp.async.wait_group 1;\n" ::: "memory");
        __syncthreads();

        int kn = k0 + 2 * BKk;
        if (kn < K) {
            int s2 = s + 2; if (s2 >= ST) s2 -= ST;
            issue(s2, kn);
        }

        const uint32_t* Ab = &As[s][0];
        const uint32_t* Bb = &Bs[s][0];
        #pragma unroll
        for (int kk = 0; kk < BKk; kk += 8) {
            const int c0 = kk >> 2;
            uint32_t af[4][4], bf[4][2];
            #pragma unroll
            for (int mt = 0; mt < 4; mt++) {
                int row = wm * 64 + mt * 16 + gid;
                int sw  = (row >> 1) & 3;
                int b0i = row * 16 + tg;
                int b1i = (row + 8) * 16 + tg;
                af[mt][0] = Ab[b0i + ((c0 ^ sw) << 2)];
                af[mt][1] = Ab[b1i + ((c0 ^ sw) << 2)];
                af[mt][2] = Ab[b0i + (((c0 + 1) ^ sw) << 2)];
                af[mt][3] = Ab[b1i + (((c0 + 1) ^ sw) << 2)];
            }
            #pragma unroll
            for (int nt = 0; nt < 4; nt++) {
                int col = wn * 32 + nt * 8 + gid;
                int sw  = (col >> 1) & 3;
                int bi  = col * 16 + tg;
                bf[nt][0] = Bb[bi + ((c0 ^ sw) << 2)];
                bf[nt][1] = Bb[bi + (((c0 + 1) ^ sw) << 2)];
            }
            #pragma unroll
            for (int mt = 0; mt < 4; mt++)
                #pragma unroll
                for (int nt = 0; nt < 4; nt++)
                    mma_tf32(acc[mt][nt][0], acc[mt][nt][1], acc[mt][nt][2], acc[mt][nt][3],
                             af[mt][0], af[mt][1], af[mt][2], af[mt][3],
                             bf[nt][0], bf[nt][1]);
        }
        s++; if (s >= ST) s = 0;
    }

    // ---- fused l2norm over the 128-col tile (mode 2, tile == one head) -----
    if (mode == 2) {
        __syncthreads();
        float invLo[4], invHi[4];
        #pragma unroll
        for (int mt = 0; mt < 4; mt++) {
            float slo = 0.0f, shi = 0.0f;
            #pragma unroll
            for (int nt = 0; nt < 4; nt++) {
                slo = fmaf(acc[mt][nt][0], acc[mt][nt][0], slo);
                slo = fmaf(acc[mt][nt][1], acc[mt][nt][1], slo);
                shi = fmaf(acc[mt][nt][2], acc[mt][nt][2], shi);
                shi = fmaf(acc[mt][nt][3], acc[mt][nt][3], shi);
            }
            slo += __shfl_xor_sync(0xffffffffu, slo, 1);
            slo += __shfl_xor_sync(0xffffffffu, slo, 2);
            shi += __shfl_xor_sync(0xffffffffu, shi, 1);
            shi += __shfl_xor_sync(0xffffffffu, shi, 2);
            if (tg == 0) {
                int r = wm * 64 + mt * 16 + gid;
                red[r * 4 + wn]       = slo;
                red[(r + 8) * 4 + wn] = shi;
            }
        }
        __syncthreads();
        #pragma unroll
        for (int mt = 0; mt < 4; mt++) {
            int r = wm * 64 + mt * 16 + gid;
            float slo = red[r * 4 + 0] + red[r * 4 + 1] + red[r * 4 + 2] + red[r * 4 + 3];
            float shi = red[(r + 8) * 4 + 0] + red[(r + 8) * 4 + 1]
                      + red[(r + 8) * 4 + 2] + red[(r + 8) * 4 + 3];
            invLo[mt] = 1.0f / fmaxf(sqrtf(slo), 1e-12f);
            invHi[mt] = 1.0f / fmaxf(sqrtf(shi), 1e-12f);
        }
        #pragma unroll
        for (int mt = 0; mt < 4; mt++)
            #pragma unroll
            for (int nt = 0; nt < 4; nt++) {
                acc[mt][nt][0] *= invLo[mt];
                acc[mt][nt][1] *= invLo[mt];
                acc[mt][nt][2] *= invHi[mt];
                acc[mt][nt][3] *= invHi[mt];
            }
    }

    // epilogue stores
    #pragma unroll
    for (int mt = 0; mt < 4; mt++) {
        #pragma unroll
        for (int nt = 0; nt < 4; nt++) {
            int row = bm + wm * 64 + mt * 16 + gid;
            int col = bn + wn * 32 + nt * 8 + tg * 2;
            float v0 = acc[mt][nt][0], v1 = acc[mt][nt][1];
            float v2 = acc[mt][nt][2], v3 = acc[mt][nt][3];
            if (mode == 1) {
                float b0 = bias[col], b1 = bias[col + 1];
                v0 = 1.0f / (1.0f + expf(-(v0 + b0)));
                v1 = 1.0f / (1.0f + expf(-(v1 + b1)));
                v2 = 1.0f / (1.0f + expf(-(v2 + b0)));
                v3 = 1.0f / (1.0f + expf(-(v3 + b1)));
            }
            *reinterpret_cast<float2*>(&Out[(size_t)row * N + col])       = make_float2(v0, v1);
            *reinterpret_cast<float2*>(&Out[(size_t)(row + 8) * N + col]) = make_float2(v2, v3);
        }
    }
}

// Combined q/k/v/gate projection: one launch, 64 column-tiles x 128 row-tiles.
// seg = blockIdx.x>>4: 0=q(mode2) 1=k(mode2) 2=v(mode0) 3=gate(mode1, A=xconv)
__global__ __launch_bounds__(256)
void gemm_qkvg_kernel(const float* __restrict__ gate_b) {
    const int seg = blockIdx.x >> 4;
    const int bn  = (blockIdx.x & 15) * 128;
    const int bm  = blockIdx.y * 128;

    const float* A;
    const float* W;
    float* Out;
    int mode;
    switch (seg) {
        case 0:  A = g_xt;    W = g_Wqt; Out = g_q;    mode = 2; break;
        case 1:  A = g_xt;    W = g_Wkt; Out = g_k;    mode = 2; break;
        case 2:  A = g_xt;    W = g_Wvt; Out = g_v;    mode = 0; break;
        default: A = g_xconv; W = g_Wgt; Out = g_gate; mode = 1; break;
    }
    gemm_tile_body(A, W, Out, gate_b, mode, bm, bn);
}

// Output projection: y = att * Wo^T (mode 0)
__global__ __launch_bounds__(256)
void gemm_out_kernel() {
    gemm_tile_body(g_att, g_Wot, g_y, nullptr, 0, blockIdx.y * 128, blockIdx.x * 128);
}

// ---------------- 4) chunked decayed scan ----------------------------------
__global__ void scan_pass1(const float* __restrict__ k, const float* __restrict__ v,
                           const float* __restrict__ gamma) {
    int blk = blockIdx.x;
    int c  = blk % NCHUNK;
    int bh = blk / NCHUNK;
    int h  = bh % Hh;
    int b  = bh / Hh;
    int d  = threadIdx.x;
    float g = gamma[h];
    size_t idx = ((size_t)(b * Tt + c * LCH)) * Cc + h * DhD + d;
    float S = 0.0f;
    #pragma unroll 4
    for (int i = 0; i < LCH; i++) {
        S = fmaf(g, S, k[idx] * v[idx]);
        idx += Cc;
    }
    g_F[((size_t)bh * NCHUNK + c) * DhD + d] = S;
}

__global__ void scan_pass2(const float* __restrict__ gamma) {
    int tid = blockIdx.x * blockDim.x + threadIdx.x;
    if (tid >= Bb * Hh * DhD) return;
    int d  = tid & (DhD - 1);
    int bh = tid >> 7;
    int h  = bh % Hh;
    float g  = gamma[h];
    float gL = powf(g, (float)LCH);     // exact 1.0 for gamma=1 head
    float carry = 0.0f;
    for (int c = 0; c < NCHUNK; c++) {
        size_t o = ((size_t)bh * NCHUNK + c) * DhD + d;
        g_carry[o] = carry;
        carry = fmaf(gL, carry, g_F[o]);
    }
}

__global__ void scan_pass3(const float* __restrict__ k, const float* __restrict__ v,
                           const float* __restrict__ q, const float* __restrict__ gate,
                           const float* __restrict__ gamma) {
    int blk = blockIdx.x;
    int c  = blk % NCHUNK;
    int bh = blk / NCHUNK;
    int h  = bh % Hh;
    int b  = bh / Hh;
    int d  = threadIdx.x;
    float g = gamma[h];
    float S = g_carry[((size_t)bh * NCHUNK + c) * DhD + d];
    size_t idx = ((size_t)(b * Tt + c * LCH)) * Cc + h * DhD + d;
    #pragma unroll 4
    for (int i = 0; i < LCH; i++) {
        S = fmaf(g, S, k[idx] * v[idx]);
        g_att[idx] = tf32r(gate[idx] * S * q[idx]);
        idx += Cc;
    }
}

// ---------------- 5) LayerNorm over C=2048 ---------------------------------
__global__ __launch_bounds__(256)
void ln_kernel(const float* __restrict__ y, const float* __restrict__ lw,
               const float* __restrict__ lb, float* __restrict__ out) {
    int row = blockIdx.x;
    int tid = threadIdx.x;
    const float4* yr = reinterpret_cast<const float4*>(y + (size_t)row * Cc);
    float4* orow     = reinterpret_cast<float4*>(out + (size_t)row * Cc);

    float4 v0 = yr[tid];
    float4 v1 = yr[tid + 256];
    float sum = v0.x + v0.y + v0.z + v0.w + v1.x + v1.y + v1.z + v1.w;
    float sq  = v0.x * v0.x + v0.y * v0.y + v0.z * v0.z + v0.w * v0.w
              + v1.x * v1.x + v1.y * v1.y + v1.z * v1.z + v1.w * v1.w;

    #pragma unroll
    for (int o = 16; o; o >>= 1) {
        sum += __shfl_xor_sync(0xffffffffu, sum, o);
        sq  += __shfl_xor_sync(0xffffffffu, sq, o);
    }
    __shared__ float ssum[8], ssq[8];
    __shared__ float s_mu, s_inv;
    int warp = tid >> 5, lane = tid & 31;
    if (lane == 0) { ssum[warp] = sum; ssq[warp] = sq; }
    __syncthreads();
    if (tid == 0) {
        float ts = 0.0f, tq = 0.0f;
        #pragma unroll
        for (int i = 0; i < 8; i++) { ts += ssum[i]; tq += ssq[i]; }
        float mu  = ts / (float)Cc;
        float var = tq / (float)Cc - mu * mu;
        s_mu  = mu;
        s_inv = rsqrtf(var + 1e-5f);
    }
    __syncthreads();
    float mu = s_mu, inv = s_inv;

    const float4 w0 = reinterpret_cast<const float4*>(lw)[tid];
    const float4 w1 = reinterpret_cast<const float4*>(lw)[tid + 256];
    const float4 b0 = reinterpret_cast<const float4*>(lb)[tid];
    const float4 b1 = reinterpret_cast<const float4*>(lb)[tid + 256];

    float4 o0, o1;
    o0.x = (v0.x - mu) * inv * w0.x + b0.x;
    o0.y = (v0.y - mu) * inv * w0.y + b0.y;
    o0.z = (v0.z - mu) * inv * w0.z + b0.z;
    o0.w = (v0.w - mu) * inv * w0.w + b0.w;
    o1.x = (v1.x - mu) * inv * w1.x + b1.x;
    o1.y = (v1.y - mu) * inv * w1.y + b1.y;
    o1.z = (v1.z - mu) * inv * w1.z + b1.z;
    o1.w = (v1.w - mu) * inv * w1.w + b1.w;
    orow[tid]       = o0;
    orow[tid + 256] = o1;
}

// ---------------- host orchestration ---------------------------------------
extern "C" void kernel_launch(void* const* d_in, const int* in_sizes, int n_in,
                              void* d_out, int out_size) {
    (void)in_sizes; (void)n_in; (void)out_size;
    const float* x      = (const float*)d_in[0];
    const float* Wq     = (const float*)d_in[1];
    const float* Wk     = (const float*)d_in[2];
    const float* Wv     = (const float*)d_in[3];
    const float* Wo     = (const float*)d_in[4];
    const float* conv_w = (const float*)d_in[5];
    const float* conv_b = (const float*)d_in[6];
    const float* gate_w = (const float*)d_in[7];
    const float* gate_b = (const float*)d_in[8];
    const float* ln_w   = (const float*)d_in[9];
    const float* ln_b   = (const float*)d_in[10];
    const float* gamma  = (const float*)d_in[11];

    float *p_q, *p_k, *p_v, *p_gate, *p_att, *p_y;
    float *p_Wqt, *p_Wkt, *p_Wvt, *p_Wot, *p_Wgt;
    cudaGetSymbolAddress((void**)&p_q, g_q);
    cudaGetSymbolAddress((void**)&p_k, g_k);
    cudaGetSymbolAddress((void**)&p_v, g_v);
    cudaGetSymbolAddress((void**)&p_gate, g_gate);
    cudaGetSymbolAddress((void**)&p_att, g_att);
    cudaGetSymbolAddress((void**)&p_y, g_y);
    cudaGetSymbolAddress((void**)&p_Wqt, g_Wqt);
    cudaGetSymbolAddress((void**)&p_Wkt, g_Wkt);
    cudaGetSymbolAddress((void**)&p_Wvt, g_Wvt);
    cudaGetSymbolAddress((void**)&p_Wot, g_Wot);
    cudaGetSymbolAddress((void**)&p_Wgt, g_Wgt);

    // 0) pre-round the 5 weight matrices to tf32 in one launch
    const int wBlocks = (Cc * Cc) / 1024;  // 4096 per weight
    cvt5_tf32_kernel<<<5 * wBlocks, 256>>>(Wq, p_Wqt, Wk, p_Wkt, Wv, p_Wvt,
                                           Wo, p_Wot, gate_w, p_Wgt);

    // 1) depthwise conv + SiLU (float4); also emits tf32-rounded x (g_xt)
    conv_silu_kernel<<<(Mrows * Cc / 4) / 256, 256>>>(x, conv_w, conv_b);

    // 2) all four projections in ONE launch (q, k, v, gate)
    dim3 qgrid(64, Mrows / 128);   // 64 col-tiles (4 segs x 16), 128 row-tiles
    gemm_qkvg_kernel<<<qgrid, 256>>>(gate_b);

    // 3) decayed scan (chunked, exact); q/k already l2-normalized in epilogue
    scan_pass1<<<Bb * Hh * NCHUNK, DhD>>>(p_k, p_v, gamma);
    scan_pass2<<<(Bb * Hh * DhD + 127) / 128, 128>>>(gamma);
    scan_pass3<<<Bb * Hh * NCHUNK, DhD>>>(p_k, p_v, p_q, p_gate, gamma);

    // 4) output projection + LayerNorm
    dim3 ogrid(Cc / 128, Mrows / 128);   // (16, 128)
    gemm_out_kernel<<<ogrid, 256>>>();
    ln_kernel<<<Mrows, 256>>>(p_y, ln_w, ln_b, (float*)d_out);
}

// round 10
// speedup vs baseline: 2.0397x; 1.0706x over previous
#include <cuda_runtime.h>
#include <cstdint>
#include <cstdio>

// Problem constants
namespace {
constexpr int Bb = 4, Tt = 4096, Cc = 2048, Hh = 16, DhD = 128;
constexpr int Mrows = Bb * Tt;            // 16384
constexpr int NCHUNK = 64;                // scan chunks
constexpr int LCH = Tt / NCHUNK;          // 64 steps per chunk
}

// ---------------- scratch (static device globals; no allocation allowed) ---
__device__ float g_xconv[(size_t)Bb * Tt * Cc];
__device__ float g_q   [(size_t)Bb * Tt * Cc];
__device__ float g_k   [(size_t)Bb * Tt * Cc];
__device__ float g_v   [(size_t)Bb * Tt * Cc];
__device__ float g_gate[(size_t)Bb * Tt * Cc];
__device__ float g_att [(size_t)Bb * Tt * Cc];
__device__ float g_y   [(size_t)Bb * Tt * Cc];
__device__ float g_xt  [(size_t)Bb * Tt * Cc];      // tf32-rounded x
__device__ float g_Wqt [(size_t)Cc * Cc];
__device__ float g_Wkt [(size_t)Cc * Cc];
__device__ float g_Wvt [(size_t)Cc * Cc];
__device__ float g_Wot [(size_t)Cc * Cc];
__device__ float g_Wgt [(size_t)Cc * Cc];
__device__ float g_F    [(size_t)Bb * Hh * NCHUNK * DhD];
__device__ float g_carry[(size_t)Bb * Hh * NCHUNK * DhD];

// ---------------- helpers --------------------------------------------------
__device__ __forceinline__ uint32_t f2tf32(float f) {
    uint32_t u;
    asm("cvt.rna.tf32.f32 %0, %1;" : "=r"(u) : "f"(f));
    return u;
}

__device__ __forceinline__ float tf32r(float f) { return __uint_as_float(f2tf32(f)); }

__device__ __forceinline__ void mma_tf32(float& d0, float& d1, float& d2, float& d3,
                                         uint32_t a0, uint32_t a1, uint32_t a2, uint32_t a3,
                                         uint32_t b0, uint32_t b1) {
    asm volatile(
        "mma.sync.aligned.m16n8k8.row.col.f32.tf32.tf32.f32 "
        "{%0,%1,%2,%3}, {%4,%5,%6,%7}, {%8,%9}, {%0,%1,%2,%3};\n"
        : "+f"(d0), "+f"(d1), "+f"(d2), "+f"(d3)
        : "r"(a0), "r"(a1), "r"(a2), "r"(a3), "r"(b0), "r"(b1));
}

// ---------------- 0) tf32 pre-round for the 5 weight matrices (one launch) --
__global__ void cvt5_tf32_kernel(const float* __restrict__ w0, float* __restrict__ o0,
                                 const float* __restrict__ w1, float* __restrict__ o1,
                                 const float* __restrict__ w2, float* __restrict__ o2,
                                 const float* __restrict__ w3, float* __restrict__ o3,
                                 const float* __restrict__ w4, float* __restrict__ o4) {
    const int seg = blockIdx.x >> 12;
    const int i   = (blockIdx.x & 4095) * 256 + threadIdx.x;
    const float* in;
    float* out;
    switch (seg) {
        case 0: in = w0; out = o0; break;
        case 1: in = w1; out = o1; break;
        case 2: in = w2; out = o2; break;
        case 3: in = w3; out = o3; break;
        default: in = w4; out = o4; break;
    }
    float4 v = reinterpret_cast<const float4*>(in)[i];
    v.x = tf32r(v.x); v.y = tf32r(v.y); v.z = tf32r(v.z); v.w = tf32r(v.w);
    reinterpret_cast<float4*>(out)[i] = v;
}

// ---------------- 1) causal depthwise conv (K=4) + SiLU + x tf32 side-out ---
__global__ void conv_silu_kernel(const float* __restrict__ x,
                                 const float* __restrict__ w,
                                 const float* __restrict__ bias) {
    int vid = blockIdx.x * blockDim.x + threadIdx.x;    // over B*T*C/4
    int cq  = vid & (Cc / 4 - 1);                       // channel quad
    int bt  = vid >> 9;                                 // /(2048/4)
    int t   = bt & (Tt - 1);
    int c   = cq * 4;

    const float4* x4 = reinterpret_cast<const float4*>(x);
    int base = (bt - t) * (Cc / 4) + cq;                // b*T*C/4 + cq

    float4 wr0 = reinterpret_cast<const float4*>(w)[c + 0];
    float4 wr1 = reinterpret_cast<const float4*>(w)[c + 1];
    float4 wr2 = reinterpret_cast<const float4*>(w)[c + 2];
    float4 wr3 = reinterpret_cast<const float4*>(w)[c + 3];
    float4 bb  = reinterpret_cast<const float4*>(bias)[cq];

    float4 a = bb;
    float4 xt3;
    #pragma unroll
    for (int j = 0; j < 4; j++) {
        int tt = t - 3 + j;
        if (tt >= 0) {
            float4 xv = x4[base + tt * (Cc / 4)];
            if (j == 3) xt3 = xv;
            float wj0 = (&wr0.x)[j], wj1 = (&wr1.x)[j], wj2 = (&wr2.x)[j], wj3 = (&wr3.x)[j];
            a.x = fmaf(xv.x, wj0, a.x);
            a.y = fmaf(xv.y, wj1, a.y);
            a.z = fmaf(xv.z, wj2, a.z);
            a.w = fmaf(xv.w, wj3, a.w);
        }
    }

    float4 s;
    s.x = tf32r(a.x / (1.0f + expf(-a.x)));
    s.y = tf32r(a.y / (1.0f + expf(-a.y)));
    s.z = tf32r(a.z / (1.0f + expf(-a.z)));
    s.w = tf32r(a.w / (1.0f + expf(-a.w)));
    reinterpret_cast<float4*>(g_xconv)[vid] = s;

    float4 xr;
    xr.x = tf32r(xt3.x); xr.y = tf32r(xt3.y); xr.z = tf32r(xt3.z); xr.w = tf32r(xt3.w);
    reinterpret_cast<float4*>(g_xt)[vid] = xr;
}

// ---------------- 2) TF32 GEMM tile body (round-2 mainloop + fragment hoist)
// Computes one 128x128 tile of Out = A[M,2048] * W[128-col slab]^T.
// mode 0: plain.  mode 1: sigmoid(out + bias[col]).  mode 2: per-row l2norm
// over the 128-col tile (tile == one head since BN=128).
__device__ __forceinline__
void gemm_tile_body(const float* __restrict__ A, const float* __restrict__ W,
                    float* __restrict__ Out, const float* __restrict__ bias,
                    int mode, int bm, int bn) {
    constexpr int BM = 128, BKk = 16, ST = 3;
    constexpr int K = Cc, N = Cc;
    __shared__ uint32_t As[ST][BM * BKk];
    __shared__ uint32_t Bs[ST][BM * BKk];
    __shared__ float red[128 * 4];

    const int tid  = threadIdx.x;
    const int warp = tid >> 5, lane = tid & 31;
    const int gid  = lane >> 2, tg = lane & 3;
    const int wm   = warp & 1;       // 0..1  -> 64-row slab
    const int wn   = warp >> 1;      // 0..3  -> 32-col slab

    const int lr = tid >> 2;         // 0..63  (loader row)
    const int lc = tid & 3;          // chunk 0..3

    uint32_t sA = (uint32_t)__cvta_generic_to_shared(&As[0][0]);
    uint32_t sB = (uint32_t)__cvta_generic_to_shared(&Bs[0][0]);

    auto issue = [&](int s, int k0) {
        #pragma unroll
        for (int r = 0; r < 2; r++) {
            int row = lr + r * 64;
            int sw  = (row >> 1) & 3;
            uint32_t off = (uint32_t)(s * BM * BKk + row * 16 + ((lc ^ sw) << 2)) * 4u;
            const float* gA = A + (size_t)(bm + row) * K + k0 + lc * 4;
            asm volatile("cp.async.cg.shared.global [%0], [%1], 16;\n"
                         :: "r"(sA + off), "l"(gA));
            const float* gB = W + (size_t)(bn + row) * K + k0 + lc * 4;
            asm volatile("cp.async.cg.shared.global [%0], [%1], 16;\n"
                         :: "r"(sB + off), "l"(gB));
        }
        asm volatile("cp.async.commit_group;\n");
    };

    float acc[4][4][4] = {};

    issue(0, 0);
    issue(1, BKk);

    int s = 0;
    for (int k0 = 0; k0 < K; k0 += BKk) {
        asm volatile("cp.async.wait_group 1;\n" ::: "memory");
        __syncthreads();

        int kn = k0 + 2 * BKk;
        if (kn < K) {
            int s2 = s + 2; if (s2 >= ST) s2 -= ST;
            issue(s2, kn);
        }

        const uint32_t* Ab = &As[s][0];
        const uint32_t* Bb = &Bs[s][0];

        // Fragment hoist: load ALL fragments for the stage, then all MMAs.
        uint32_t af[2][4][4], bf[2][4][2];
        #pragma unroll
        for (int half = 0; half < 2; half++) {
            const int c0 = half * 2;
            #pragma unroll
            for (int mt = 0; mt < 4; mt++) {
                int row = wm * 64 + mt * 16 + gid;
                int sw  = (row >> 1) & 3;
                int b0i = row * 16 + tg;
                int b1i = (row + 8) * 16 + tg;
                af[half][mt][0] = Ab[b0i + ((c0 ^ sw) << 2)];
                af[half][mt][1] = Ab[b1i + ((c0 ^ sw) << 2)];
                af[half][mt][2] = Ab[b0i + (((c0 + 1) ^ sw) << 2)];
                af[half][mt][3] = Ab[b1i + (((c0 + 1) ^ sw) << 2)];
            }
            #pragma unroll
            for (int nt = 0; nt < 4; nt++) {
                int col = wn * 32 + nt * 8 + gid;
                int sw  = (col >> 1) & 3;
                int bi  = col * 16 + tg;
                bf[half][nt][0] = Bb[bi + ((c0 ^ sw) << 2)];
                bf[half][nt][1] = Bb[bi + (((c0 + 1) ^ sw) << 2)];
            }
        }
        #pragma unroll
        for (int half = 0; half < 2; half++)
            #pragma unroll
            for (int mt = 0; mt < 4; mt++)
                #pragma unroll
                for (int nt = 0; nt < 4; nt++)
                    mma_tf32(acc[mt][nt][0], acc[mt][nt][1], acc[mt][nt][2], acc[mt][nt][3],
                             af[half][mt][0], af[half][mt][1], af[half][mt][2], af[half][mt][3],
                             bf[half][nt][0], bf[half][nt][1]);
        s++; if (s >= ST) s = 0;
    }

    // ---- fused l2norm over the 128-col tile (mode 2, tile == one head) -----
    if (mode == 2) {
        __syncthreads();
        float invLo[4], invHi[4];
        #pragma unroll
        for (int mt = 0; mt < 4; mt++) {
            float slo = 0.0f, shi = 0.0f;
            #pragma unroll
            for (int nt = 0; nt < 4; nt++) {
                slo = fmaf(acc[mt][nt][0], acc[mt][nt][0], slo);
                slo = fmaf(acc[mt][nt][1], acc[mt][nt][1], slo);
                shi = fmaf(acc[mt][nt][2], acc[mt][nt][2], shi);
                shi = fmaf(acc[mt][nt][3], acc[mt][nt][3], shi);
            }
            slo += __shfl_xor_sync(0xffffffffu, slo, 1);
            slo += __shfl_xor_sync(0xffffffffu, slo, 2);
            shi += __shfl_xor_sync(0xffffffffu, shi, 1);
            shi += __shfl_xor_sync(0xffffffffu, shi, 2);
            if (tg == 0) {
                int r = wm * 64 + mt * 16 + gid;
                red[r * 4 + wn]       = slo;
                red[(r + 8) * 4 + wn] = shi;
            }
        }
        __syncthreads();
        #pragma unroll
        for (int mt = 0; mt < 4; mt++) {
            int r = wm * 64 + mt * 16 + gid;
            float slo = red[r * 4 + 0] + red[r * 4 + 1] + red[r * 4 + 2] + red[r * 4 + 3];
            float shi = red[(r + 8) * 4 + 0] + red[(r + 8) * 4 + 1]
                      + red[(r + 8) * 4 + 2] + red[(r + 8) * 4 + 3];
            invLo[mt] = 1.0f / fmaxf(sqrtf(slo), 1e-12f);
            invHi[mt] = 1.0f / fmaxf(sqrtf(shi), 1e-12f);
        }
        #pragma unroll
        for (int mt = 0; mt < 4; mt++)
            #pragma unroll
            for (int nt = 0; nt < 4; nt++) {
                acc[mt][nt][0] *= invLo[mt];
                acc[mt][nt][1] *= invLo[mt];
                acc[mt][nt][2] *= invHi[mt];
                acc[mt][nt][3] *= invHi[mt];
            }
    }

    // epilogue stores
    #pragma unroll
    for (int mt = 0; mt < 4; mt++) {
        #pragma unroll
        for (int nt = 0; nt < 4; nt++) {
            int row = bm + wm * 64 + mt * 16 + gid;
            int col = bn + wn * 32 + nt * 8 + tg * 2;
            float v0 = acc[mt][nt][0], v1 = acc[mt][nt][1];
            float v2 = acc[mt][nt][2], v3 = acc[mt][nt][3];
            if (mode == 1) {
                float b0 = bias[col], b1 = bias[col + 1];
                v0 = 1.0f / (1.0f + expf(-(v0 + b0)));
                v1 = 1.0f / (1.0f + expf(-(v1 + b1)));
                v2 = 1.0f / (1.0f + expf(-(v2 + b0)));
                v3 = 1.0f / (1.0f + expf(-(v3 + b1)));
            }
            *reinterpret_cast<float2*>(&Out[(size_t)row * N + col])       = make_float2(v0, v1);
            *reinterpret_cast<float2*>(&Out[(size_t)(row + 8) * N + col]) = make_float2(v2, v3);
        }
    }
}

// Combined q/k/v/gate projection: one launch, 64 column-tiles x 128 row-tiles.
// seg = blockIdx.x>>4: 0=q(mode2) 1=k(mode2) 2=v(mode0) 3=gate(mode1, A=xconv)
__global__ __launch_bounds__(256, 2)
void gemm_qkvg_kernel(const float* __restrict__ gate_b) {
    const int seg = blockIdx.x >> 4;
    const int bn  = (blockIdx.x & 15) * 128;
    const int bm  = blockIdx.y * 128;

    const float* A;
    const float* W;
    float* Out;
    int mode;
    switch (seg) {
        case 0:  A = g_xt;    W = g_Wqt; Out = g_q;    mode = 2; break;
        case 1:  A = g_xt;    W = g_Wkt; Out = g_k;    mode = 2; break;
        case 2:  A = g_xt;    W = g_Wvt; Out = g_v;    mode = 0; break;
        default: A = g_xconv; W = g_Wgt; Out = g_gate; mode = 1; break;
    }
    gemm_tile_body(A, W, Out, gate_b, mode, bm, bn);
}

// Output projection: y = att * Wo^T (mode 0)
__global__ __launch_bounds__(256, 2)
void gemm_out_kernel() {
    gemm_tile_body(g_att, g_Wot, g_y, nullptr, 0, blockIdx.y * 128, blockIdx.x * 128);
}

// ---------------- 4) chunked decayed scan (float4, warp-per-chunk) ----------
__global__ void scan_pass1(const float* __restrict__ k, const float* __restrict__ v,
                           const float* __restrict__ gamma) {
    int wid  = threadIdx.x >> 5, lane = threadIdx.x & 31;
    int blk  = blockIdx.x * 4 + wid;          // 0..4095
    int c    = blk & (NCHUNK - 1);
    int bh   = blk >> 6;
    int h    = bh & (Hh - 1);
    int b    = bh >> 4;
    float g  = gamma[h];
    const float4* k4 = reinterpret_cast<const float4*>(k);
    const float4* v4 = reinterpret_cast<const float4*>(v);
    size_t idx = ((size_t)(b * Tt + c * LCH) * Cc + h * DhD) / 4 + lane;
    float4 S = make_float4(0.f, 0.f, 0.f, 0.f);
    #pragma unroll 4
    for (int i = 0; i < LCH; i++) {
        float4 kk = k4[idx], vv = v4[idx];
        S.x = fmaf(g, S.x, kk.x * vv.x);
        S.y = fmaf(g, S.y, kk.y * vv.y);
        S.z = fmaf(g, S.z, kk.z * vv.z);
        S.w = fmaf(g, S.w, kk.w * vv.w);
        idx += Cc / 4;
    }
    reinterpret_cast<float4*>(g_F)[((size_t)bh * NCHUNK + c) * (DhD / 4) + lane] = S;
}

__global__ void scan_pass2(const float* __restrict__ gamma) {
    int tid = blockIdx.x * blockDim.x + threadIdx.x;   // over Bb*Hh*DhD/4 = 2048
    int d4  = tid & (DhD / 4 - 1);
    int bh  = tid >> 5;
    int h   = bh & (Hh - 1);
    float g  = gamma[h];
    float gL = powf(g, (float)LCH);     // exact 1.0 for gamma=1 head
    const float4* F4 = reinterpret_cast<const float4*>(g_F);
    float4* C4       = reinterpret_cast<float4*>(g_carry);
    float4 carry = make_float4(0.f, 0.f, 0.f, 0.f);
    for (int c = 0; c < NCHUNK; c++) {
        size_t o = ((size_t)bh * NCHUNK + c) * (DhD / 4) + d4;
        C4[o] = carry;
        float4 f = F4[o];
        carry.x = fmaf(gL, carry.x, f.x);
        carry.y = fmaf(gL, carry.y, f.y);
        carry.z = fmaf(gL, carry.z, f.z);
        carry.w = fmaf(gL, carry.w, f.w);
    }
}

__global__ void scan_pass3(const float* __restrict__ k, const float* __restrict__ v,
                           const float* __restrict__ q, const float* __restrict__ gate,
                           const float* __restrict__ gamma) {
    int wid  = threadIdx.x >> 5, lane = threadIdx.x & 31;
    int blk  = blockIdx.x * 4 + wid;
    int c    = blk & (NCHUNK - 1);
    int bh   = blk >> 6;
    int h    = bh & (Hh - 1);
    int b    = bh >> 4;
    float g  = gamma[h];
    const float4* k4 = reinterpret_cast<const float4*>(k);
    const float4* v4 = reinterpret_cast<const float4*>(v);
    const float4* q4 = reinterpret_cast<const float4*>(q);
    const float4* g4 = reinterpret_cast<const float4*>(gate);
    float4* a4       = reinterpret_cast<float4*>(g_att);
    float4 S = reinterpret_cast<const float4*>(g_carry)
                   [((size_t)bh * NCHUNK + c) * (DhD / 4) + lane];
    size_t idx = ((size_t)(b * Tt + c * LCH) * Cc + h * DhD) / 4 + lane;
    #pragma unroll 4
    for (int i = 0; i < LCH; i++) {
        float4 kk = k4[idx], vv = v4[idx];
        S.x = fmaf(g, S.x, kk.x * vv.x);
        S.y = fmaf(g, S.y, kk.y * vv.y);
        S.z = fmaf(g, S.z, kk.z * vv.z);
        S.w = fmaf(g, S.w, kk.w * vv.w);
        float4 gg = g4[idx], qq = q4[idx];
        float4 o;
        o.x = tf32r(gg.x * S.x * qq.x);
        o.y = tf32r(gg.y * S.y * qq.y);
        o.z = tf32r(gg.z * S.z * qq.z);
        o.w = tf32r(gg.w * S.w * qq.w);
        a4[idx] = o;
        idx += Cc / 4;
    }
}

// ---------------- 5) LayerNorm over C=2048 ---------------------------------
__global__ __launch_bounds__(256)
void ln_kernel(const float* __restrict__ y, const float* __restrict__ lw,
               const float* __restrict__ lb, float* __restrict__ out) {
    int row = blockIdx.x;
    int tid = threadIdx.x;
    const float4* yr = reinterpret_cast<const float4*>(y + (size_t)row * Cc);
    float4* orow     = reinterpret_cast<float4*>(out + (size_t)row * Cc);

    float4 v0 = yr[tid];
    float4 v1 = yr[tid + 256];
    float sum = v0.x + v0.y + v0.z + v0.w + v1.x + v1.y + v1.z + v1.w;
    float sq  = v0.x * v0.x + v0.y * v0.y + v0.z * v0.z + v0.w * v0.w
              + v1.x * v1.x + v1.y * v1.y + v1.z * v1.z + v1.w * v1.w;

    #pragma unroll
    for (int o = 16; o; o >>= 1) {
        sum += __shfl_xor_sync(0xffffffffu, sum, o);
        sq  += __shfl_xor_sync(0xffffffffu, sq, o);
    }
    __shared__ float ssum[8], ssq[8];
    __shared__ float s_mu, s_inv;
    int warp = tid >> 5, lane = tid & 31;
    if (lane == 0) { ssum[warp] = sum; ssq[warp] = sq; }
    __syncthreads();
    if (tid == 0) {
        float ts = 0.0f, tq = 0.0f;
        #pragma unroll
        for (int i = 0; i < 8; i++) { ts += ssum[i]; tq += ssq[i]; }
        float mu  = ts / (float)Cc;
        float var = tq / (float)Cc - mu * mu;
        s_mu  = mu;
        s_inv = rsqrtf(var + 1e-5f);
    }
    __syncthreads();
    float mu = s_mu, inv = s_inv;

    const float4 w0 = reinterpret_cast<const float4*>(lw)[tid];
    const float4 w1 = reinterpret_cast<const float4*>(lw)[tid + 256];
    const float4 b0 = reinterpret_cast<const float4*>(lb)[tid];
    const float4 b1 = reinterpret_cast<const float4*>(lb)[tid + 256];

    float4 o0, o1;
    o0.x = (v0.x - mu) * inv * w0.x + b0.x;
    o0.y = (v0.y - mu) * inv * w0.y + b0.y;
    o0.z = (v0.z - mu) * inv * w0.z + b0.z;
    o0.w = (v0.w - mu) * inv * w0.w + b0.w;
    o1.x = (v1.x - mu) * inv * w1.x + b1.x;
    o1.y = (v1.y - mu) * inv * w1.y + b1.y;
    o1.z = (v1.z - mu) * inv * w1.z + b1.z;
    o1.w = (v1.w - mu) * inv * w1.w + b1.w;
    orow[tid]       = o0;
    orow[tid + 256] = o1;
}

// ---------------- host orchestration ---------------------------------------
extern "C" void kernel_launch(void* const* d_in, const int* in_sizes, int n_in,
                              void* d_out, int out_size) {
    (void)in_sizes; (void)n_in; (void)out_size;
    const float* x      = (const float*)d_in[0];
    const float* Wq     = (const float*)d_in[1];
    const float* Wk     = (const float*)d_in[2];
    const float* Wv     = (const float*)d_in[3];
    const float* Wo     = (const float*)d_in[4];
    const float* conv_w = (const float*)d_in[5];
    const float* conv_b = (const float*)d_in[6];
    const float* gate_w = (const float*)d_in[7];
    const float* gate_b = (const float*)d_in[8];
    const float* ln_w   = (const float*)d_in[9];
    const float* ln_b   = (const float*)d_in[10];
    const float* gamma  = (const float*)d_in[11];

    float *p_q, *p_k, *p_v, *p_gate, *p_y;
    float *p_Wqt, *p_Wkt, *p_Wvt, *p_Wot, *p_Wgt;
    cudaGetSymbolAddress((void**)&p_q, g_q);
    cudaGetSymbolAddress((void**)&p_k, g_k);
    cudaGetSymbolAddress((void**)&p_v, g_v);
    cudaGetSymbolAddress((void**)&p_gate, g_gate);
    cudaGetSymbolAddress((void**)&p_y, g_y);
    cudaGetSymbolAddress((void**)&p_Wqt, g_Wqt);
    cudaGetSymbolAddress((void**)&p_Wkt, g_Wkt);
    cudaGetSymbolAddress((void**)&p_Wvt, g_Wvt);
    cudaGetSymbolAddress((void**)&p_Wot, g_Wot);
    cudaGetSymbolAddress((void**)&p_Wgt, g_Wgt);

    // 0) pre-round the 5 weight matrices to tf32 in one launch
    const int wBlocks = (Cc * Cc) / 1024;  // 4096 per weight
    cvt5_tf32_kernel<<<5 * wBlocks, 256>>>(Wq, p_Wqt, Wk, p_Wkt, Wv, p_Wvt,
                                           Wo, p_Wot, gate_w, p_Wgt);

    // 1) depthwise conv + SiLU (float4); also emits tf32-rounded x (g_xt)
    conv_silu_kernel<<<(Mrows * Cc / 4) / 256, 256>>>(x, conv_w, conv_b);

    // 2) all four projections in ONE launch (q, k, v, gate)
    dim3 qgrid(64, Mrows / 128);   // 64 col-tiles (4 segs x 16), 128 row-tiles
    gemm_qkvg_kernel<<<qgrid, 256>>>(gate_b);

    // 3) decayed scan (chunked, exact); q/k already l2-normalized in epilogue
    scan_pass1<<<Bb * Hh * NCHUNK / 4, 128>>>(p_k, p_v, gamma);
    scan_pass2<<<16, 128>>>(gamma);
    scan_pass3<<<Bb * Hh * NCHUNK / 4, 128>>>(p_k, p_v, p_q, p_gate, gamma);

    // 4) output projection + LayerNorm
    dim3 ogrid(Cc / 128, Mrows / 128);   // (16, 128)
    gemm_out_kernel<<<ogrid, 256>>>();
    ln_kernel<<<Mrows, 256>>>(p_y, ln_w, ln_b, (float*)d_out);
}

// round 11
// speedup vs baseline: 2.0579x; 1.0089x over previous
#include <cuda_runtime.h>
#include <cstdint>
#include <cstdio>

// Problem constants
namespace {
constexpr int Bb = 4, Tt = 4096, Cc = 2048, Hh = 16, DhD = 128;
constexpr int Mrows = Bb * Tt;            // 16384
constexpr int NCHUNK = 64;                // scan chunks
constexpr int LCH = Tt / NCHUNK;          // 64 steps per chunk
// GEMM pipeline: 4 stages, prefetch distance 3
constexpr int GST = 4;
constexpr int STAGE_W = 128 * 16;         // 2048 words per (matrix,stage)
constexpr int GEMM_SMEM = 2 * GST * STAGE_W * 4 + 128 * 4 * 4;  // 67584 B
}

// ---------------- scratch (static device globals; no allocation allowed) ---
__device__ float g_xconv[(size_t)Bb * Tt * Cc];
__device__ float g_q   [(size_t)Bb * Tt * Cc];
__device__ float g_k   [(size_t)Bb * Tt * Cc];
__device__ float g_v   [(size_t)Bb * Tt * Cc];
__device__ float g_gate[(size_t)Bb * Tt * Cc];
__device__ float g_att [(size_t)Bb * Tt * Cc];
__device__ float g_y   [(size_t)Bb * Tt * Cc];
__device__ float g_xt  [(size_t)Bb * Tt * Cc];      // tf32-rounded x
__device__ float g_Wqt [(size_t)Cc * Cc];
__device__ float g_Wkt [(size_t)Cc * Cc];
__device__ float g_Wvt [(size_t)Cc * Cc];
__device__ float g_Wot [(size_t)Cc * Cc];
__device__ float g_Wgt [(size_t)Cc * Cc];
__device__ float g_F    [(size_t)Bb * Hh * NCHUNK * DhD];
__device__ float g_carry[(size_t)Bb * Hh * NCHUNK * DhD];

// ---------------- helpers --------------------------------------------------
__device__ __forceinline__ uint32_t f2tf32(float f) {
    uint32_t u;
    asm("cvt.rna.tf32.f32 %0, %1;" : "=r"(u) : "f"(f));
    return u;
}

__device__ __forceinline__ float tf32r(float f) { return __uint_as_float(f2tf32(f)); }

__device__ __forceinline__ void mma_tf32(float& d0, float& d1, float& d2, float& d3,
                                         uint32_t a0, uint32_t a1, uint32_t a2, uint32_t a3,
                                         uint32_t b0, uint32_t b1) {
    asm volatile(
        "mma.sync.aligned.m16n8k8.row.col.f32.tf32.tf32.f32 "
        "{%0,%1,%2,%3}, {%4,%5,%6,%7}, {%8,%9}, {%0,%1,%2,%3};\n"
        : "+f"(d0), "+f"(d1), "+f"(d2), "+f"(d3)
        : "r"(a0), "r"(a1), "r"(a2), "r"(a3), "r"(b0), "r"(b1));
}

// ---------------- 0) tf32 pre-round for the 5 weight matrices (one launch) --
__global__ void cvt5_tf32_kernel(const float* __restrict__ w0, float* __restrict__ o0,
                                 const float* __restrict__ w1, float* __restrict__ o1,
                                 const float* __restrict__ w2, float* __restrict__ o2,
                                 const float* __restrict__ w3, float* __restrict__ o3,
                                 const float* __restrict__ w4, float* __restrict__ o4) {
    const int seg = blockIdx.x >> 12;
    const int i   = (blockIdx.x & 4095) * 256 + threadIdx.x;
    const float* in;
    float* out;
    switch (seg) {
        case 0: in = w0; out = o0; break;
        case 1: in = w1; out = o1; break;
        case 2: in = w2; out = o2; break;
        case 3: in = w3; out = o3; break;
        default: in = w4; out = o4; break;
    }
    float4 v = reinterpret_cast<const float4*>(in)[i];
    v.x = tf32r(v.x); v.y = tf32r(v.y); v.z = tf32r(v.z); v.w = tf32r(v.w);
    reinterpret_cast<float4*>(out)[i] = v;
}

// ---------------- 1) causal depthwise conv (K=4) + SiLU + x tf32 side-out ---
__global__ void conv_silu_kernel(const float* __restrict__ x,
                                 const float* __restrict__ w,
                                 const float* __restrict__ bias) {
    int vid = blockIdx.x * blockDim.x + threadIdx.x;    // over B*T*C/4
    int cq  = vid & (Cc / 4 - 1);                       // channel quad
    int bt  = vid >> 9;                                 // /(2048/4)
    int t   = bt & (Tt - 1);
    int c   = cq * 4;

    const float4* x4 = reinterpret_cast<const float4*>(x);
    int base = (bt - t) * (Cc / 4) + cq;                // b*T*C/4 + cq

    float4 wr0 = reinterpret_cast<const float4*>(w)[c + 0];
    float4 wr1 = reinterpret_cast<const float4*>(w)[c + 1];
    float4 wr2 = reinterpret_cast<const float4*>(w)[c + 2];
    float4 wr3 = reinterpret_cast<const float4*>(w)[c + 3];
    float4 bb  = reinterpret_cast<const float4*>(bias)[cq];

    float4 a = bb;
    float4 xt3;
    #pragma unroll
    for (int j = 0; j < 4; j++) {
        int tt = t - 3 + j;
        if (tt >= 0) {
            float4 xv = x4[base + tt * (Cc / 4)];
            if (j == 3) xt3 = xv;
            float wj0 = (&wr0.x)[j], wj1 = (&wr1.x)[j], wj2 = (&wr2.x)[j], wj3 = (&wr3.x)[j];
            a.x = fmaf(xv.x, wj0, a.x);
            a.y = fmaf(xv.y, wj1, a.y);
            a.z = fmaf(xv.z, wj2, a.z);
            a.w = fmaf(xv.w, wj3, a.w);
        }
    }

    float4 s;
    s.x = tf32r(a.x / (1.0f + expf(-a.x)));
    s.y = tf32r(a.y / (1.0f + expf(-a.y)));
    s.z = tf32r(a.z / (1.0f + expf(-a.z)));
    s.w = tf32r(a.w / (1.0f + expf(-a.w)));
    reinterpret_cast<float4*>(g_xconv)[vid] = s;

    float4 xr;
    xr.x = tf32r(xt3.x); xr.y = tf32r(xt3.y); xr.z = tf32r(xt3.z); xr.w = tf32r(xt3.w);
    reinterpret_cast<float4*>(g_xt)[vid] = xr;
}

// ---------------- 2) TF32 GEMM tile body (4-stage pipeline, frag hoist) -----
// Computes one 128x128 tile of Out = A[M,2048] * W[128-col slab]^T.
// mode 0: plain.  mode 1: sigmoid(out + bias[col]).  mode 2: per-row l2norm
// over the 128-col tile (tile == one head since BN=128).
// smem layout per (matrix,stage): 128 rows x 16 words, XOR-swizzled chunks:
//   word(row,k) at row*16 + (((k>>2) ^ ((row>>1)&3))<<2) + (k&3)
__device__ __forceinline__
void gemm_tile_body(const float* __restrict__ A, const float* __restrict__ W,
                    float* __restrict__ Out, const float* __restrict__ bias,
                    int mode, int bm, int bn) {
    constexpr int BM = 128, BKk = 16;
    constexpr int K = Cc, N = Cc;
    constexpr int KCH = K / BKk;          // 128 iterations

    extern __shared__ uint32_t dyn[];
    uint32_t* AsB = dyn;                  // GST * STAGE_W words
    uint32_t* BsB = dyn + GST * STAGE_W;  // GST * STAGE_W words
    float*    red = (float*)(dyn + 2 * GST * STAGE_W);  // 128*4 floats

    const int tid  = threadIdx.x;
    const int warp = tid >> 5, lane = tid & 31;
    const int gid  = lane >> 2, tg = lane & 3;
    const int wm   = warp & 1;       // 0..1  -> 64-row slab
    const int wn   = warp >> 1;      // 0..3  -> 32-col slab

    const int lr = tid >> 2;         // 0..63  (loader row)
    const int lc = tid & 3;          // chunk 0..3

    uint32_t sA = (uint32_t)__cvta_generic_to_shared(AsB);
    uint32_t sB = (uint32_t)__cvta_generic_to_shared(BsB);

    auto issue = [&](int s, int k0) {
        #pragma unroll
        for (int r = 0; r < 2; r++) {
            int row = lr + r * 64;
            int sw  = (row >> 1) & 3;
            uint32_t off = (uint32_t)(s * BM * BKk + row * 16 + ((lc ^ sw) << 2)) * 4u;
            const float* gA = A + (size_t)(bm + row) * K + k0 + lc * 4;
            asm volatile("cp.async.cg.shared.global [%0], [%1], 16;\n"
                         :: "r"(sA + off), "l"(gA));
            const float* gB = W + (size_t)(bn + row) * K + k0 + lc * 4;
            asm volatile("cp.async.cg.shared.global [%0], [%1], 16;\n"
                         :: "r"(sB + off), "l"(gB));
        }
        asm volatile("cp.async.commit_group;\n");
    };

    float acc[4][4][4] = {};

    issue(0, 0);
    issue(1, BKk);
    issue(2, 2 * BKk);

    int s = 0;
    for (int i = 0; i < KCH; i++) {
        if (i < KCH - 2)       asm volatile("cp.async.wait_group 2;\n" ::: "memory");
        else if (i == KCH - 2) asm volatile("cp.async.wait_group 1;\n" ::: "memory");
        else                   asm volatile("cp.async.wait_group 0;\n" ::: "memory");
        __syncthreads();

        if (i + 3 < KCH) {
            int s2 = s + 3; if (s2 >= GST) s2 -= GST;
            issue(s2, (i + 3) * BKk);
        }

        const uint32_t* Ab = &AsB[s * STAGE_W];
        const uint32_t* Bb = &BsB[s * STAGE_W];

        // Fragment hoist: load ALL fragments for the stage, then all MMAs.
        uint32_t af[2][4][4], bf[2][4][2];
        #pragma unroll
        for (int half = 0; half < 2; half++) {
            const int c0 = half * 2;
            #pragma unroll
            for (int mt = 0; mt < 4; mt++) {
                int row = wm * 64 + mt * 16 + gid;
                int sw  = (row >> 1) & 3;
                int b0i = row * 16 + tg;
                int b1i = (row + 8) * 16 + tg;
                af[half][mt][0] = Ab[b0i + ((c0 ^ sw) << 2)];
                af[half][mt][1] = Ab[b1i + ((c0 ^ sw) << 2)];
                af[half][mt][2] = Ab[b0i + (((c0 + 1) ^ sw) << 2)];
                af[half][mt][3] = Ab[b1i + (((c0 + 1) ^ sw) << 2)];
            }
            #pragma unroll
            for (int nt = 0; nt < 4; nt++) {
                int col = wn * 32 + nt * 8 + gid;
                int sw  = (col >> 1) & 3;
                int bi  = col * 16 + tg;
                bf[half][nt][0] = Bb[bi + ((c0 ^ sw) << 2)];
                bf[half][nt][1] = Bb[bi + (((c0 + 1) ^ sw) << 2)];
            }
        }
        #pragma unroll
        for (int half = 0; half < 2; half++)
            #pragma unroll
            for (int mt = 0; mt < 4; mt++)
                #pragma unroll
                for (int nt = 0; nt < 4; nt++)
                    mma_tf32(acc[mt][nt][0], acc[mt][nt][1], acc[mt][nt][2], acc[mt][nt][3],
                             af[half][mt][0], af[half][mt][1], af[half][mt][2], af[half][mt][3],
                             bf[half][nt][0], bf[half][nt][1]);
        s++; if (s >= GST) s = 0;
    }

    // ---- fused l2norm over the 128-col tile (mode 2, tile == one head) -----
    if (mode == 2) {
        __syncthreads();
        float invLo[4], invHi[4];
        #pragma unroll
        for (int mt = 0; mt < 4; mt++) {
            float slo = 0.0f, shi = 0.0f;
            #pragma unroll
            for (int nt = 0; nt < 4; nt++) {
                slo = fmaf(acc[mt][nt][0], acc[mt][nt][0], slo);
                slo = fmaf(acc[mt][nt][1], acc[mt][nt][1], slo);
                shi = fmaf(acc[mt][nt][2], acc[mt][nt][2], shi);
                shi = fmaf(acc[mt][nt][3], acc[mt][nt][3], shi);
            }
            slo += __shfl_xor_sync(0xffffffffu, slo, 1);
            slo += __shfl_xor_sync(0xffffffffu, slo, 2);
            shi += __shfl_xor_sync(0xffffffffu, shi, 1);
            shi += __shfl_xor_sync(0xffffffffu, shi, 2);
            if (tg == 0) {
                int r = wm * 64 + mt * 16 + gid;
                red[r * 4 + wn]       = slo;
                red[(r + 8) * 4 + wn] = shi;
            }
        }
        __syncthreads();
        #pragma unroll
        for (int mt = 0; mt < 4; mt++) {
            int r = wm * 64 + mt * 16 + gid;
            float slo = red[r * 4 + 0] + red[r * 4 + 1] + red[r * 4 + 2] + red[r * 4 + 3];
            float shi = red[(r + 8) * 4 + 0] + red[(r + 8) * 4 + 1]
                      + red[(r + 8) * 4 + 2] + red[(r + 8) * 4 + 3];
            invLo[mt] = 1.0f / fmaxf(sqrtf(slo), 1e-12f);
            invHi[mt] = 1.0f / fmaxf(sqrtf(shi), 1e-12f);
        }
        #pragma unroll
        for (int mt = 0; mt < 4; mt++)
            #pragma unroll
            for (int nt = 0; nt < 4; nt++) {
                acc[mt][nt][0] *= invLo[mt];
                acc[mt][nt][1] *= invLo[mt];
                acc[mt][nt][2] *= invHi[mt];
                acc[mt][nt][3] *= invHi[mt];
            }
    }

    // epilogue stores
    #pragma unroll
    for (int mt = 0; mt < 4; mt++) {
        #pragma unroll
        for (int nt = 0; nt < 4; nt++) {
            int row = bm + wm * 64 + mt * 16 + gid;
            int col = bn + wn * 32 + nt * 8 + tg * 2;
            float v0 = acc[mt][nt][0], v1 = acc[mt][nt][1];
            float v2 = acc[mt][nt][2], v3 = acc[mt][nt][3];
            if (mode == 1) {
                float b0 = bias[col], b1 = bias[col + 1];
                v0 = 1.0f / (1.0f + expf(-(v0 + b0)));
                v1 = 1.0f / (1.0f + expf(-(v1 + b1)));
                v2 = 1.0f / (1.0f + expf(-(v2 + b0)));
                v3 = 1.0f / (1.0f + expf(-(v3 + b1)));
            }
            *reinterpret_cast<float2*>(&Out[(size_t)row * N + col])       = make_float2(v0, v1);
            *reinterpret_cast<float2*>(&Out[(size_t)(row + 8) * N + col]) = make_float2(v2, v3);
        }
    }
}

// Combined q/k/v/gate projection: one launch, 64 column-tiles x 128 row-tiles.
// seg = blockIdx.x>>4: 0=q(mode2) 1=k(mode2) 2=v(mode0) 3=gate(mode1, A=xconv)
__global__ __launch_bounds__(256, 2)
void gemm_qkvg_kernel(const float* __restrict__ gate_b) {
    const int seg = blockIdx.x >> 4;
    const int bn  = (blockIdx.x & 15) * 128;
    const int bm  = blockIdx.y * 128;

    const float* A;
    const float* W;
    float* Out;
    int mode;
    switch (seg) {
        case 0:  A = g_xt;    W = g_Wqt; Out = g_q;    mode = 2; break;
        case 1:  A = g_xt;    W = g_Wkt; Out = g_k;    mode = 2; break;
        case 2:  A = g_xt;    W = g_Wvt; Out = g_v;    mode = 0; break;
        default: A = g_xconv; W = g_Wgt; Out = g_gate; mode = 1; break;
    }
    gemm_tile_body(A, W, Out, gate_b, mode, bm, bn);
}

// Output projection: y = att * Wo^T (mode 0)
__global__ __launch_bounds__(256, 2)
void gemm_out_kernel() {
    gemm_tile_body(g_att, g_Wot, g_y, nullptr, 0, blockIdx.y * 128, blockIdx.x * 128);
}

// ---------------- 4) chunked decayed scan (float4, warp-per-chunk) ----------
__global__ void scan_pass1(const float* __restrict__ k, const float* __restrict__ v,
                           const float* __restrict__ gamma) {
    int wid  = threadIdx.x >> 5, lane = threadIdx.x & 31;
    int blk  = blockIdx.x * 4 + wid;          // 0..4095
    int c    = blk & (NCHUNK - 1);
    int bh   = blk >> 6;
    int h    = bh & (Hh - 1);
    int b    = bh >> 4;
    float g  = gamma[h];
    const float4* k4 = reinterpret_cast<const float4*>(k);
    const float4* v4 = reinterpret_cast<const float4*>(v);
    size_t idx = ((size_t)(b * Tt + c * LCH) * Cc + h * DhD) / 4 + lane;
    float4 S = make_float4(0.f, 0.f, 0.f, 0.f);
    #pragma unroll 4
    for (int i = 0; i < LCH; i++) {
        float4 kk = k4[idx], vv = v4[idx];
        S.x = fmaf(g, S.x, kk.x * vv.x);
        S.y = fmaf(g, S.y, kk.y * vv.y);
        S.z = fmaf(g, S.z, kk.z * vv.z);
        S.w = fmaf(g, S.w, kk.w * vv.w);
        idx += Cc / 4;
    }
    reinterpret_cast<float4*>(g_F)[((size_t)bh * NCHUNK + c) * (DhD / 4) + lane] = S;
}

__global__ void scan_pass2(const float* __restrict__ gamma) {
    int tid = blockIdx.x * blockDim.x + threadIdx.x;   // over Bb*Hh*DhD/4 = 2048
    int d4  = tid & (DhD / 4 - 1);
    int bh  = tid >> 5;
    int h   = bh & (Hh - 1);
    float g  = gamma[h];
    float gL = powf(g, (float)LCH);     // exact 1.0 for gamma=1 head
    const float4* F4 = reinterpret_cast<const float4*>(g_F);
    float4* C4       = reinterpret_cast<float4*>(g_carry);
    float4 carry = make_float4(0.f, 0.f, 0.f, 0.f);
    for (int c = 0; c < NCHUNK; c++) {
        size_t o = ((size_t)bh * NCHUNK + c) * (DhD / 4) + d4;
        C4[o] = carry;
        float4 f = F4[o];
        carry.x = fmaf(gL, carry.x, f.x);
        carry.y = fmaf(gL, carry.y, f.y);
        carry.z = fmaf(gL, carry.z, f.z);
        carry.w = fmaf(gL, carry.w, f.w);
    }
}

__global__ void scan_pass3(const float* __restrict__ k, const float* __restrict__ v,
                           const float* __restrict__ q, const float* __restrict__ gate,
                           const float* __restrict__ gamma) {
    int wid  = threadIdx.x >> 5, lane = threadIdx.x & 31;
    int blk  = blockIdx.x * 4 + wid;
    int c    = blk & (NCHUNK - 1);
    int bh   = blk >> 6;
    int h    = bh & (Hh - 1);
    int b    = bh >> 4;
    float g  = gamma[h];
    const float4* k4 = reinterpret_cast<const float4*>(k);
    const float4* v4 = reinterpret_cast<const float4*>(v);
    const float4* q4 = reinterpret_cast<const float4*>(q);
    const float4* g4 = reinterpret_cast<const float4*>(gate);
    float4* a4       = reinterpret_cast<float4*>(g_att);
    float4 S = reinterpret_cast<const float4*>(g_carry)
                   [((size_t)bh * NCHUNK + c) * (DhD / 4) + lane];
    size_t idx = ((size_t)(b * Tt + c * LCH) * Cc + h * DhD) / 4 + lane;
    #pragma unroll 4
    for (int i = 0; i < LCH; i++) {
        float4 kk = k4[idx], vv = v4[idx];
        S.x = fmaf(g, S.x, kk.x * vv.x);
        S.y = fmaf(g, S.y, kk.y * vv.y);
        S.z = fmaf(g, S.z, kk.z * vv.z);
        S.w = fmaf(g, S.w, kk.w * vv.w);
        float4 gg = g4[idx], qq = q4[idx];
        float4 o;
        o.x = tf32r(gg.x * S.x * qq.x);
        o.y = tf32r(gg.y * S.y * qq.y);
        o.z = tf32r(gg.z * S.z * qq.z);
        o.w = tf32r(gg.w * S.w * qq.w);
        a4[idx] = o;
        idx += Cc / 4;
    }
}

// ---------------- 5) LayerNorm over C=2048 ---------------------------------
__global__ __launch_bounds__(256)
void ln_kernel(const float* __restrict__ y, const float* __restrict__ lw,
               const float* __restrict__ lb, float* __restrict__ out) {
    int row = blockIdx.x;
    int tid = threadIdx.x;
    const float4* yr = reinterpret_cast<const float4*>(y + (size_t)row * Cc);
    float4* orow     = reinterpret_cast<float4*>(out + (size_t)row * Cc);

    float4 v0 = yr[tid];
    float4 v1 = yr[tid + 256];
    float sum = v0.x + v0.y + v0.z + v0.w + v1.x + v1.y + v1.z + v1.w;
    float sq  = v0.x * v0.x + v0.y * v0.y + v0.z * v0.z + v0.w * v0.w
              + v1.x * v1.x + v1.y * v1.y + v1.z * v1.z + v1.w * v1.w;

    #pragma unroll
    for (int o = 16; o; o >>= 1) {
        sum += __shfl_xor_sync(0xffffffffu, sum, o);
        sq  += __shfl_xor_sync(0xffffffffu, sq, o);
    }
    __shared__ float ssum[8], ssq[8];
    __shared__ float s_mu, s_inv;
    int warp = tid >> 5, lane = tid & 31;
    if (lane == 0) { ssum[warp] = sum; ssq[warp] = sq; }
    __syncthreads();
    if (tid == 0) {
        float ts = 0.0f, tq = 0.0f;
        #pragma unroll
        for (int i = 0; i < 8; i++) { ts += ssum[i]; tq += ssq[i]; }
        float mu  = ts / (float)Cc;
        float var = tq / (float)Cc - mu * mu;
        s_mu  = mu;
        s_inv = rsqrtf(var + 1e-5f);
    }
    __syncthreads();
    float mu = s_mu, inv = s_inv;

    const float4 w0 = reinterpret_cast<const float4*>(lw)[tid];
    const float4 w1 = reinterpret_cast<const float4*>(lw)[tid + 256];
    const float4 b0 = reinterpret_cast<const float4*>(lb)[tid];
    const float4 b1 = reinterpret_cast<const float4*>(lb)[tid + 256];

    float4 o0, o1;
    o0.x = (v0.x - mu) * inv * w0.x + b0.x;
    o0.y = (v0.y - mu) * inv * w0.y + b0.y;
    o0.z = (v0.z - mu) * inv * w0.z + b0.z;
    o0.w = (v0.w - mu) * inv * w0.w + b0.w;
    o1.x = (v1.x - mu) * inv * w1.x + b1.x;
    o1.y = (v1.y - mu) * inv * w1.y + b1.y;
    o1.z = (v1.z - mu) * inv * w1.z + b1.z;
    o1.w = (v1.w - mu) * inv * w1.w + b1.w;
    orow[tid]       = o0;
    orow[tid + 256] = o1;
}

// ---------------- host orchestration ---------------------------------------
extern "C" void kernel_launch(void* const* d_in, const int* in_sizes, int n_in,
                              void* d_out, int out_size) {
    (void)in_sizes; (void)n_in; (void)out_size;
    const float* x      = (const float*)d_in[0];
    const float* Wq     = (const float*)d_in[1];
    const float* Wk     = (const float*)d_in[2];
    const float* Wv     = (const float*)d_in[3];
    const float* Wo     = (const float*)d_in[4];
    const float* conv_w = (const float*)d_in[5];
    const float* conv_b = (const float*)d_in[6];
    const float* gate_w = (const float*)d_in[7];
    const float* gate_b = (const float*)d_in[8];
    const float* ln_w   = (const float*)d_in[9];
    const float* ln_b   = (const float*)d_in[10];
    const float* gamma  = (const float*)d_in[11];

    float *p_q, *p_k, *p_v, *p_gate, *p_y;
    float *p_Wqt, *p_Wkt, *p_Wvt, *p_Wot, *p_Wgt;
    cudaGetSymbolAddress((void**)&p_q, g_q);
    cudaGetSymbolAddress((void**)&p_k, g_k);
    cudaGetSymbolAddress((void**)&p_v, g_v);
    cudaGetSymbolAddress((void**)&p_gate, g_gate);
    cudaGetSymbolAddress((void**)&p_y, g_y);
    cudaGetSymbolAddress((void**)&p_Wqt, g_Wqt);
    cudaGetSymbolAddress((void**)&p_Wkt, g_Wkt);
    cudaGetSymbolAddress((void**)&p_Wvt, g_Wvt);
    cudaGetSymbolAddress((void**)&p_Wot, g_Wot);
    cudaGetSymbolAddress((void**)&p_Wgt, g_Wgt);

    // allow 66KB dynamic smem on the GEMM kernels (idempotent)
    cudaFuncSetAttribute(gemm_qkvg_kernel, cudaFuncAttributeMaxDynamicSharedMemorySize, GEMM_SMEM);
    cudaFuncSetAttribute(gemm_out_kernel,  cudaFuncAttributeMaxDynamicSharedMemorySize, GEMM_SMEM);

    // 0) pre-round the 5 weight matrices to tf32 in one launch
    const int wBlocks = (Cc * Cc) / 1024;  // 4096 per weight
    cvt5_tf32_kernel<<<5 * wBlocks, 256>>>(Wq, p_Wqt, Wk, p_Wkt, Wv, p_Wvt,
                                           Wo, p_Wot, gate_w, p_Wgt);

    // 1) depthwise conv + SiLU (float4); also emits tf32-rounded x (g_xt)
    conv_silu_kernel<<<(Mrows * Cc / 4) / 256, 256>>>(x, conv_w, conv_b);

    // 2) all four projections in ONE launch (q, k, v, gate)
    dim3 qgrid(64, Mrows / 128);   // 64 col-tiles (4 segs x 16), 128 row-tiles
    gemm_qkvg_kernel<<<qgrid, 256, GEMM_SMEM>>>(gate_b);

    // 3) decayed scan (chunked, exact); q/k already l2-normalized in epilogue
    scan_pass1<<<Bb * Hh * NCHUNK / 4, 128>>>(p_k, p_v, gamma);
    scan_pass2<<<16, 128>>>(gamma);
    scan_pass3<<<Bb * Hh * NCHUNK / 4, 128>>>(p_k, p_v, p_q, p_gate, gamma);

    // 4) output projection + LayerNorm
    dim3 ogrid(Cc / 128, Mrows / 128);   // (16, 128)
    gemm_out_kernel<<<ogrid, 256, GEMM_SMEM>>>();
    ln_kernel<<<Mrows, 256>>>(p_y, ln_w, ln_b, (float*)d_out);
}

// round 12
// speedup vs baseline: 3.6517x; 1.7745x over previous
#include <cuda_runtime.h>
#include <cuda_fp16.h>
#include <cstdint>
#include <cstdio>

// Problem constants
namespace {
constexpr int Bb = 4, Tt = 4096, Cc = 2048, Hh = 16, DhD = 128;
constexpr int Mrows = Bb * Tt;            // 16384
constexpr int NCHUNK = 64;                // scan chunks
constexpr int LCH = Tt / NCHUNK;          // 64 steps per chunk
// GEMM pipeline: 4 stages, prefetch distance 3. One stage row = 16 b32 words
// = 32 fp16 halves of K. 64 mainloop iterations cover K=2048.
constexpr int GST = 4;
constexpr int STAGE_W = 128 * 16;         // 2048 words per (matrix,stage)
constexpr int GEMM_SMEM = 2 * GST * STAGE_W * 4 + 128 * 4 * 4;  // 67584 B
}

// ---------------- scratch (static device globals; no allocation allowed) ---
__device__ __half g_xconv[(size_t)Bb * Tt * Cc];
__device__ float  g_q   [(size_t)Bb * Tt * Cc];
__device__ float  g_k   [(size_t)Bb * Tt * Cc];
__device__ float  g_v   [(size_t)Bb * Tt * Cc];
__device__ float  g_gate[(size_t)Bb * Tt * Cc];
__device__ __half g_att [(size_t)Bb * Tt * Cc];
__device__ float  g_y   [(size_t)Bb * Tt * Cc];
__device__ __half g_xt  [(size_t)Bb * Tt * Cc];      // fp16-rounded x
__device__ __half g_Wqt [(size_t)Cc * Cc];
__device__ __half g_Wkt [(size_t)Cc * Cc];
__device__ __half g_Wvt [(size_t)Cc * Cc];
__device__ __half g_Wot [(size_t)Cc * Cc];
__device__ __half g_Wgt [(size_t)Cc * Cc];
__device__ float  g_F    [(size_t)Bb * Hh * NCHUNK * DhD];
__device__ float  g_carry[(size_t)Bb * Hh * NCHUNK * DhD];

// ---------------- helpers --------------------------------------------------
__device__ __forceinline__ uint32_t pack_h2(float a, float b) {
    __half2 h = __floats2half2_rn(a, b);
    return *reinterpret_cast<uint32_t*>(&h);
}

__device__ __forceinline__ void mma_f16(float& d0, float& d1, float& d2, float& d3,
                                        uint32_t a0, uint32_t a1, uint32_t a2, uint32_t a3,
                                        uint32_t b0, uint32_t b1) {
    asm volatile(
        "mma.sync.aligned.m16n8k16.row.col.f32.f16.f16.f32 "
        "{%0,%1,%2,%3}, {%4,%5,%6,%7}, {%8,%9}, {%0,%1,%2,%3};\n"
        : "+f"(d0), "+f"(d1), "+f"(d2), "+f"(d3)
        : "r"(a0), "r"(a1), "r"(a2), "r"(a3), "r"(b0), "r"(b1));
}

// ---------------- 0) fp16 conversion of the 5 weight matrices (one launch) --
// Each thread converts 8 floats -> 8 halves (16B out).
__global__ void cvt5_f16_kernel(const float* __restrict__ w0, __half* __restrict__ o0,
                                const float* __restrict__ w1, __half* __restrict__ o1,
                                const float* __restrict__ w2, __half* __restrict__ o2,
                                const float* __restrict__ w3, __half* __restrict__ o3,
                                const float* __restrict__ w4, __half* __restrict__ o4) {
    const int seg = blockIdx.x >> 11;                 // 2048 blocks per weight
    const int i   = (blockIdx.x & 2047) * 256 + threadIdx.x;  // 8-elem group idx
    const float* in;
    __half* out;
    switch (seg) {
        case 0: in = w0; out = o0; break;
        case 1: in = w1; out = o1; break;
        case 2: in = w2; out = o2; break;
        case 3: in = w3; out = o3; break;
        default: in = w4; out = o4; break;
    }
    float4 v0 = reinterpret_cast<const float4*>(in)[i * 2];
    float4 v1 = reinterpret_cast<const float4*>(in)[i * 2 + 1];
    uint4 pk;
    pk.x = pack_h2(v0.x, v0.y);
    pk.y = pack_h2(v0.z, v0.w);
    pk.z = pack_h2(v1.x, v1.y);
    pk.w = pack_h2(v1.z, v1.w);
    reinterpret_cast<uint4*>(out)[i] = pk;
}

// ---------------- 1) causal depthwise conv (K=4) + SiLU + x fp16 side-out ---
__global__ void conv_silu_kernel(const float* __restrict__ x,
                                 const float* __restrict__ w,
                                 const float* __restrict__ bias) {
    int vid = blockIdx.x * blockDim.x + threadIdx.x;    // over B*T*C/4
    int cq  = vid & (Cc / 4 - 1);                       // channel quad
    int bt  = vid >> 9;                                 // /(2048/4)
    int t   = bt & (Tt - 1);
    int c   = cq * 4;

    const float4* x4 = reinterpret_cast<const float4*>(x);
    int base = (bt - t) * (Cc / 4) + cq;                // b*T*C/4 + cq

    float4 wr0 = reinterpret_cast<const float4*>(w)[c + 0];
    float4 wr1 = reinterpret_cast<const float4*>(w)[c + 1];
    float4 wr2 = reinterpret_cast<const float4*>(w)[c + 2];
    float4 wr3 = reinterpret_cast<const float4*>(w)[c + 3];
    float4 bb  = reinterpret_cast<const float4*>(bias)[cq];

    float4 a = bb;
    float4 xt3;
    #pragma unroll
    for (int j = 0; j < 4; j++) {
        int tt = t - 3 + j;
        if (tt >= 0) {
            float4 xv = x4[base + tt * (Cc / 4)];
            if (j == 3) xt3 = xv;
            float wj0 = (&wr0.x)[j], wj1 = (&wr1.x)[j], wj2 = (&wr2.x)[j], wj3 = (&wr3.x)[j];
            a.x = fmaf(xv.x, wj0, a.x);
            a.y = fmaf(xv.y, wj1, a.y);
            a.z = fmaf(xv.z, wj2, a.z);
            a.w = fmaf(xv.w, wj3, a.w);
        }
    }

    uint2 sc;
    sc.x = pack_h2(a.x / (1.0f + expf(-a.x)), a.y / (1.0f + expf(-a.y)));
    sc.y = pack_h2(a.z / (1.0f + expf(-a.z)), a.w / (1.0f + expf(-a.w)));
    reinterpret_cast<uint2*>(g_xconv)[vid] = sc;

    uint2 xr;
    xr.x = pack_h2(xt3.x, xt3.y);
    xr.y = pack_h2(xt3.z, xt3.w);
    reinterpret_cast<uint2*>(g_xt)[vid] = xr;
}

// ---------------- 2) FP16 GEMM tile body (4-stage pipeline, frag hoist) -----
// Computes one 128x128 tile of Out = A[M,2048] * W[128-col slab]^T, fp16 in,
// fp32 accumulate. Schedule/addressing isomorphic to the proven tf32 loop:
// stage row = 16 b32 words = 32 halves of K; 64 iterations.
// mode 0: plain.  mode 1: sigmoid(out + bias[col]).  mode 2: per-row l2norm.
// smem layout per (matrix,stage): 128 rows x 16 words, XOR-swizzled chunks:
//   word(row,w) at row*16 + (((w>>2) ^ ((row>>1)&3))<<2) + (w&3)
__device__ __forceinline__
void gemm_tile_body(const __half* __restrict__ A, const __half* __restrict__ W,
                    float* __restrict__ Out, const float* __restrict__ bias,
                    int mode, int bm, int bn) {
    constexpr int BM = 128;
    constexpr int KH = 32;                // K halves per stage
    constexpr int KCH = Cc / KH;          // 64 iterations
    constexpr int N = Cc;

    extern __shared__ uint32_t dyn[];
    uint32_t* AsB = dyn;                  // GST * STAGE_W words
    uint32_t* BsB = dyn + GST * STAGE_W;  // GST * STAGE_W words
    float*    red = (float*)(dyn + 2 * GST * STAGE_W);  // 128*4 floats

    const int tid  = threadIdx.x;
    const int warp = tid >> 5, lane = tid & 31;
    const int gid  = lane >> 2, tg = lane & 3;
    const int wm   = warp & 1;       // 0..1  -> 64-row slab
    const int wn   = warp >> 1;      // 0..3  -> 32-col slab

    const int lr = tid >> 2;         // 0..63  (loader row)
    const int lc = tid & 3;          // chunk 0..3 (8 halves each)

    uint32_t sA = (uint32_t)__cvta_generic_to_shared(AsB);
    uint32_t sB = (uint32_t)__cvta_generic_to_shared(BsB);

    auto issue = [&](int s, int k0) {   // k0 in halves
        #pragma unroll
        for (int r = 0; r < 2; r++) {
            int row = lr + r * 64;
            int sw  = (row >> 1) & 3;
            uint32_t off = (uint32_t)(s * BM * 16 + row * 16 + ((lc ^ sw) << 2)) * 4u;
            const __half* gA = A + (size_t)(bm + row) * Cc + k0 + lc * 8;
            asm volatile("cp.async.cg.shared.global [%0], [%1], 16;\n"
                         :: "r"(sA + off), "l"(gA));
            const __half* gB = W + (size_t)(bn + row) * Cc + k0 + lc * 8;
            asm volatile("cp.async.cg.shared.global [%0], [%1], 16;\n"
                         :: "r"(sB + off), "l"(gB));
        }
        asm volatile("cp.async.commit_group;\n");
    };

    float acc[4][4][4] = {};

    issue(0, 0);
    issue(1, KH);
    issue(2, 2 * KH);

    int s = 0;
    for (int i = 0; i < KCH; i++) {
        if (i < KCH - 2)       asm volatile("cp.async.wait_group 2;\n" ::: "memory");
        else if (i == KCH - 2) asm volatile("cp.async.wait_group 1;\n" ::: "memory");
        else                   asm volatile("cp.async.wait_group 0;\n" ::: "memory");
        __syncthreads();

        if (i + 3 < KCH) {
            int s2 = s + 3; if (s2 >= GST) s2 -= GST;
            issue(s2, (i + 3) * KH);
        }

        const uint32_t* Ab = &AsB[s * STAGE_W];
        const uint32_t* Bb = &BsB[s * STAGE_W];

        // Fragment hoist: load ALL fragments for the stage, then all MMAs.
        // half = one k16 group: chunks (c0, c0+1). m16n8k16 fragment layout:
        // a0={row gid, k 2tg..2tg+1}, a1={row gid+8, same}, a2/a3 = +8 k.
        uint32_t af[2][4][4], bf[2][4][2];
        #pragma unroll
        for (int half = 0; half < 2; half++) {
            const int c0 = half * 2;
            #pragma unroll
            for (int mt = 0; mt < 4; mt++) {
                int row = wm * 64 + mt * 16 + gid;
                int sw  = (row >> 1) & 3;
                int b0i = row * 16 + tg;
                int b1i = (row + 8) * 16 + tg;
                af[half][mt][0] = Ab[b0i + ((c0 ^ sw) << 2)];
                af[half][mt][1] = Ab[b1i + ((c0 ^ sw) << 2)];
                af[half][mt][2] = Ab[b0i + (((c0 + 1) ^ sw) << 2)];
                af[half][mt][3] = Ab[b1i + (((c0 + 1) ^ sw) << 2)];
            }
            #pragma unroll
            for (int nt = 0; nt < 4; nt++) {
                int col = wn * 32 + nt * 8 + gid;
                int sw  = (col >> 1) & 3;
                int bi  = col * 16 + tg;
                bf[half][nt][0] = Bb[bi + ((c0 ^ sw) << 2)];
                bf[half][nt][1] = Bb[bi + (((c0 + 1) ^ sw) << 2)];
            }
        }
        #pragma unroll
        for (int half = 0; half < 2; half++)
            #pragma unroll
            for (int mt = 0; mt < 4; mt++)
                #pragma unroll
                for (int nt = 0; nt < 4; nt++)
                    mma_f16(acc[mt][nt][0], acc[mt][nt][1], acc[mt][nt][2], acc[mt][nt][3],
                            af[half][mt][0], af[half][mt][1], af[half][mt][2], af[half][mt][3],
                            bf[half][nt][0], bf[half][nt][1]);
        s++; if (s >= GST) s = 0;
    }

    // ---- fused l2norm over the 128-col tile (mode 2, tile == one head) -----
    if (mode == 2) {
        __syncthreads();
        float invLo[4], invHi[4];
        #pragma unroll
        for (int mt = 0; mt < 4; mt++) {
            float slo = 0.0f, shi = 0.0f;
            #pragma unroll
            for (int nt = 0; nt < 4; nt++) {
                slo = fmaf(acc[mt][nt][0], acc[mt][nt][0], slo);
                slo = fmaf(acc[mt][nt][1], acc[mt][nt][1], slo);
                shi = fmaf(acc[mt][nt][2], acc[mt][nt][2], shi);
                shi = fmaf(acc[mt][nt][3], acc[mt][nt][3], shi);
            }
            slo += __shfl_xor_sync(0xffffffffu, slo, 1);
            slo += __shfl_xor_sync(0xffffffffu, slo, 2);
            shi += __shfl_xor_sync(0xffffffffu, shi, 1);
            shi += __shfl_xor_sync(0xffffffffu, shi, 2);
            if (tg == 0) {
                int r = wm * 64 + mt * 16 + gid;
                red[r * 4 + wn]       = slo;
                red[(r + 8) * 4 + wn] = shi;
            }
        }
        __syncthreads();
        #pragma unroll
        for (int mt = 0; mt < 4; mt++) {
            int r = wm * 64 + mt * 16 + gid;
            float slo = red[r * 4 + 0] + red[r * 4 + 1] + red[r * 4 + 2] + red[r * 4 + 3];
            float shi = red[(r + 8) * 4 + 0] + red[(r + 8) * 4 + 1]
                      + red[(r + 8) * 4 + 2] + red[(r + 8) * 4 + 3];
            invLo[mt] = 1.0f / fmaxf(sqrtf(slo), 1e-12f);
            invHi[mt] = 1.0f / fmaxf(sqrtf(shi), 1e-12f);
        }
        #pragma unroll
        for (int mt = 0; mt < 4; mt++)
            #pragma unroll
            for (int nt = 0; nt < 4; nt++) {
                acc[mt][nt][0] *= invLo[mt];
                acc[mt][nt][1] *= invLo[mt];
                acc[mt][nt][2] *= invHi[mt];
                acc[mt][nt][3] *= invHi[mt];
            }
    }

    // epilogue stores (fp32)
    #pragma unroll
    for (int mt = 0; mt < 4; mt++) {
        #pragma unroll
        for (int nt = 0; nt < 4; nt++) {
            int row = bm + wm * 64 + mt * 16 + gid;
            int col = bn + wn * 32 + nt * 8 + tg * 2;
            float v0 = acc[mt][nt][0], v1 = acc[mt][nt][1];
            float v2 = acc[mt][nt][2], v3 = acc[mt][nt][3];
            if (mode == 1) {
                float b0 = bias[col], b1 = bias[col + 1];
                v0 = 1.0f / (1.0f + expf(-(v0 + b0)));
                v1 = 1.0f / (1.0f + expf(-(v1 + b1)));
                v2 = 1.0f / (1.0f + expf(-(v2 + b0)));
                v3 = 1.0f / (1.0f + expf(-(v3 + b1)));
            }
            *reinterpret_cast<float2*>(&Out[(size_t)row * N + col])       = make_float2(v0, v1);
            *reinterpret_cast<float2*>(&Out[(size_t)(row + 8) * N + col]) = make_float2(v2, v3);
        }
    }
}

// Combined q/k/v/gate projection: one launch, 64 column-tiles x 128 row-tiles.
// seg = blockIdx.x>>4: 0=q(mode2) 1=k(mode2) 2=v(mode0) 3=gate(mode1, A=xconv)
__global__ __launch_bounds__(256, 2)
void gemm_qkvg_kernel(const float* __restrict__ gate_b) {
    const int seg = blockIdx.x >> 4;
    const int bn  = (blockIdx.x & 15) * 128;
    const int bm  = blockIdx.y * 128;

    const __half* A;
    const __half* W;
    float* Out;
    int mode;
    switch (seg) {
        case 0:  A = g_xt;    W = g_Wqt; Out = g_q;    mode = 2; break;
        case 1:  A = g_xt;    W = g_Wkt; Out = g_k;    mode = 2; break;
        case 2:  A = g_xt;    W = g_Wvt; Out = g_v;    mode = 0; break;
        default: A = g_xconv; W = g_Wgt; Out = g_gate; mode = 1; break;
    }
    gemm_tile_body(A, W, Out, gate_b, mode, bm, bn);
}

// Output projection: y = att * Wo^T (mode 0)
__global__ __launch_bounds__(256, 2)
void gemm_out_kernel() {
    gemm_tile_body(g_att, g_Wot, g_y, nullptr, 0, blockIdx.y * 128, blockIdx.x * 128);
}

// ---------------- 4) chunked decayed scan (float4, warp-per-chunk) ----------
__global__ void scan_pass1(const float* __restrict__ k, const float* __restrict__ v,
                           const float* __restrict__ gamma) {
    int wid  = threadIdx.x >> 5, lane = threadIdx.x & 31;
    int blk  = blockIdx.x * 4 + wid;          // 0..4095
    int c    = blk & (NCHUNK - 1);
    int bh   = blk >> 6;
    int h    = bh & (Hh - 1);
    int b    = bh >> 4;
    float g  = gamma[h];
    const float4* k4 = reinterpret_cast<const float4*>(k);
    const float4* v4 = reinterpret_cast<const float4*>(v);
    size_t idx = ((size_t)(b * Tt + c * LCH) * Cc + h * DhD) / 4 + lane;
    float4 S = make_float4(0.f, 0.f, 0.f, 0.f);
    #pragma unroll 4
    for (int i = 0; i < LCH; i++) {
        float4 kk = k4[idx], vv = v4[idx];
        S.x = fmaf(g, S.x, kk.x * vv.x);
        S.y = fmaf(g, S.y, kk.y * vv.y);
        S.z = fmaf(g, S.z, kk.z * vv.z);
        S.w = fmaf(g, S.w, kk.w * vv.w);
        idx += Cc / 4;
    }
    reinterpret_cast<float4*>(g_F)[((size_t)bh * NCHUNK + c) * (DhD / 4) + lane] = S;
}

__global__ void scan_pass2(const float* __restrict__ gamma) {
    int tid = blockIdx.x * blockDim.x + threadIdx.x;   // over Bb*Hh*DhD/4 = 2048
    int d4  = tid & (DhD / 4 - 1);
    int bh  = tid >> 5;
    int h   = bh & (Hh - 1);
    float g  = gamma[h];
    float gL = powf(g, (float)LCH);     // exact 1.0 for gamma=1 head
    const float4* F4 = reinterpret_cast<const float4*>(g_F);
    float4* C4       = reinterpret_cast<float4*>(g_carry);
    float4 carry = make_float4(0.f, 0.f, 0.f, 0.f);
    for (int c = 0; c < NCHUNK; c++) {
        size_t o = ((size_t)bh * NCHUNK + c) * (DhD / 4) + d4;
        C4[o] = carry;
        float4 f = F4[o];
        carry.x = fmaf(gL, carry.x, f.x);
        carry.y = fmaf(gL, carry.y, f.y);
        carry.z = fmaf(gL, carry.z, f.z);
        carry.w = fmaf(gL, carry.w, f.w);
    }
}

__global__ void scan_pass3(const float* __restrict__ k, const float* __restrict__ v,
                           const float* __restrict__ q, const float* __restrict__ gate,
                           const float* __restrict__ gamma) {
    int wid  = threadIdx.x >> 5, lane = threadIdx.x & 31;
    int blk  = blockIdx.x * 4 + wid;
    int c    = blk & (NCHUNK - 1);
    int bh   = blk >> 6;
    int h    = bh & (Hh - 1);
    int b    = bh >> 4;
    float g  = gamma[h];
    const float4* k4 = reinterpret_cast<const float4*>(k);
    const float4* v4 = reinterpret_cast<const float4*>(v);
    const float4* q4 = reinterpret_cast<const float4*>(q);
    const float4* g4 = reinterpret_cast<const float4*>(gate);
    uint2* a2        = reinterpret_cast<uint2*>(g_att);   // 4 halves per slot
    float4 S = reinterpret_cast<const float4*>(g_carry)
                   [((size_t)bh * NCHUNK + c) * (DhD / 4) + lane];
    size_t idx = ((size_t)(b * Tt + c * LCH) * Cc + h * DhD) / 4 + lane;
    #pragma unroll 4
    for (int i = 0; i < LCH; i++) {
        float4 kk = k4[idx], vv = v4[idx];
        S.x = fmaf(g, S.x, kk.x * vv.x);
        S.y = fmaf(g, S.y, kk.y * vv.y);
        S.z = fmaf(g, S.z, kk.z * vv.z);
        S.w = fmaf(g, S.w, kk.w * vv.w);
        float4 gg = g4[idx], qq = q4[idx];
        uint2 o;
        o.x = pack_h2(gg.x * S.x * qq.x, gg.y * S.y * qq.y);
        o.y = pack_h2(gg.z * S.z * qq.z, gg.w * S.w * qq.w);
        a2[idx] = o;
        idx += Cc / 4;
    }
}

// ---------------- 5) LayerNorm over C=2048 ---------------------------------
__global__ __launch_bounds__(256)
void ln_kernel(const float* __restrict__ y, const float* __restrict__ lw,
               const float* __restrict__ lb, float* __restrict__ out) {
    int row = blockIdx.x;
    int tid = threadIdx.x;
    const float4* yr = reinterpret_cast<const float4*>(y + (size_t)row * Cc);
    float4* orow     = reinterpret_cast<float4*>(out + (size_t)row * Cc);

    float4 v0 = yr[tid];
    float4 v1 = yr[tid + 256];
    float sum = v0.x + v0.y + v0.z + v0.w + v1.x + v1.y + v1.z + v1.w;
    float sq  = v0.x * v0.x + v0.y * v0.y + v0.z * v0.z + v0.w * v0.w
              + v1.x * v1.x + v1.y * v1.y + v1.z * v1.z + v1.w * v1.w;

    #pragma unroll
    for (int o = 16; o; o >>= 1) {
        sum += __shfl_xor_sync(0xffffffffu, sum, o);
        sq  += __shfl_xor_sync(0xffffffffu, sq, o);
    }
    __shared__ float ssum[8], ssq[8];
    __shared__ float s_mu, s_inv;
    int warp = tid >> 5, lane = tid & 31;
    if (lane == 0) { ssum[warp] = sum; ssq[warp] = sq; }
    __syncthreads();
    if (tid == 0) {
        float ts = 0.0f, tq = 0.0f;
        #pragma unroll
        for (int i = 0; i < 8; i++) { ts += ssum[i]; tq += ssq[i]; }
        float mu  = ts / (float)Cc;
        float var = tq / (float)Cc - mu * mu;
        s_mu  = mu;
        s_inv = rsqrtf(var + 1e-5f);
    }
    __syncthreads();
    float mu = s_mu, inv = s_inv;

    const float4 w0 = reinterpret_cast<const float4*>(lw)[tid];
    const float4 w1 = reinterpret_cast<const float4*>(lw)[tid + 256];
    const float4 b0 = reinterpret_cast<const float4*>(lb)[tid];
    const float4 b1 = reinterpret_cast<const float4*>(lb)[tid + 256];

    float4 o0, o1;
    o0.x = (v0.x - mu) * inv * w0.x + b0.x;
    o0.y = (v0.y - mu) * inv * w0.y + b0.y;
    o0.z = (v0.z - mu) * inv * w0.z + b0.z;
    o0.w = (v0.w - mu) * inv * w0.w + b0.w;
    o1.x = (v1.x - mu) * inv * w1.x + b1.x;
    o1.y = (v1.y - mu) * inv * w1.y + b1.y;
    o1.z = (v1.z - mu) * inv * w1.z + b1.z;
    o1.w = (v1.w - mu) * inv * w1.w + b1.w;
    orow[tid]       = o0;
    orow[tid + 256] = o1;
}

// ---------------- host orchestration ---------------------------------------
extern "C" void kernel_launch(void* const* d_in, const int* in_sizes, int n_in,
                              void* d_out, int out_size) {
    (void)in_sizes; (void)n_in; (void)out_size;
    const float* x      = (const float*)d_in[0];
    const float* Wq     = (const float*)d_in[1];
    const float* Wk     = (const float*)d_in[2];
    const float* Wv     = (const float*)d_in[3];
    const float* Wo     = (const float*)d_in[4];
    const float* conv_w = (const float*)d_in[5];
    const float* conv_b = (const float*)d_in[6];
    const float* gate_w = (const float*)d_in[7];
    const float* gate_b = (const float*)d_in[8];
    const float* ln_w   = (const float*)d_in[9];
    const float* ln_b   = (const float*)d_in[10];
    const float* gamma  = (const float*)d_in[11];

    float *p_q, *p_k, *p_v, *p_gate, *p_y;
    __half *p_Wqt, *p_Wkt, *p_Wvt, *p_Wot, *p_Wgt;
    cudaGetSymbolAddress((void**)&p_q, g_q);
    cudaGetSymbolAddress((void**)&p_k, g_k);
    cudaGetSymbolAddress((void**)&p_v, g_v);
    cudaGetSymbolAddress((void**)&p_gate, g_gate);
    cudaGetSymbolAddress((void**)&p_y, g_y);
    cudaGetSymbolAddress((void**)&p_Wqt, g_Wqt);
    cudaGetSymbolAddress((void**)&p_Wkt, g_Wkt);
    cudaGetSymbolAddress((void**)&p_Wvt, g_Wvt);
    cudaGetSymbolAddress((void**)&p_Wot, g_Wot);
    cudaGetSymbolAddress((void**)&p_Wgt, g_Wgt);

    // allow 66KB dynamic smem on the GEMM kernels (idempotent)
    cudaFuncSetAttribute(gemm_qkvg_kernel, cudaFuncAttributeMaxDynamicSharedMemorySize, GEMM_SMEM);
    cudaFuncSetAttribute(gemm_out_kernel,  cudaFuncAttributeMaxDynamicSharedMemorySize, GEMM_SMEM);

    // 0) convert the 5 weight matrices to fp16 in one launch
    const int wBlocks = (Cc * Cc) / 2048;  // 2048 blocks per weight
    cvt5_f16_kernel<<<5 * wBlocks, 256>>>(Wq, p_Wqt, Wk, p_Wkt, Wv, p_Wvt,
                                          Wo, p_Wot, gate_w, p_Wgt);

    // 1) depthwise conv + SiLU (float4); also emits fp16 x (g_xt)
    conv_silu_kernel<<<(Mrows * Cc / 4) / 256, 256>>>(x, conv_w, conv_b);

    // 2) all four projections in ONE launch (q, k, v, gate)
    dim3 qgrid(64, Mrows / 128);   // 64 col-tiles (4 segs x 16), 128 row-tiles
    gemm_qkvg_kernel<<<qgrid, 256, GEMM_SMEM>>>(gate_b);

    // 3) decayed scan (chunked, exact); q/k already l2-normalized in epilogue
    scan_pass1<<<Bb * Hh * NCHUNK / 4, 128>>>(p_k, p_v, gamma);
    scan_pass2<<<16, 128>>>(gamma);
    scan_pass3<<<Bb * Hh * NCHUNK / 4, 128>>>(p_k, p_v, p_q, p_gate, gamma);

    // 4) output projection + LayerNorm
    dim3 ogrid(Cc / 128, Mrows / 128);   // (16, 128)
    gemm_out_kernel<<<ogrid, 256, GEMM_SMEM>>>();
    ln_kernel<<<Mrows, 256>>>(p_y, ln_w, ln_b, (float*)d_out);
}

// round 13
// speedup vs baseline: 3.8879x; 1.0647x over previous
#include <cuda_runtime.h>
#include <cuda_fp16.h>
#include <cstdint>
#include <cstdio>

// Problem constants
namespace {
constexpr int Bb = 4, Tt = 4096, Cc = 2048, Hh = 16, DhD = 128;
constexpr int Mrows = Bb * Tt;            // 16384
constexpr int NCHUNK = 64;                // scan chunks
constexpr int LCH = Tt / NCHUNK;          // 64 steps per chunk
// GEMM pipeline: 4 stages, prefetch distance 3. One stage row = 16 b32 words
// = 32 fp16 halves of K. 64 mainloop iterations cover K=2048.
constexpr int GST = 4;
constexpr int STAGE_W = 128 * 16;         // 2048 words per (matrix,stage)
constexpr int GEMM_SMEM = 2 * GST * STAGE_W * 4 + 128 * 4 * 4;  // 67584 B
}

// ---------------- scratch (static device globals; no allocation allowed) ---
__device__ __half g_xconv[(size_t)Bb * Tt * Cc];
__device__ float  g_q   [(size_t)Bb * Tt * Cc];
__device__ float  g_k   [(size_t)Bb * Tt * Cc];
__device__ float  g_v   [(size_t)Bb * Tt * Cc];
__device__ float  g_gate[(size_t)Bb * Tt * Cc];
__device__ __half g_att [(size_t)Bb * Tt * Cc];
__device__ float  g_y   [(size_t)Bb * Tt * Cc];
__device__ __half g_xt  [(size_t)Bb * Tt * Cc];      // fp16-rounded x
__device__ __half g_Wqt [(size_t)Cc * Cc];
__device__ __half g_Wkt [(size_t)Cc * Cc];
__device__ __half g_Wvt [(size_t)Cc * Cc];
__device__ __half g_Wot [(size_t)Cc * Cc];
__device__ __half g_Wgt [(size_t)Cc * Cc];
__device__ float  g_F    [(size_t)Bb * Hh * NCHUNK * DhD];
__device__ float  g_carry[(size_t)Bb * Hh * NCHUNK * DhD];

// ---------------- helpers --------------------------------------------------
__device__ __forceinline__ uint32_t pack_h2(float a, float b) {
    __half2 h = __floats2half2_rn(a, b);
    return *reinterpret_cast<uint32_t*>(&h);
}

__device__ __forceinline__ void mma_f16(float& d0, float& d1, float& d2, float& d3,
                                        uint32_t a0, uint32_t a1, uint32_t a2, uint32_t a3,
                                        uint32_t b0, uint32_t b1) {
    asm volatile(
        "mma.sync.aligned.m16n8k16.row.col.f32.f16.f16.f32 "
        "{%0,%1,%2,%3}, {%4,%5,%6,%7}, {%8,%9}, {%0,%1,%2,%3};\n"
        : "+f"(d0), "+f"(d1), "+f"(d2), "+f"(d3)
        : "r"(a0), "r"(a1), "r"(a2), "r"(a3), "r"(b0), "r"(b1));
}

#define LDMATRIX_X4(r0, r1, r2, r3, addr) \
    asm volatile("ldmatrix.sync.aligned.m8n8.x4.shared.b16 {%0,%1,%2,%3}, [%4];" \
                 : "=r"(r0), "=r"(r1), "=r"(r2), "=r"(r3) : "r"(addr))

// ---------------- 0) fp16 conversion of the 5 weight matrices (one launch) --
__global__ void cvt5_f16_kernel(const float* __restrict__ w0, __half* __restrict__ o0,
                                const float* __restrict__ w1, __half* __restrict__ o1,
                                const float* __restrict__ w2, __half* __restrict__ o2,
                                const float* __restrict__ w3, __half* __restrict__ o3,
                                const float* __restrict__ w4, __half* __restrict__ o4) {
    const int seg = blockIdx.x >> 11;                 // 2048 blocks per weight
    const int i   = (blockIdx.x & 2047) * 256 + threadIdx.x;  // 8-elem group idx
    const float* in;
    __half* out;
    switch (seg) {
        case 0: in = w0; out = o0; break;
        case 1: in = w1; out = o1; break;
        case 2: in = w2; out = o2; break;
        case 3: in = w3; out = o3; break;
        default: in = w4; out = o4; break;
    }
    float4 v0 = reinterpret_cast<const float4*>(in)[i * 2];
    float4 v1 = reinterpret_cast<const float4*>(in)[i * 2 + 1];
    uint4 pk;
    pk.x = pack_h2(v0.x, v0.y);
    pk.y = pack_h2(v0.z, v0.w);
    pk.z = pack_h2(v1.x, v1.y);
    pk.w = pack_h2(v1.z, v1.w);
    reinterpret_cast<uint4*>(out)[i] = pk;
}

// ---------------- 1) causal depthwise conv (K=4) + SiLU + x fp16 side-out ---
__global__ void conv_silu_kernel(const float* __restrict__ x,
                                 const float* __restrict__ w,
                                 const float* __restrict__ bias) {
    int vid = blockIdx.x * blockDim.x + threadIdx.x;    // over B*T*C/4
    int cq  = vid & (Cc / 4 - 1);                       // channel quad
    int bt  = vid >> 9;                                 // /(2048/4)
    int t   = bt & (Tt - 1);
    int c   = cq * 4;

    const float4* x4 = reinterpret_cast<const float4*>(x);
    int base = (bt - t) * (Cc / 4) + cq;                // b*T*C/4 + cq

    float4 wr0 = reinterpret_cast<const float4*>(w)[c + 0];
    float4 wr1 = reinterpret_cast<const float4*>(w)[c + 1];
    float4 wr2 = reinterpret_cast<const float4*>(w)[c + 2];
    float4 wr3 = reinterpret_cast<const float4*>(w)[c + 3];
    float4 bb  = reinterpret_cast<const float4*>(bias)[cq];

    float4 a = bb;
    float4 xt3;
    #pragma unroll
    for (int j = 0; j < 4; j++) {
        int tt = t - 3 + j;
        if (tt >= 0) {
            float4 xv = x4[base + tt * (Cc / 4)];
            if (j == 3) xt3 = xv;
            float wj0 = (&wr0.x)[j], wj1 = (&wr1.x)[j], wj2 = (&wr2.x)[j], wj3 = (&wr3.x)[j];
            a.x = fmaf(xv.x, wj0, a.x);
            a.y = fmaf(xv.y, wj1, a.y);
            a.z = fmaf(xv.z, wj2, a.z);
            a.w = fmaf(xv.w, wj3, a.w);
        }
    }

    uint2 sc;
    sc.x = pack_h2(a.x / (1.0f + expf(-a.x)), a.y / (1.0f + expf(-a.y)));
    sc.y = pack_h2(a.z / (1.0f + expf(-a.z)), a.w / (1.0f + expf(-a.w)));
    reinterpret_cast<uint2*>(g_xconv)[vid] = sc;

    uint2 xr;
    xr.x = pack_h2(xt3.x, xt3.y);
    xr.y = pack_h2(xt3.z, xt3.w);
    reinterpret_cast<uint2*>(g_xt)[vid] = xr;
}

// ---------------- 2) FP16 GEMM tile body (4-stage pipeline, ldmatrix) -------
// Computes one 128x128 tile of Out = A[M,2048] * W[128-col slab]^T, fp16 in,
// fp32 accumulate. Stage row = 16 b32 words = 32 halves of K; 64 iterations.
// Fragment loads via ldmatrix.x4 — values identical to the scalar-LDS version.
// mode 0: plain.  mode 1: sigmoid(out + bias[col]).  mode 2: per-row l2norm.
// smem layout per (matrix,stage): 128 rows x 16 words, XOR-swizzled chunks:
//   word(row,w) at row*16 + (((w>>2) ^ ((row>>1)&3))<<2) + (w&3)
__device__ __forceinline__
void gemm_tile_body(const __half* __restrict__ A, const __half* __restrict__ W,
                    float* __restrict__ Out, const float* __restrict__ bias,
                    int mode, int bm, int bn) {
    constexpr int BM = 128;
    constexpr int KH = 32;                // K halves per stage
    constexpr int KCH = Cc / KH;          // 64 iterations
    constexpr int N = Cc;

    extern __shared__ uint32_t dyn[];
    uint32_t* AsB = dyn;                  // GST * STAGE_W words
    uint32_t* BsB = dyn + GST * STAGE_W;  // GST * STAGE_W words
    float*    red = (float*)(dyn + 2 * GST * STAGE_W);  // 128*4 floats

    const int tid  = threadIdx.x;
    const int warp = tid >> 5, lane = tid & 31;
    const int gid  = lane >> 2, tg = lane & 3;
    const int wm   = warp & 1;       // 0..1  -> 64-row slab
    const int wn   = warp >> 1;      // 0..3  -> 32-col slab

    const int lr = tid >> 2;         // 0..63  (loader row)
    const int lc = tid & 3;          // chunk 0..3 (8 halves each)

    uint32_t sA = (uint32_t)__cvta_generic_to_shared(AsB);
    uint32_t sB = (uint32_t)__cvta_generic_to_shared(BsB);

    // ---- per-lane ldmatrix byte offsets within a stage (loop-invariant) ----
    const int lq  = lane >> 3;       // matrix quad 0..3
    const int lr8 = lane & 7;
    uint32_t aoff[2][4];             // [half][mt]
    uint32_t boff[2][2];             // [half][ntp]
    #pragma unroll
    for (int half = 0; half < 2; half++) {
        #pragma unroll
        for (int mt = 0; mt < 4; mt++) {
            int row   = wm * 64 + mt * 16 + (lq & 1) * 8 + lr8;
            int sw    = (row >> 1) & 3;
            int chunk = half * 2 + (lq >> 1);
            aoff[half][mt] = (uint32_t)(row * 64 + ((chunk ^ sw) << 4));
        }
        #pragma unroll
        for (int ntp = 0; ntp < 2; ntp++) {
            int col   = wn * 32 + (2 * ntp + (lq >> 1)) * 8 + lr8;
            int sw    = (col >> 1) & 3;
            int chunk = half * 2 + (lq & 1);
            boff[half][ntp] = (uint32_t)(col * 64 + ((chunk ^ sw) << 4));
        }
    }

    auto issue = [&](int s, int k0) {   // k0 in halves
        #pragma unroll
        for (int r = 0; r < 2; r++) {
            int row = lr + r * 64;
            int sw  = (row >> 1) & 3;
            uint32_t off = (uint32_t)(s * BM * 16 + row * 16 + ((lc ^ sw) << 2)) * 4u;
            const __half* gA = A + (size_t)(bm + row) * Cc + k0 + lc * 8;
            asm volatile("cp.async.cg.shared.global [%0], [%1], 16;\n"
                         :: "r"(sA + off), "l"(gA));
            const __half* gB = W + (size_t)(bn + row) * Cc + k0 + lc * 8;
            asm volatile("cp.async.cg.shared.global [%0], [%1], 16;\n"
                         :: "r"(sB + off), "l"(gB));
        }
        asm volatile("cp.async.commit_group;\n");
    };

    float acc[4][4][4] = {};

    issue(0, 0);
    issue(1, KH);
    issue(2, 2 * KH);

    int s = 0;
    for (int i = 0; i < KCH; i++) {
        if (i < KCH - 2)       asm volatile("cp.async.wait_group 2;\n" ::: "memory");
        else if (i == KCH - 2) asm volatile("cp.async.wait_group 1;\n" ::: "memory");
        else                   asm volatile("cp.async.wait_group 0;\n" ::: "memory");
        __syncthreads();

        if (i + 3 < KCH) {
            int s2 = s + 3; if (s2 >= GST) s2 -= GST;
            issue(s2, (i + 3) * KH);
        }

        const uint32_t stA = sA + (uint32_t)(s * STAGE_W) * 4u;
        const uint32_t stB = sB + (uint32_t)(s * STAGE_W) * 4u;

        // Fragment loads: 8 A + 4 B ldmatrix.x4 per iteration.
        uint32_t af[2][4][4], bf[2][4][2];
        #pragma unroll
        for (int half = 0; half < 2; half++) {
            #pragma unroll
            for (int mt = 0; mt < 4; mt++)
                LDMATRIX_X4(af[half][mt][0], af[half][mt][1],
                            af[half][mt][2], af[half][mt][3],
                            stA + aoff[half][mt]);
            #pragma unroll
            for (int ntp = 0; ntp < 2; ntp++)
                LDMATRIX_X4(bf[half][2 * ntp][0],     bf[half][2 * ntp][1],
                            bf[half][2 * ntp + 1][0], bf[half][2 * ntp + 1][1],
                            stB + boff[half][ntp]);
        }
        #pragma unroll
        for (int half = 0; half < 2; half++)
            #pragma unroll
            for (int mt = 0; mt < 4; mt++)
                #pragma unroll
                for (int nt = 0; nt < 4; nt++)
                    mma_f16(acc[mt][nt][0], acc[mt][nt][1], acc[mt][nt][2], acc[mt][nt][3],
                            af[half][mt][0], af[half][mt][1], af[half][mt][2], af[half][mt][3],
                            bf[half][nt][0], bf[half][nt][1]);
        s++; if (s >= GST) s = 0;
    }

    // ---- fused l2norm over the 128-col tile (mode 2, tile == one head) -----
    if (mode == 2) {
        __syncthreads();
        float invLo[4], invHi[4];
        #pragma unroll
        for (int mt = 0; mt < 4; mt++) {
            float slo = 0.0f, shi = 0.0f;
            #pragma unroll
            for (int nt = 0; nt < 4; nt++) {
                slo = fmaf(acc[mt][nt][0], acc[mt][nt][0], slo);
                slo = fmaf(acc[mt][nt][1], acc[mt][nt][1], slo);
                shi = fmaf(acc[mt][nt][2], acc[mt][nt][2], shi);
                shi = fmaf(acc[mt][nt][3], acc[mt][nt][3], shi);
            }
            slo += __shfl_xor_sync(0xffffffffu, slo, 1);
            slo += __shfl_xor_sync(0xffffffffu, slo, 2);
            shi += __shfl_xor_sync(0xffffffffu, shi, 1);
            shi += __shfl_xor_sync(0xffffffffu, shi, 2);
            if (tg == 0) {
                int r = wm * 64 + mt * 16 + gid;
                red[r * 4 + wn]       = slo;
                red[(r + 8) * 4 + wn] = shi;
            }
        }
        __syncthreads();
        #pragma unroll
        for (int mt = 0; mt < 4; mt++) {
            int r = wm * 64 + mt * 16 + gid;
            float slo = red[r * 4 + 0] + red[r * 4 + 1] + red[r * 4 + 2] + red[r * 4 + 3];
            float shi = red[(r + 8) * 4 + 0] + red[(r + 8) * 4 + 1]
                      + red[(r + 8) * 4 + 2] + red[(r + 8) * 4 + 3];
            invLo[mt] = 1.0f / fmaxf(sqrtf(slo), 1e-12f);
            invHi[mt] = 1.0f / fmaxf(sqrtf(shi), 1e-12f);
        }
        #pragma unroll
        for (int mt = 0; mt < 4; mt++)
            #pragma unroll
            for (int nt = 0; nt < 4; nt++) {
                acc[mt][nt][0] *= invLo[mt];
                acc[mt][nt][1] *= invLo[mt];
                acc[mt][nt][2] *= invHi[mt];
                acc[mt][nt][3] *= invHi[mt];
            }
    }

    // epilogue stores (fp32)
    #pragma unroll
    for (int mt = 0; mt < 4; mt++) {
        #pragma unroll
        for (int nt = 0; nt < 4; nt++) {
            int row = bm + wm * 64 + mt * 16 + gid;
            int col = bn + wn * 32 + nt * 8 + tg * 2;
            float v0 = acc[mt][nt][0], v1 = acc[mt][nt][1];
            float v2 = acc[mt][nt][2], v3 = acc[mt][nt][3];
            if (mode == 1) {
                float b0 = bias[col], b1 = bias[col + 1];
                v0 = 1.0f / (1.0f + expf(-(v0 + b0)));
                v1 = 1.0f / (1.0f + expf(-(v1 + b1)));
                v2 = 1.0f / (1.0f + expf(-(v2 + b0)));
                v3 = 1.0f / (1.0f + expf(-(v3 + b1)));
            }
            *reinterpret_cast<float2*>(&Out[(size_t)row * N + col])       = make_float2(v0, v1);
            *reinterpret_cast<float2*>(&Out[(size_t)(row + 8) * N + col]) = make_float2(v2, v3);
        }
    }
}

// Combined q/k/v/gate projection: one launch, 64 column-tiles x 128 row-tiles.
// seg = blockIdx.x>>4: 0=q(mode2) 1=k(mode2) 2=v(mode0) 3=gate(mode1, A=xconv)
__global__ __launch_bounds__(256, 2)
void gemm_qkvg_kernel(const float* __restrict__ gate_b) {
    const int seg = blockIdx.x >> 4;
    const int bn  = (blockIdx.x & 15) * 128;
    const int bm  = blockIdx.y * 128;

    const __half* A;
    const __half* W;
    float* Out;
    int mode;
    switch (seg) {
        case 0:  A = g_xt;    W = g_Wqt; Out = g_q;    mode = 2; break;
        case 1:  A = g_xt;    W = g_Wkt; Out = g_k;    mode = 2; break;
        case 2:  A = g_xt;    W = g_Wvt; Out = g_v;    mode = 0; break;
        default: A = g_xconv; W = g_Wgt; Out = g_gate; mode = 1; break;
    }
    gemm_tile_body(A, W, Out, gate_b, mode, bm, bn);
}

// Output projection: y = att * Wo^T (mode 0)
__global__ __launch_bounds__(256, 2)
void gemm_out_kernel() {
    gemm_tile_body(g_att, g_Wot, g_y, nullptr, 0, blockIdx.y * 128, blockIdx.x * 128);
}

// ---------------- 4) chunked decayed scan (float4, warp-per-chunk) ----------
__global__ void scan_pass1(const float* __restrict__ k, const float* __restrict__ v,
                           const float* __restrict__ gamma) {
    int wid  = threadIdx.x >> 5, lane = threadIdx.x & 31;
    int blk  = blockIdx.x * 4 + wid;          // 0..4095
    int c    = blk & (NCHUNK - 1);
    int bh   = blk >> 6;
    int h    = bh & (Hh - 1);
    int b    = bh >> 4;
    float g  = gamma[h];
    const float4* k4 = reinterpret_cast<const float4*>(k);
    const float4* v4 = reinterpret_cast<const float4*>(v);
    size_t idx = ((size_t)(b * Tt + c * LCH) * Cc + h * DhD) / 4 + lane;
    float4 S = make_float4(0.f, 0.f, 0.f, 0.f);
    #pragma unroll 4
    for (int i = 0; i < LCH; i++) {
        float4 kk = k4[idx], vv = v4[idx];
        S.x = fmaf(g, S.x, kk.x * vv.x);
        S.y = fmaf(g, S.y, kk.y * vv.y);
        S.z = fmaf(g, S.z, kk.z * vv.z);
        S.w = fmaf(g, S.w, kk.w * vv.w);
        idx += Cc / 4;
    }
    reinterpret_cast<float4*>(g_F)[((size_t)bh * NCHUNK + c) * (DhD / 4) + lane] = S;
}

__global__ void scan_pass2(const float* __restrict__ gamma) {
    int tid = blockIdx.x * blockDim.x + threadIdx.x;   // over Bb*Hh*DhD/4 = 2048
    int d4  = tid & (DhD / 4 - 1);
    int bh  = tid >> 5;
    int h   = bh & (Hh - 1);
    float g  = gamma[h];
    float gL = powf(g, (float)LCH);     // exact 1.0 for gamma=1 head
    const float4* F4 = reinterpret_cast<const float4*>(g_F);
    float4* C4       = reinterpret_cast<float4*>(g_carry);
    float4 carry = make_float4(0.f, 0.f, 0.f, 0.f);
    for (int c = 0; c < NCHUNK; c++) {
        size_t o = ((size_t)bh * NCHUNK + c) * (DhD / 4) + d4;
        C4[o] = carry;
        float4 f = F4[o];
        carry.x = fmaf(gL, carry.x, f.x);
        carry.y = fmaf(gL, carry.y, f.y);
        carry.z = fmaf(gL, carry.z, f.z);
        carry.w = fmaf(gL, carry.w, f.w);
    }
}

__global__ void scan_pass3(const float* __restrict__ k, const float* __restrict__ v,
                           const float* __restrict__ q, const float* __restrict__ gate,
                           const float* __restrict__ gamma) {
    int wid  = threadIdx.x >> 5, lane = threadIdx.x & 31;
    int blk  = blockIdx.x * 4 + wid;
    int c    = blk & (NCHUNK - 1);
    int bh   = blk >> 6;
    int h    = bh & (Hh - 1);
    int b    = bh >> 4;
    float g  = gamma[h];
    const float4* k4 = reinterpret_cast<const float4*>(k);
    const float4* v4 = reinterpret_cast<const float4*>(v);
    const float4* q4 = reinterpret_cast<const float4*>(q);
    const float4* g4 = reinterpret_cast<const float4*>(gate);
    uint2* a2        = reinterpret_cast<uint2*>(g_att);   // 4 halves per slot
    float4 S = reinterpret_cast<const float4*>(g_carry)
                   [((size_t)bh * NCHUNK + c) * (DhD / 4) + lane];
    size_t idx = ((size_t)(b * Tt + c * LCH) * Cc + h * DhD) / 4 + lane;
    #pragma unroll 4
    for (int i = 0; i < LCH; i++) {
        float4 kk = k4[idx], vv = v4[idx];
        S.x = fmaf(g, S.x, kk.x * vv.x);
        S.y = fmaf(g, S.y, kk.y * vv.y);
        S.z = fmaf(g, S.z, kk.z * vv.z);
        S.w = fmaf(g, S.w, kk.w * vv.w);
        float4 gg = g4[idx], qq = q4[idx];
        uint2 o;
        o.x = pack_h2(gg.x * S.x * qq.x, gg.y * S.y * qq.y);
        o.y = pack_h2(gg.z * S.z * qq.z, gg.w * S.w * qq.w);
        a2[idx] = o;
        idx += Cc / 4;
    }
}

// ---------------- 5) LayerNorm over C=2048 ---------------------------------
__global__ __launch_bounds__(256)
void ln_kernel(const float* __restrict__ y, const float* __restrict__ lw,
               const float* __restrict__ lb, float* __restrict__ out) {
    int row = blockIdx.x;
    int tid = threadIdx.x;
    const float4* yr = reinterpret_cast<const float4*>(y + (size_t)row * Cc);
    float4* orow     = reinterpret_cast<float4*>(out + (size_t)row * Cc);

    float4 v0 = yr[tid];
    float4 v1 = yr[tid + 256];
    float sum = v0.x + v0.y + v0.z + v0.w + v1.x + v1.y + v1.z + v1.w;
    float sq  = v0.x * v0.x + v0.y * v0.y + v0.z * v0.z + v0.w * v0.w
              + v1.x * v1.x + v1.y * v1.y + v1.z * v1.z + v1.w * v1.w;

    #pragma unroll
    for (int o = 16; o; o >>= 1) {
        sum += __shfl_xor_sync(0xffffffffu, sum, o);
        sq  += __shfl_xor_sync(0xffffffffu, sq, o);
    }
    __shared__ float ssum[8], ssq[8];
    __shared__ float s_mu, s_inv;
    int warp = tid >> 5, lane = tid & 31;
    if (lane == 0) { ssum[warp] = sum; ssq[warp] = sq; }
    __syncthreads();
    if (tid == 0) {
        float ts = 0.0f, tq = 0.0f;
        #pragma unroll
        for (int i = 0; i < 8; i++) { ts += ssum[i]; tq += ssq[i]; }
        float mu  = ts / (float)Cc;
        float var = tq / (float)Cc - mu * mu;
        s_mu  = mu;
        s_inv = rsqrtf(var + 1e-5f);
    }
    __syncthreads();
    float mu = s_mu, inv = s_inv;

    const float4 w0 = reinterpret_cast<const float4*>(lw)[tid];
    const float4 w1 = reinterpret_cast<const float4*>(lw)[tid + 256];
    const float4 b0 = reinterpret_cast<const float4*>(lb)[tid];
    const float4 b1 = reinterpret_cast<const float4*>(lb)[tid + 256];

    float4 o0, o1;
    o0.x = (v0.x - mu) * inv * w0.x + b0.x;
    o0.y = (v0.y - mu) * inv * w0.y + b0.y;
    o0.z = (v0.z - mu) * inv * w0.z + b0.z;
    o0.w = (v0.w - mu) * inv * w0.w + b0.w;
    o1.x = (v1.x - mu) * inv * w1.x + b1.x;
    o1.y = (v1.y - mu) * inv * w1.y + b1.y;
    o1.z = (v1.z - mu) * inv * w1.z + b1.z;
    o1.w = (v1.w - mu) * inv * w1.w + b1.w;
    orow[tid]       = o0;
    orow[tid + 256] = o1;
}

// ---------------- host orchestration ---------------------------------------
extern "C" void kernel_launch(void* const* d_in, const int* in_sizes, int n_in,
                              void* d_out, int out_size) {
    (void)in_sizes; (void)n_in; (void)out_size;
    const float* x      = (const float*)d_in[0];
    const float* Wq     = (const float*)d_in[1];
    const float* Wk     = (const float*)d_in[2];
    const float* Wv     = (const float*)d_in[3];
    const float* Wo     = (const float*)d_in[4];
    const float* conv_w = (const float*)d_in[5];
    const float* conv_b = (const float*)d_in[6];
    const float* gate_w = (const float*)d_in[7];
    const float* gate_b = (const float*)d_in[8];
    const float* ln_w   = (const float*)d_in[9];
    const float* ln_b   = (const float*)d_in[10];
    const float* gamma  = (const float*)d_in[11];

    float *p_q, *p_k, *p_v, *p_gate, *p_y;
    __half *p_Wqt, *p_Wkt, *p_Wvt, *p_Wot, *p_Wgt;
    cudaGetSymbolAddress((void**)&p_q, g_q);
    cudaGetSymbolAddress((void**)&p_k, g_k);
    cudaGetSymbolAddress((void**)&p_v, g_v);
    cudaGetSymbolAddress((void**)&p_gate, g_gate);
    cudaGetSymbolAddress((void**)&p_y, g_y);
    cudaGetSymbolAddress((void**)&p_Wqt, g_Wqt);
    cudaGetSymbolAddress((void**)&p_Wkt, g_Wkt);
    cudaGetSymbolAddress((void**)&p_Wvt, g_Wvt);
    cudaGetSymbolAddress((void**)&p_Wot, g_Wot);
    cudaGetSymbolAddress((void**)&p_Wgt, g_Wgt);

    // allow 66KB dynamic smem on the GEMM kernels (idempotent)
    cudaFuncSetAttribute(gemm_qkvg_kernel, cudaFuncAttributeMaxDynamicSharedMemorySize, GEMM_SMEM);
    cudaFuncSetAttribute(gemm_out_kernel,  cudaFuncAttributeMaxDynamicSharedMemorySize, GEMM_SMEM);

    // 0) convert the 5 weight matrices to fp16 in one launch
    const int wBlocks = (Cc * Cc) / 2048;  // 2048 blocks per weight
    cvt5_f16_kernel<<<5 * wBlocks, 256>>>(Wq, p_Wqt, Wk, p_Wkt, Wv, p_Wvt,
                                          Wo, p_Wot, gate_w, p_Wgt);

    // 1) depthwise conv + SiLU (float4); also emits fp16 x (g_xt)
    conv_silu_kernel<<<(Mrows * Cc / 4) / 256, 256>>>(x, conv_w, conv_b);

    // 2) all four projections in ONE launch (q, k, v, gate)
    dim3 qgrid(64, Mrows / 128);   // 64 col-tiles (4 segs x 16), 128 row-tiles
    gemm_qkvg_kernel<<<qgrid, 256, GEMM_SMEM>>>(gate_b);

    // 3) decayed scan (chunked, exact); q/k already l2-normalized in epilogue
    scan_pass1<<<Bb * Hh * NCHUNK / 4, 128>>>(p_k, p_v, gamma);
    scan_pass2<<<16, 128>>>(gamma);
    scan_pass3<<<Bb * Hh * NCHUNK / 4, 128>>>(p_k, p_v, p_q, p_gate, gamma);

    // 4) output projection + LayerNorm
    dim3 ogrid(Cc / 128, Mrows / 128);   // (16, 128)
    gemm_out_kernel<<<ogrid, 256, GEMM_SMEM>>>();
    ln_kernel<<<Mrows, 256>>>(p_y, ln_w, ln_b, (float*)d_out);
}

// round 14
// speedup vs baseline: 4.0653x; 1.0456x over previous
#include <cuda_runtime.h>
#include <cuda_fp16.h>
#include <cstdint>
#include <cstdio>

// Problem constants
namespace {
constexpr int Bb = 4, Tt = 4096, Cc = 2048, Hh = 16, DhD = 128;
constexpr int Mrows = Bb * Tt;            // 16384
constexpr int NCHUNK = 64;                // scan chunks
constexpr int LCH = Tt / NCHUNK;          // 64 steps per chunk
// GEMM pipeline: 4 stages, prefetch distance 3. One stage row = 16 b32 words
// = 32 fp16 halves of K. 64 mainloop iterations cover K=2048.
constexpr int GST = 4;
constexpr int STAGE_W = 128 * 16;         // 2048 words per (matrix,stage)
constexpr int GEMM_SMEM = 2 * GST * STAGE_W * 4 + 128 * 4 * 4;  // 67584 B
}

// ---------------- scratch (static device globals; no allocation allowed) ---
__device__ __half g_xconv[(size_t)Bb * Tt * Cc];
__device__ __half g_q   [(size_t)Bb * Tt * Cc];
__device__ __half g_k   [(size_t)Bb * Tt * Cc];
__device__ __half g_v   [(size_t)Bb * Tt * Cc];
__device__ __half g_gate[(size_t)Bb * Tt * Cc];
__device__ __half g_att [(size_t)Bb * Tt * Cc];
__device__ float  g_y   [(size_t)Bb * Tt * Cc];
__device__ __half g_xt  [(size_t)Bb * Tt * Cc];      // fp16-rounded x
__device__ __half g_Wqt [(size_t)Cc * Cc];
__device__ __half g_Wkt [(size_t)Cc * Cc];
__device__ __half g_Wvt [(size_t)Cc * Cc];
__device__ __half g_Wot [(size_t)Cc * Cc];
__device__ __half g_Wgt [(size_t)Cc * Cc];
__device__ float  g_F    [(size_t)Bb * Hh * NCHUNK * DhD];
__device__ float  g_carry[(size_t)Bb * Hh * NCHUNK * DhD];

// ---------------- helpers --------------------------------------------------
__device__ __forceinline__ uint32_t pack_h2(float a, float b) {
    __half2 h = __floats2half2_rn(a, b);
    return *reinterpret_cast<uint32_t*>(&h);
}
__device__ __forceinline__ float2 unpack_h2(uint32_t u) {
    return __half22float2(*reinterpret_cast<__half2*>(&u));
}

__device__ __forceinline__ void mma_f16(float& d0, float& d1, float& d2, float& d3,
                                        uint32_t a0, uint32_t a1, uint32_t a2, uint32_t a3,
                                        uint32_t b0, uint32_t b1) {
    asm volatile(
        "mma.sync.aligned.m16n8k16.row.col.f32.f16.f16.f32 "
        "{%0,%1,%2,%3}, {%4,%5,%6,%7}, {%8,%9}, {%0,%1,%2,%3};\n"
        : "+f"(d0), "+f"(d1), "+f"(d2), "+f"(d3)
        : "r"(a0), "r"(a1), "r"(a2), "r"(a3), "r"(b0), "r"(b1));
}

#define LDMATRIX_X4(r0, r1, r2, r3, addr) \
    asm volatile("ldmatrix.sync.aligned.m8n8.x4.shared.b16 {%0,%1,%2,%3}, [%4];" \
                 : "=r"(r0), "=r"(r1), "=r"(r2), "=r"(r3) : "r"(addr))

// ---------------- 0) fp16 conversion of the 5 weight matrices (one launch) --
__global__ void cvt5_f16_kernel(const float* __restrict__ w0, __half* __restrict__ o0,
                                const float* __restrict__ w1, __half* __restrict__ o1,
                                const float* __restrict__ w2, __half* __restrict__ o2,
                                const float* __restrict__ w3, __half* __restrict__ o3,
                                const float* __restrict__ w4, __half* __restrict__ o4) {
    const int seg = blockIdx.x >> 11;                 // 2048 blocks per weight
    const int i   = (blockIdx.x & 2047) * 256 + threadIdx.x;  // 8-elem group idx
    const float* in;
    __half* out;
    switch (seg) {
        case 0: in = w0; out = o0; break;
        case 1: in = w1; out = o1; break;
        case 2: in = w2; out = o2; break;
        case 3: in = w3; out = o3; break;
        default: in = w4; out = o4; break;
    }
    float4 v0 = reinterpret_cast<const float4*>(in)[i * 2];
    float4 v1 = reinterpret_cast<const float4*>(in)[i * 2 + 1];
    uint4 pk;
    pk.x = pack_h2(v0.x, v0.y);
    pk.y = pack_h2(v0.z, v0.w);
    pk.z = pack_h2(v1.x, v1.y);
    pk.w = pack_h2(v1.z, v1.w);
    reinterpret_cast<uint4*>(out)[i] = pk;
}

// ---------------- 1) causal depthwise conv (K=4) + SiLU + x fp16 side-out ---
__global__ void conv_silu_kernel(const float* __restrict__ x,
                                 const float* __restrict__ w,
                                 const float* __restrict__ bias) {
    int vid = blockIdx.x * blockDim.x + threadIdx.x;    // over B*T*C/4
    int cq  = vid & (Cc / 4 - 1);                       // channel quad
    int bt  = vid >> 9;                                 // /(2048/4)
    int t   = bt & (Tt - 1);
    int c   = cq * 4;

    const float4* x4 = reinterpret_cast<const float4*>(x);
    int base = (bt - t) * (Cc / 4) + cq;                // b*T*C/4 + cq

    float4 wr0 = reinterpret_cast<const float4*>(w)[c + 0];
    float4 wr1 = reinterpret_cast<const float4*>(w)[c + 1];
    float4 wr2 = reinterpret_cast<const float4*>(w)[c + 2];
    float4 wr3 = reinterpret_cast<const float4*>(w)[c + 3];
    float4 bb  = reinterpret_cast<const float4*>(bias)[cq];

    float4 a = bb;
    float4 xt3;
    #pragma unroll
    for (int j = 0; j < 4; j++) {
        int tt = t - 3 + j;
        if (tt >= 0) {
            float4 xv = x4[base + tt * (Cc / 4)];
            if (j == 3) xt3 = xv;
            float wj0 = (&wr0.x)[j], wj1 = (&wr1.x)[j], wj2 = (&wr2.x)[j], wj3 = (&wr3.x)[j];
            a.x = fmaf(xv.x, wj0, a.x);
            a.y = fmaf(xv.y, wj1, a.y);
            a.z = fmaf(xv.z, wj2, a.z);
            a.w = fmaf(xv.w, wj3, a.w);
        }
    }

    uint2 sc;
    sc.x = pack_h2(a.x / (1.0f + expf(-a.x)), a.y / (1.0f + expf(-a.y)));
    sc.y = pack_h2(a.z / (1.0f + expf(-a.z)), a.w / (1.0f + expf(-a.w)));
    reinterpret_cast<uint2*>(g_xconv)[vid] = sc;

    uint2 xr;
    xr.x = pack_h2(xt3.x, xt3.y);
    xr.y = pack_h2(xt3.z, xt3.w);
    reinterpret_cast<uint2*>(g_xt)[vid] = xr;
}

// ---------------- 2) FP16 GEMM tile body (4-stage pipeline, ldmatrix) -------
// Computes one 128x128 tile of Out = A[M,2048] * W[128-col slab]^T, fp16 in,
// fp32 accumulate. OutT = __half (qkvg) or float (y).
// mode 0: plain.  mode 1: sigmoid(out + bias[col]).  mode 2: per-row l2norm.
// smem layout per (matrix,stage): 128 rows x 16 words, XOR-swizzled chunks:
//   word(row,w) at row*16 + (((w>>2) ^ ((row>>1)&3))<<2) + (w&3)
template <typename OutT>
__device__ __forceinline__
void gemm_tile_body(const __half* __restrict__ A, const __half* __restrict__ W,
                    OutT* __restrict__ Out, const float* __restrict__ bias,
                    int mode, int bm, int bn) {
    constexpr int BM = 128;
    constexpr int KH = 32;                // K halves per stage
    constexpr int KCH = Cc / KH;          // 64 iterations
    constexpr int N = Cc;

    extern __shared__ uint32_t dyn[];
    float* red = (float*)(dyn + 2 * GST * STAGE_W);  // 128*4 floats

    const int tid  = threadIdx.x;
    const int warp = tid >> 5, lane = tid & 31;
    const int gid  = lane >> 2, tg = lane & 3;
    const int wm   = warp & 1;       // 0..1  -> 64-row slab
    const int wn   = warp >> 1;      // 0..3  -> 32-col slab

    const int lr = tid >> 2;         // 0..63  (loader row)
    const int lc = tid & 3;          // chunk 0..3 (8 halves each)

    uint32_t sA = (uint32_t)__cvta_generic_to_shared(dyn);
    uint32_t sB = sA + (uint32_t)(GST * STAGE_W) * 4u;

    // ---- per-lane ldmatrix byte offsets within a stage (loop-invariant) ----
    const int lq  = lane >> 3;       // matrix quad 0..3
    const int lr8 = lane & 7;
    uint32_t aoff[2][4];             // [half][mt]
    uint32_t boff[2][2];             // [half][ntp]
    #pragma unroll
    for (int half = 0; half < 2; half++) {
        #pragma unroll
        for (int mt = 0; mt < 4; mt++) {
            int row   = wm * 64 + mt * 16 + (lq & 1) * 8 + lr8;
            int sw    = (row >> 1) & 3;
            int chunk = half * 2 + (lq >> 1);
            aoff[half][mt] = (uint32_t)(row * 64 + ((chunk ^ sw) << 4));
        }
        #pragma unroll
        for (int ntp = 0; ntp < 2; ntp++) {
            int col   = wn * 32 + (2 * ntp + (lq >> 1)) * 8 + lr8;
            int sw    = (col >> 1) & 3;
            int chunk = half * 2 + (lq & 1);
            boff[half][ntp] = (uint32_t)(col * 64 + ((chunk ^ sw) << 4));
        }
    }

    auto issue = [&](int s, int k0) {   // k0 in halves
        #pragma unroll
        for (int r = 0; r < 2; r++) {
            int row = lr + r * 64;
            int sw  = (row >> 1) & 3;
            uint32_t off = (uint32_t)(s * BM * 16 + row * 16 + ((lc ^ sw) << 2)) * 4u;
            const __half* gA = A + (size_t)(bm + row) * Cc + k0 + lc * 8;
            asm volatile("cp.async.cg.shared.global [%0], [%1], 16;\n"
                         :: "r"(sA + off), "l"(gA));
            const __half* gB = W + (size_t)(bn + row) * Cc + k0 + lc * 8;
            asm volatile("cp.async.cg.shared.global [%0], [%1], 16;\n"
                         :: "r"(sB + off), "l"(gB));
        }
        asm volatile("cp.async.commit_group;\n");
    };

    float acc[4][4][4] = {};

    issue(0, 0);
    issue(1, KH);
    issue(2, 2 * KH);

    int s = 0;
    for (int i = 0; i < KCH; i++) {
        if (i < KCH - 2)       asm volatile("cp.async.wait_group 2;\n" ::: "memory");
        else if (i == KCH - 2) asm volatile("cp.async.wait_group 1;\n" ::: "memory");
        else                   asm volatile("cp.async.wait_group 0;\n" ::: "memory");
        __syncthreads();

        if (i + 3 < KCH) {
            int s2 = s + 3; if (s2 >= GST) s2 -= GST;
            issue(s2, (i + 3) * KH);
        }

        const uint32_t stA = sA + (uint32_t)(s * STAGE_W) * 4u;
        const uint32_t stB = sB + (uint32_t)(s * STAGE_W) * 4u;

        // Fragment loads: 8 A + 4 B ldmatrix.x4 per iteration.
        uint32_t af[2][4][4], bf[2][4][2];
        #pragma unroll
        for (int half = 0; half < 2; half++) {
            #pragma unroll
            for (int mt = 0; mt < 4; mt++)
                LDMATRIX_X4(af[half][mt][0], af[half][mt][1],
                            af[half][mt][2], af[half][mt][3],
                            stA + aoff[half][mt]);
            #pragma unroll
            for (int ntp = 0; ntp < 2; ntp++)
                LDMATRIX_X4(bf[half][2 * ntp][0],     bf[half][2 * ntp][1],
                            bf[half][2 * ntp + 1][0], bf[half][2 * ntp + 1][1],
                            stB + boff[half][ntp]);
        }
        #pragma unroll
        for (int half = 0; half < 2; half++)
            #pragma unroll
            for (int mt = 0; mt < 4; mt++)
                #pragma unroll
                for (int nt = 0; nt < 4; nt++)
                    mma_f16(acc[mt][nt][0], acc[mt][nt][1], acc[mt][nt][2], acc[mt][nt][3],
                            af[half][mt][0], af[half][mt][1], af[half][mt][2], af[half][mt][3],
                            bf[half][nt][0], bf[half][nt][1]);
        s++; if (s >= GST) s = 0;
    }

    // ---- fused l2norm over the 128-col tile (mode 2, tile == one head) -----
    if (mode == 2) {
        __syncthreads();
        float invLo[4], invHi[4];
        #pragma unroll
        for (int mt = 0; mt < 4; mt++) {
            float slo = 0.0f, shi = 0.0f;
            #pragma unroll
            for (int nt = 0; nt < 4; nt++) {
                slo = fmaf(acc[mt][nt][0], acc[mt][nt][0], slo);
                slo = fmaf(acc[mt][nt][1], acc[mt][nt][1], slo);
                shi = fmaf(acc[mt][nt][2], acc[mt][nt][2], shi);
                shi = fmaf(acc[mt][nt][3], acc[mt][nt][3], shi);
            }
            slo += __shfl_xor_sync(0xffffffffu, slo, 1);
            slo += __shfl_xor_sync(0xffffffffu, slo, 2);
            shi += __shfl_xor_sync(0xffffffffu, shi, 1);
            shi += __shfl_xor_sync(0xffffffffu, shi, 2);
            if (tg == 0) {
                int r = wm * 64 + mt * 16 + gid;
                red[r * 4 + wn]       = slo;
                red[(r + 8) * 4 + wn] = shi;
            }
        }
        __syncthreads();
        #pragma unroll
        for (int mt = 0; mt < 4; mt++) {
            int r = wm * 64 + mt * 16 + gid;
            float slo = red[r * 4 + 0] + red[r * 4 + 1] + red[r * 4 + 2] + red[r * 4 + 3];
            float shi = red[(r + 8) * 4 + 0] + red[(r + 8) * 4 + 1]
                      + red[(r + 8) * 4 + 2] + red[(r + 8) * 4 + 3];
            invLo[mt] = 1.0f / fmaxf(sqrtf(slo), 1e-12f);
            invHi[mt] = 1.0f / fmaxf(sqrtf(shi), 1e-12f);
        }
        #pragma unroll
        for (int mt = 0; mt < 4; mt++)
            #pragma unroll
            for (int nt = 0; nt < 4; nt++) {
                acc[mt][nt][0] *= invLo[mt];
                acc[mt][nt][1] *= invLo[mt];
                acc[mt][nt][2] *= invHi[mt];
                acc[mt][nt][3] *= invHi[mt];
            }
    }

    // epilogue stores
    #pragma unroll
    for (int mt = 0; mt < 4; mt++) {
        #pragma unroll
        for (int nt = 0; nt < 4; nt++) {
            int row = bm + wm * 64 + mt * 16 + gid;
            int col = bn + wn * 32 + nt * 8 + tg * 2;
            float v0 = acc[mt][nt][0], v1 = acc[mt][nt][1];
            float v2 = acc[mt][nt][2], v3 = acc[mt][nt][3];
            if (mode == 1) {
                float b0 = bias[col], b1 = bias[col + 1];
                v0 = 1.0f / (1.0f + expf(-(v0 + b0)));
                v1 = 1.0f / (1.0f + expf(-(v1 + b1)));
                v2 = 1.0f / (1.0f + expf(-(v2 + b0)));
                v3 = 1.0f / (1.0f + expf(-(v3 + b1)));
            }
            if constexpr (sizeof(OutT) == 2) {
                *reinterpret_cast<uint32_t*>(
                    (__half*)Out + (size_t)row * N + col)       = pack_h2(v0, v1);
                *reinterpret_cast<uint32_t*>(
                    (__half*)Out + (size_t)(row + 8) * N + col) = pack_h2(v2, v3);
            } else {
                *reinterpret_cast<float2*>(
                    (float*)Out + (size_t)row * N + col)        = make_float2(v0, v1);
                *reinterpret_cast<float2*>(
                    (float*)Out + (size_t)(row + 8) * N + col)  = make_float2(v2, v3);
            }
        }
    }
}

// Combined q/k/v/gate projection: one launch, 64 column-tiles x 128 row-tiles.
// seg = blockIdx.x>>4: 0=q(mode2) 1=k(mode2) 2=v(mode0) 3=gate(mode1, A=xconv)
__global__ __launch_bounds__(256, 2)
void gemm_qkvg_kernel(const float* __restrict__ gate_b) {
    const int seg = blockIdx.x >> 4;
    const int bn  = (blockIdx.x & 15) * 128;
    const int bm  = blockIdx.y * 128;

    const __half* A;
    const __half* W;
    __half* Out;
    int mode;
    switch (seg) {
        case 0:  A = g_xt;    W = g_Wqt; Out = g_q;    mode = 2; break;
        case 1:  A = g_xt;    W = g_Wkt; Out = g_k;    mode = 2; break;
        case 2:  A = g_xt;    W = g_Wvt; Out = g_v;    mode = 0; break;
        default: A = g_xconv; W = g_Wgt; Out = g_gate; mode = 1; break;
    }
    gemm_tile_body<__half>(A, W, Out, gate_b, mode, bm, bn);
}

// Output projection: y = att * Wo^T (mode 0, fp32 out for LayerNorm)
__global__ __launch_bounds__(256, 2)
void gemm_out_kernel() {
    gemm_tile_body<float>(g_att, g_Wot, g_y, nullptr, 0, blockIdx.y * 128, blockIdx.x * 128);
}

// ---------------- 4) chunked decayed scan (fp16 in, fp32 math) -------------
__global__ void scan_pass1(const __half* __restrict__ k, const __half* __restrict__ v,
                           const float* __restrict__ gamma) {
    int wid  = threadIdx.x >> 5, lane = threadIdx.x & 31;
    int blk  = blockIdx.x * 4 + wid;          // 0..4095
    int c    = blk & (NCHUNK - 1);
    int bh   = blk >> 6;
    int h    = bh & (Hh - 1);
    int b    = bh >> 4;
    float g  = gamma[h];
    const uint2* k2 = reinterpret_cast<const uint2*>(k);
    const uint2* v2 = reinterpret_cast<const uint2*>(v);
    size_t idx = ((size_t)(b * Tt + c * LCH) * Cc + h * DhD) / 4 + lane;
    float4 S = make_float4(0.f, 0.f, 0.f, 0.f);
    #pragma unroll 4
    for (int i = 0; i < LCH; i++) {
        uint2 ku = k2[idx], vu = v2[idx];
        float2 k0 = unpack_h2(ku.x), k1 = unpack_h2(ku.y);
        float2 va = unpack_h2(vu.x), vb = unpack_h2(vu.y);
        S.x = fmaf(g, S.x, k0.x * va.x);
        S.y = fmaf(g, S.y, k0.y * va.y);
        S.z = fmaf(g, S.z, k1.x * vb.x);
        S.w = fmaf(g, S.w, k1.y * vb.y);
        idx += Cc / 4;
    }
    reinterpret_cast<float4*>(g_F)[((size_t)bh * NCHUNK + c) * (DhD / 4) + lane] = S;
}

__global__ void scan_pass2(const float* __restrict__ gamma) {
    int tid = blockIdx.x * blockDim.x + threadIdx.x;   // over Bb*Hh*DhD/4 = 2048
    int d4  = tid & (DhD / 4 - 1);
    int bh  = tid >> 5;
    int h   = bh & (Hh - 1);
    float g  = gamma[h];
    float gL = powf(g, (float)LCH);     // exact 1.0 for gamma=1 head
    const float4* F4 = reinterpret_cast<const float4*>(g_F);
    float4* C4       = reinterpret_cast<float4*>(g_carry);
    float4 carry = make_float4(0.f, 0.f, 0.f, 0.f);
    for (int c = 0; c < NCHUNK; c++) {
        size_t o = ((size_t)bh * NCHUNK + c) * (DhD / 4) + d4;
        C4[o] = carry;
        float4 f = F4[o];
        carry.x = fmaf(gL, carry.x, f.x);
        carry.y = fmaf(gL, carry.y, f.y);
        carry.z = fmaf(gL, carry.z, f.z);
        carry.w = fmaf(gL, carry.w, f.w);
    }
}

__global__ void scan_pass3(const __half* __restrict__ k, const __half* __restrict__ v,
                           const __half* __restrict__ q, const __half* __restrict__ gate,
                           const float* __restrict__ gamma) {
    int wid  = threadIdx.x >> 5, lane = threadIdx.x & 31;
    int blk  = blockIdx.x * 4 + wid;
    int c    = blk & (NCHUNK - 1);
    int bh   = blk >> 6;
    int h    = bh & (Hh - 1);
    int b    = bh >> 4;
    float g  = gamma[h];
    const uint2* k2 = reinterpret_cast<const uint2*>(k);
    const uint2* v2 = reinterpret_cast<const uint2*>(v);
    const uint2* q2 = reinterpret_cast<const uint2*>(q);
    const uint2* g2 = reinterpret_cast<const uint2*>(gate);
    uint2* a2       = reinterpret_cast<uint2*>(g_att);   // 4 halves per slot
    float4 S = reinterpret_cast<const float4*>(g_carry)
                   [((size_t)bh * NCHUNK + c) * (DhD / 4) + lane];
    size_t idx = ((size_t)(b * Tt + c * LCH) * Cc + h * DhD) / 4 + lane;
    #pragma unroll 4
    for (int i = 0; i < LCH; i++) {
        uint2 ku = k2[idx], vu = v2[idx];
        float2 k0 = unpack_h2(ku.x), k1 = unpack_h2(ku.y);
        float2 va = unpack_h2(vu.x), vb = unpack_h2(vu.y);
        S.x = fmaf(g, S.x, k0.x * va.x);
        S.y = fmaf(g, S.y, k0.y * va.y);
        S.z = fmaf(g, S.z, k1.x * vb.x);
        S.w = fmaf(g, S.w, k1.y * vb.y);
        uint2 gu = g2[idx], qu = q2[idx];
        float2 g0 = unpack_h2(gu.x), g1 = unpack_h2(gu.y);
        float2 q0 = unpack_h2(qu.x), q1 = unpack_h2(qu.y);
        uint2 o;
        o.x = pack_h2(g0.x * S.x * q0.x, g0.y * S.y * q0.y);
        o.y = pack_h2(g1.x * S.z * q1.x, g1.y * S.w * q1.y);
        a2[idx] = o;
        idx += Cc / 4;
    }
}

// ---------------- 5) LayerNorm over C=2048 ---------------------------------
__global__ __launch_bounds__(256)
void ln_kernel(const float* __restrict__ y, const float* __restrict__ lw,
               const float* __restrict__ lb, float* __restrict__ out) {
    int row = blockIdx.x;
    int tid = threadIdx.x;
    const float4* yr = reinterpret_cast<const float4*>(y + (size_t)row * Cc);
    float4* orow     = reinterpret_cast<float4*>(out + (size_t)row * Cc);

    float4 v0 = yr[tid];
    float4 v1 = yr[tid + 256];
    float sum = v0.x + v0.y + v0.z + v0.w + v1.x + v1.y + v1.z + v1.w;
    float sq  = v0.x * v0.x + v0.y * v0.y + v0.z * v0.z + v0.w * v0.w
              + v1.x * v1.x + v1.y * v1.y + v1.z * v1.z + v1.w * v1.w;

    #pragma unroll
    for (int o = 16; o; o >>= 1) {
        sum += __shfl_xor_sync(0xffffffffu, sum, o);
        sq  += __shfl_xor_sync(0xffffffffu, sq, o);
    }
    __shared__ float ssum[8], ssq[8];
    __shared__ float s_mu, s_inv;
    int warp = tid >> 5, lane = tid & 31;
    if (lane == 0) { ssum[warp] = sum; ssq[warp] = sq; }
    __syncthreads();
    if (tid == 0) {
        float ts = 0.0f, tq = 0.0f;
        #pragma unroll
        for (int i = 0; i < 8; i++) { ts += ssum[i]; tq += ssq[i]; }
        float mu  = ts / (float)Cc;
        float var = tq / (float)Cc - mu * mu;
        s_mu  = mu;
        s_inv = rsqrtf(var + 1e-5f);
    }
    __syncthreads();
    float mu = s_mu, inv = s_inv;

    const float4 w0 = reinterpret_cast<const float4*>(lw)[tid];
    const float4 w1 = reinterpret_cast<const float4*>(lw)[tid + 256];
    const float4 b0 = reinterpret_cast<const float4*>(lb)[tid];
    const float4 b1 = reinterpret_cast<const float4*>(lb)[tid + 256];

    float4 o0, o1;
    o0.x = (v0.x - mu) * inv * w0.x + b0.x;
    o0.y = (v0.y - mu) * inv * w0.y + b0.y;
    o0.z = (v0.z - mu) * inv * w0.z + b0.z;
    o0.w = (v0.w - mu) * inv * w0.w + b0.w;
    o1.x = (v1.x - mu) * inv * w1.x + b1.x;
    o1.y = (v1.y - mu) * inv * w1.y + b1.y;
    o1.z = (v1.z - mu) * inv * w1.z + b1.z;
    o1.w = (v1.w - mu) * inv * w1.w + b1.w;
    orow[tid]       = o0;
    orow[tid + 256] = o1;
}

// ---------------- host orchestration ---------------------------------------
extern "C" void kernel_launch(void* const* d_in, const int* in_sizes, int n_in,
                              void* d_out, int out_size) {
    (void)in_sizes; (void)n_in; (void)out_size;
    const float* x      = (const float*)d_in[0];
    const float* Wq     = (const float*)d_in[1];
    const float* Wk     = (const float*)d_in[2];
    const float* Wv     = (const float*)d_in[3];
    const float* Wo     = (const float*)d_in[4];
    const float* conv_w = (const float*)d_in[5];
    const float* conv_b = (const float*)d_in[6];
    const float* gate_w = (const float*)d_in[7];
    const float* gate_b = (const float*)d_in[8];
    const float* ln_w   = (const float*)d_in[9];
    const float* ln_b   = (const float*)d_in[10];
    const float* gamma  = (const float*)d_in[11];

    __half *p_q, *p_k, *p_v, *p_gate;
    float  *p_y;
    __half *p_Wqt, *p_Wkt, *p_Wvt, *p_Wot, *p_Wgt;
    cudaGetSymbolAddress((void**)&p_q, g_q);
    cudaGetSymbolAddress((void**)&p_k, g_k);
    cudaGetSymbolAddress((void**)&p_v, g_v);
    cudaGetSymbolAddress((void**)&p_gate, g_gate);
    cudaGetSymbolAddress((void**)&p_y, g_y);
    cudaGetSymbolAddress((void**)&p_Wqt, g_Wqt);
    cudaGetSymbolAddress((void**)&p_Wkt, g_Wkt);
    cudaGetSymbolAddress((void**)&p_Wvt, g_Wvt);
    cudaGetSymbolAddress((void**)&p_Wot, g_Wot);
    cudaGetSymbolAddress((void**)&p_Wgt, g_Wgt);

    // allow 66KB dynamic smem on the GEMM kernels (idempotent)
    cudaFuncSetAttribute(gemm_qkvg_kernel, cudaFuncAttributeMaxDynamicSharedMemorySize, GEMM_SMEM);
    cudaFuncSetAttribute(gemm_out_kernel,  cudaFuncAttributeMaxDynamicSharedMemorySize, GEMM_SMEM);

    // 0) convert the 5 weight matrices to fp16 in one launch
    const int wBlocks = (Cc * Cc) / 2048;  // 2048 blocks per weight
    cvt5_f16_kernel<<<5 * wBlocks, 256>>>(Wq, p_Wqt, Wk, p_Wkt, Wv, p_Wvt,
                                          Wo, p_Wot, gate_w, p_Wgt);

    // 1) depthwise conv + SiLU (float4); also emits fp16 x (g_xt)
    conv_silu_kernel<<<(Mrows * Cc / 4) / 256, 256>>>(x, conv_w, conv_b);

    // 2) all four projections in ONE launch (q, k, v, gate) — fp16 outputs
    dim3 qgrid(64, Mrows / 128);   // 64 col-tiles (4 segs x 16), 128 row-tiles
    gemm_qkvg_kernel<<<qgrid, 256, GEMM_SMEM>>>(gate_b);

    // 3) decayed scan (chunked, exact); fp16 inputs, fp32 recurrence
    scan_pass1<<<Bb * Hh * NCHUNK / 4, 128>>>(p_k, p_v, gamma);
    scan_pass2<<<16, 128>>>(gamma);
    scan_pass3<<<Bb * Hh * NCHUNK / 4, 128>>>(p_k, p_v, p_q, p_gate, gamma);

    // 4) output projection + LayerNorm
    dim3 ogrid(Cc / 128, Mrows / 128);   // (16, 128)
    gemm_out_kernel<<<ogrid, 256, GEMM_SMEM>>>();
    ln_kernel<<<Mrows, 256>>>(p_y, ln_w, ln_b, (float*)d_out);
}